// round 6
// baseline (speedup 1.0000x reference)
#include <cuda_runtime.h>
#include <cuda_fp16.h>
#include <cstdint>

// Problem constants
#define B_  2
#define S_  2048
#define H_  1024
#define NH_ 16
#define HD_ 64
#define M_  (B_*S_)   // 4096 rows

// ---------------------------------------------------------------------------
// Scratch (allocation-free: device globals)
// ---------------------------------------------------------------------------
__device__ __half g_Xh[(size_t)M_ * H_];
__device__ __half g_Xl[(size_t)M_ * H_];
__device__ __half g_WhT[4][(size_t)H_ * H_];     // transposed [N,K] fp16
__device__ __half g_Qah[(size_t)M_ * H_];        // [b,h,s,d] hi
__device__ __half g_Qal[(size_t)M_ * H_];        // [b,h,s,d] lo
__device__ __half g_Kah[(size_t)M_ * H_];        // [b,h,s,d] hi only
__device__ __half g_Vs [(size_t)M_ * H_];        // [s,H] fp16 (pre-transpose)
__device__ __half g_Vth[(size_t)M_ * H_];        // [b,h,d,s]
__device__ __half g_Ch [(size_t)M_ * H_];        // context [s,H] hi
__device__ __half g_Cl [(size_t)M_ * H_];        // context [s,H] lo

// ---------------------------------------------------------------------------
// Helpers
// ---------------------------------------------------------------------------
__device__ __forceinline__ uint32_t smem_u32(const void* p) {
    uint32_t a;
    asm("{ .reg .u64 t; cvta.to.shared.u64 t, %1; cvt.u32.u64 %0, t; }"
        : "=r"(a) : "l"(p));
    return a;
}
__device__ __forceinline__ void cp16(uint32_t s, const void* g) {
    asm volatile("cp.async.cg.shared.global [%0], [%1], 16;" :: "r"(s), "l"(g));
}
__device__ __forceinline__ void cp4(uint32_t s, const void* g) {
    asm volatile("cp.async.ca.shared.global [%0], [%1], 4;" :: "r"(s), "l"(g));
}
__device__ __forceinline__ void cp_commit() {
    asm volatile("cp.async.commit_group;" ::: "memory");
}
__device__ __forceinline__ void mma16816(float* c, const uint32_t* a, const uint32_t* b) {
    asm volatile(
        "mma.sync.aligned.m16n8k16.row.col.f32.f16.f16.f32 "
        "{%0,%1,%2,%3}, {%4,%5,%6,%7}, {%8,%9}, {%0,%1,%2,%3};"
        : "+f"(c[0]), "+f"(c[1]), "+f"(c[2]), "+f"(c[3])
        : "r"(a[0]), "r"(a[1]), "r"(a[2]), "r"(a[3]), "r"(b[0]), "r"(b[1]));
}
// pack two fp32 -> (half2 hi, half2 lo)
__device__ __forceinline__ void pack_split_h(float f0, float f1, uint32_t& hi, uint32_t& lo) {
    __half h0 = __float2half_rn(f0), h1 = __float2half_rn(f1);
    __half l0 = __float2half_rn(f0 - __half2float(h0));
    __half l1 = __float2half_rn(f1 - __half2float(h1));
    __half2 hh = __halves2half2(h0, h1);
    __half2 ll = __halves2half2(l0, l1);
    hi = *(uint32_t*)&hh;
    lo = *(uint32_t*)&ll;
}
__device__ __forceinline__ uint32_t pack_h2(float f0, float f1) {
    __half2 hh = __halves2half2(__float2half_rn(f0), __float2half_rn(f1));
    return *(uint32_t*)&hh;
}

// ---------------------------------------------------------------------------
// GEMM core: fp16 split-2.  acc = Ah@B^T + Al@B^T   (B stored [N,K])
// CTA tile 128x256, K-chunk 32, 4-stage cp.async, 8 warps (2x4), warp 64x64.
// ---------------------------------------------------------------------------
#define TM 128
#define TN 256
#define TK 32
#define PITCH 40                 // halves per smem row (80 B)
#define OAH 0
#define OAL 10240                // 128*80
#define OBH 20480                // + 256*80
#define STG 40960
#define NSTAGE 4
#define GSMEM (STG * NSTAGE)     // 163840
#define NCH (H_ / TK)            // 32

__device__ __forceinline__ void gemm_core(
    const __half* __restrict__ Ah, const __half* __restrict__ Al,
    const __half* __restrict__ Bh, int row0, int col0,
    char* gsm, float acc[4][8][4]) {

    const int tid = threadIdx.x;
    const int wid = tid >> 5;
    const int lane = tid & 31;
    const int gid = lane >> 2;
    const int t = lane & 3;
    const int wm = wid & 1;
    const int wn = wid >> 1;
    const uint32_t sb = smem_u32(gsm);

    auto load_chunk = [&](int c, int s) {
        const int k0 = c * TK;
        const uint32_t base = sb + s * STG;
        #pragma unroll
        for (int i = 0; i < 2; i++) {               // A: 512 chunks/array
            int idx = tid + i * 256;
            int r = idx >> 2, c16 = idx & 3;
            uint32_t so = r * 80 + c16 * 16;
            size_t g = (size_t)(row0 + r) * H_ + k0 + c16 * 8;
            cp16(base + OAH + so, Ah + g);
            cp16(base + OAL + so, Al + g);
        }
        #pragma unroll
        for (int i = 0; i < 4; i++) {               // B: 1024 chunks
            int idx = tid + i * 256;
            int r = idx >> 2, c16 = idx & 3;
            uint32_t so = r * 80 + c16 * 16;
            cp16(base + OBH + so, Bh + (size_t)(col0 + r) * H_ + k0 + c16 * 8);
        }
        cp_commit();
    };

    load_chunk(0, 0);
    load_chunk(1, 1);
    load_chunk(2, 2);

    for (int c = 0; c < NCH; c++) {
        const int s = c & 3;
        if (c + 3 < NCH) load_chunk(c + 3, (c + 3) & 3);
        else cp_commit();
        asm volatile("cp.async.wait_group 3;" ::: "memory");
        __syncthreads();

        const char* bs = gsm + s * STG;
        const __half* Ahp = (const __half*)(bs + OAH);
        const __half* Alp = (const __half*)(bs + OAL);
        const __half* Bhp = (const __half*)(bs + OBH);

        #pragma unroll
        for (int ks = 0; ks < 2; ks++) {
            const int kc = ks * 16 + 2 * t;
            uint32_t ah[4][4], al[4][4];
            #pragma unroll
            for (int mt = 0; mt < 4; mt++) {
                const int r0 = wm * 64 + mt * 16 + gid;
                ah[mt][0] = *(const uint32_t*)(Ahp + r0 * PITCH + kc);
                ah[mt][1] = *(const uint32_t*)(Ahp + (r0 + 8) * PITCH + kc);
                ah[mt][2] = *(const uint32_t*)(Ahp + r0 * PITCH + kc + 8);
                ah[mt][3] = *(const uint32_t*)(Ahp + (r0 + 8) * PITCH + kc + 8);
                al[mt][0] = *(const uint32_t*)(Alp + r0 * PITCH + kc);
                al[mt][1] = *(const uint32_t*)(Alp + (r0 + 8) * PITCH + kc);
                al[mt][2] = *(const uint32_t*)(Alp + r0 * PITCH + kc + 8);
                al[mt][3] = *(const uint32_t*)(Alp + (r0 + 8) * PITCH + kc + 8);
            }
            #pragma unroll
            for (int half = 0; half < 2; half++) {
                uint32_t bh[4][2];
                #pragma unroll
                for (int n4 = 0; n4 < 4; n4++) {
                    const int n0 = wn * 64 + (half * 4 + n4) * 8 + gid;
                    bh[n4][0] = *(const uint32_t*)(Bhp + n0 * PITCH + kc);
                    bh[n4][1] = *(const uint32_t*)(Bhp + n0 * PITCH + kc + 8);
                }
                #pragma unroll
                for (int mt = 0; mt < 4; mt++)
                    #pragma unroll
                    for (int n4 = 0; n4 < 4; n4++) {
                        float* a = acc[mt][half * 4 + n4];
                        mma16816(a, ah[mt], bh[n4]);
                        mma16816(a, al[mt], bh[n4]);
                    }
            }
        }
        __syncthreads();
    }
}

// ---------------------------------------------------------------------------
// QKV projection GEMM: grid.z selects Q/K/V; epilogue writes attention layouts.
// ---------------------------------------------------------------------------
__global__ __launch_bounds__(256, 1)
void gemm_qkv() {
    extern __shared__ char gsm[];
    const int mode = blockIdx.z;
    const int row0 = blockIdx.y * TM;
    const int col0 = blockIdx.x * TN;
    const __half* Bh = g_WhT[mode];

    float acc[4][8][4];
    #pragma unroll
    for (int i = 0; i < 4; i++)
        #pragma unroll
        for (int j = 0; j < 8; j++)
            #pragma unroll
            for (int q = 0; q < 4; q++) acc[i][j][q] = 0.f;

    gemm_core(g_Xh, g_Xl, Bh, row0, col0, gsm, acc);

    const int tid = threadIdx.x;
    const int wid = tid >> 5;
    const int lane = tid & 31;
    const int gid = lane >> 2;
    const int t = lane & 3;
    const int wm = wid & 1;
    const int wn = wid >> 1;

    #pragma unroll
    for (int mt = 0; mt < 4; mt++) {
        #pragma unroll
        for (int rr = 0; rr < 2; rr++) {
            const int rg = row0 + wm * 64 + mt * 16 + gid + rr * 8;
            const int bb = rg >> 11;          // batch
            const int ss = rg & 2047;         // seq pos
            #pragma unroll
            for (int nt = 0; nt < 8; nt++) {
                const int cg = col0 + wn * 64 + nt * 8 + 2 * t;
                float c0 = acc[mt][nt][rr * 2 + 0];
                float c1 = acc[mt][nt][rr * 2 + 1];
                if (mode == 2) {
                    // V: straight [s,H] fp16
                    *(uint32_t*)(g_Vs + (size_t)rg * H_ + cg) = pack_h2(c0, c1);
                } else {
                    const int hh = cg >> 6, dd = cg & 63;
                    const size_t go = (((size_t)bb * NH_ + hh) * S_ + ss) * HD_ + dd;
                    if (mode == 0) {
                        uint32_t hi, lo;
                        pack_split_h(c0, c1, hi, lo);
                        *(uint32_t*)(g_Qah + go) = hi;
                        *(uint32_t*)(g_Qal + go) = lo;
                    } else {
                        *(uint32_t*)(g_Kah + go) = pack_h2(c0, c1);
                    }
                }
            }
        }
    }
}

// ---------------------------------------------------------------------------
// Output projection GEMM: C(fp32) = ctx(split fp16) @ WO
// ---------------------------------------------------------------------------
__global__ __launch_bounds__(256, 1)
void gemm_o(float* __restrict__ out) {
    extern __shared__ char gsm[];
    const int row0 = blockIdx.y * TM;
    const int col0 = blockIdx.x * TN;

    float acc[4][8][4];
    #pragma unroll
    for (int i = 0; i < 4; i++)
        #pragma unroll
        for (int j = 0; j < 8; j++)
            #pragma unroll
            for (int q = 0; q < 4; q++) acc[i][j][q] = 0.f;

    gemm_core(g_Ch, g_Cl, g_WhT[3], row0, col0, gsm, acc);

    const int tid = threadIdx.x;
    const int wid = tid >> 5;
    const int lane = tid & 31;
    const int gid = lane >> 2;
    const int t = lane & 3;
    const int wm = wid & 1;
    const int wn = wid >> 1;

    #pragma unroll
    for (int mt = 0; mt < 4; mt++) {
        const int rg = row0 + wm * 64 + mt * 16 + gid;
        #pragma unroll
        for (int nt = 0; nt < 8; nt++) {
            const int cg = col0 + wn * 64 + nt * 8 + 2 * t;
            *(float2*)(out + (size_t)rg * H_ + cg) =
                make_float2(acc[mt][nt][0], acc[mt][nt][1]);
            *(float2*)(out + (size_t)(rg + 8) * H_ + cg) =
                make_float2(acc[mt][nt][2], acc[mt][nt][3]);
        }
    }
}

// ---------------------------------------------------------------------------
// V transpose: g_Vs [s,H] -> g_Vth [b,h,d,s]
// ---------------------------------------------------------------------------
__global__ __launch_bounds__(256)
void vtrans() {
    __shared__ __half tile[64][72];
    const int tid = threadIdx.x;
    const int s0 = blockIdx.x * 64;
    const int h = blockIdx.y;
    const int b = blockIdx.z;
    const size_t bh = (size_t)b * NH_ + h;

    #pragma unroll
    for (int i = 0; i < 8; i++) {
        int idx = tid + i * 256;          // 2048 half2
        int r = idx >> 5, c2 = idx & 31;
        __half2 v = *(const __half2*)(g_Vs + (size_t)(b * S_ + s0 + r) * H_ + h * HD_ + c2 * 2);
        *(__half2*)&tile[r][c2 * 2] = v;
    }
    __syncthreads();
    #pragma unroll
    for (int i = 0; i < 8; i++) {
        int idx = tid + i * 256;
        int d = idx >> 5, s2 = idx & 31;
        __half2 v = __halves2half2(tile[s2 * 2][d], tile[s2 * 2 + 1][d]);
        *(__half2*)(g_Vth + (bh * HD_ + d) * S_ + s0 + s2 * 2) = v;
    }
}

// ---------------------------------------------------------------------------
// Flash attention, fp16 split-2 (Q hi/lo, K hi, P hi/lo, V hi).
// CTA = 256 q-rows x one (b,h); 8 warps x two m16 tiles; kv-tile 64, 2 bufs.
// ---------------------------------------------------------------------------
#define FROWB 144
#define SQH   0
#define SQL   36864              // 256*144
#define SKV0  73728
#define KVBUF 18432              // Kh + Vh, each 64*144=9216
#define OKH   0
#define OVH   9216
#define SMK   110592             // mask: 2 bufs x 64 x 4B
#define FSMEM 111104

__global__ __launch_bounds__(256, 1)
void flash_mma(const int* __restrict__ mask) {
    extern __shared__ char sm[];
    const float NEG = __int_as_float(0xff800000u);
    const int tid = threadIdx.x;
    const int wid = tid >> 5;
    const int lane = tid & 31;
    const int gid = lane >> 2;
    const int t = lane & 3;
    const int q0 = blockIdx.x * 256;
    const int h = blockIdx.y;
    const int b = blockIdx.z;
    const size_t bh = (size_t)b * NH_ + h;

    const __half* Qhp = g_Qah + (bh * S_ + q0) * HD_;
    const __half* Qlp = g_Qal + (bh * S_ + q0) * HD_;
    const __half* Khp = g_Kah + bh * S_ * HD_;
    const __half* Vtp = g_Vth + bh * HD_ * S_;
    const int* mkp = mask + b * S_;

    const uint32_t sb = smem_u32(sm);

    // Load Q (256 x 64 halves, hi+lo)
    #pragma unroll
    for (int i = 0; i < 8; i++) {
        int idx = tid + i * 256;          // 2048 chunks per array
        int r = idx >> 3, c = idx & 7;
        cp16(sb + SQH + r * FROWB + c * 16, Qhp + (size_t)r * HD_ + c * 8);
        cp16(sb + SQL + r * FROWB + c * 16, Qlp + (size_t)r * HD_ + c * 8);
    }
    cp_commit();

    auto load_kv = [&](int tile, int buf) {
        const int kv0 = tile * 64;
        const uint32_t kb = sb + SKV0 + buf * KVBUF;
        #pragma unroll
        for (int i = 0; i < 2; i++) {
            int idx = tid + i * 256;      // 512 chunks each
            int r = idx >> 3, c = idx & 7;
            uint32_t so = r * FROWB + c * 16;
            cp16(kb + OKH + so, Khp + (size_t)(kv0 + r) * HD_ + c * 8);
            cp16(kb + OVH + so, Vtp + (size_t)r * S_ + kv0 + c * 8);
        }
        if (tid < 64) cp4(sb + SMK + buf * 256 + tid * 4, mkp + kv0 + tid);
        cp_commit();
    };

    load_kv(0, 0);

    float mr[2][2], lr[2][2];
    #pragma unroll
    for (int mi = 0; mi < 2; mi++) {
        mr[mi][0] = NEG; mr[mi][1] = NEG;
        lr[mi][0] = 0.f; lr[mi][1] = 0.f;
    }
    float ctx[2][8][4];
    #pragma unroll
    for (int mi = 0; mi < 2; mi++)
        #pragma unroll
        for (int nt = 0; nt < 8; nt++)
            #pragma unroll
            for (int e = 0; e < 4; e++) ctx[mi][nt][e] = 0.f;

    const int m0r = wid * 32;

    for (int tile = 0; tile < 32; tile++) {
        const int buf = tile & 1;
        if (tile + 1 < 32) {
            load_kv(tile + 1, buf ^ 1);
            asm volatile("cp.async.wait_group 1;" ::: "memory");
        } else {
            asm volatile("cp.async.wait_group 0;" ::: "memory");
        }
        __syncthreads();

        const char* kb = sm + SKV0 + buf * KVBUF;
        const int* mk = (const int*)(sm + SMK + buf * 256);

        // --- S = QK^T (split-2) ---
        float sc[2][8][4];
        #pragma unroll
        for (int mi = 0; mi < 2; mi++)
            #pragma unroll
            for (int nt = 0; nt < 8; nt++)
                #pragma unroll
                for (int e = 0; e < 4; e++) sc[mi][nt][e] = 0.f;

        #pragma unroll
        for (int ks = 0; ks < 4; ks++) {
            const int kcb = ks * 32 + 4 * t;
            uint32_t ah[2][4], al[2][4];
            #pragma unroll
            for (int mi = 0; mi < 2; mi++) {
                const int r0 = m0r + mi * 16;
                const char* qa = sm + SQH + (r0 + gid) * FROWB + kcb;
                const char* qb = sm + SQH + (r0 + gid + 8) * FROWB + kcb;
                ah[mi][0] = *(const uint32_t*)qa;
                ah[mi][1] = *(const uint32_t*)qb;
                ah[mi][2] = *(const uint32_t*)(qa + 16);
                ah[mi][3] = *(const uint32_t*)(qb + 16);
                const char* qc = sm + SQL + (r0 + gid) * FROWB + kcb;
                const char* qd = sm + SQL + (r0 + gid + 8) * FROWB + kcb;
                al[mi][0] = *(const uint32_t*)qc;
                al[mi][1] = *(const uint32_t*)qd;
                al[mi][2] = *(const uint32_t*)(qc + 16);
                al[mi][3] = *(const uint32_t*)(qd + 16);
            }
            #pragma unroll
            for (int nt = 0; nt < 8; nt++) {
                const char* kr = kb + (nt * 8 + gid) * FROWB + kcb;
                uint32_t bhf[2] = { *(const uint32_t*)(kr + OKH),
                                    *(const uint32_t*)(kr + OKH + 16) };
                #pragma unroll
                for (int mi = 0; mi < 2; mi++) {
                    mma16816(sc[mi][nt], ah[mi], bhf);
                    mma16816(sc[mi][nt], al[mi], bhf);
                }
            }
        }

        // --- scale, clip, mask; online softmax (per m-tile) ---
        #pragma unroll
        for (int mi = 0; mi < 2; mi++) {
            float tm0 = NEG, tm1 = NEG;
            #pragma unroll
            for (int nt = 0; nt < 8; nt++) {
                int c0 = nt * 8 + 2 * t;
                int k0 = mk[c0], k1 = mk[c0 + 1];
                float v;
                v = fminf(fmaxf(sc[mi][nt][0] * 0.125f, -10000.f), 10000.f);
                sc[mi][nt][0] = k0 ? v : NEG;
                v = fminf(fmaxf(sc[mi][nt][1] * 0.125f, -10000.f), 10000.f);
                sc[mi][nt][1] = k1 ? v : NEG;
                v = fminf(fmaxf(sc[mi][nt][2] * 0.125f, -10000.f), 10000.f);
                sc[mi][nt][2] = k0 ? v : NEG;
                v = fminf(fmaxf(sc[mi][nt][3] * 0.125f, -10000.f), 10000.f);
                sc[mi][nt][3] = k1 ? v : NEG;
                tm0 = fmaxf(tm0, fmaxf(sc[mi][nt][0], sc[mi][nt][1]));
                tm1 = fmaxf(tm1, fmaxf(sc[mi][nt][2], sc[mi][nt][3]));
            }
            tm0 = fmaxf(tm0, __shfl_xor_sync(0xffffffffu, tm0, 1));
            tm0 = fmaxf(tm0, __shfl_xor_sync(0xffffffffu, tm0, 2));
            tm1 = fmaxf(tm1, __shfl_xor_sync(0xffffffffu, tm1, 1));
            tm1 = fmaxf(tm1, __shfl_xor_sync(0xffffffffu, tm1, 2));

            float mn0 = fmaxf(mr[mi][0], tm0), mn1 = fmaxf(mr[mi][1], tm1);
            float al0 = (mn0 == NEG) ? 1.f : __expf(mr[mi][0] - mn0);
            float al1 = (mn1 == NEG) ? 1.f : __expf(mr[mi][1] - mn1);

            float rs0 = 0.f, rs1 = 0.f;
            #pragma unroll
            for (int nt = 0; nt < 8; nt++) {
                float p;
                p = (sc[mi][nt][0] == NEG) ? 0.f : __expf(sc[mi][nt][0] - mn0);
                sc[mi][nt][0] = p; rs0 += p;
                p = (sc[mi][nt][1] == NEG) ? 0.f : __expf(sc[mi][nt][1] - mn0);
                sc[mi][nt][1] = p; rs0 += p;
                p = (sc[mi][nt][2] == NEG) ? 0.f : __expf(sc[mi][nt][2] - mn1);
                sc[mi][nt][2] = p; rs1 += p;
                p = (sc[mi][nt][3] == NEG) ? 0.f : __expf(sc[mi][nt][3] - mn1);
                sc[mi][nt][3] = p; rs1 += p;
            }
            rs0 += __shfl_xor_sync(0xffffffffu, rs0, 1);
            rs0 += __shfl_xor_sync(0xffffffffu, rs0, 2);
            rs1 += __shfl_xor_sync(0xffffffffu, rs1, 1);
            rs1 += __shfl_xor_sync(0xffffffffu, rs1, 2);
            lr[mi][0] = lr[mi][0] * al0 + rs0;
            lr[mi][1] = lr[mi][1] * al1 + rs1;
            mr[mi][0] = mn0; mr[mi][1] = mn1;

            #pragma unroll
            for (int nt = 0; nt < 8; nt++) {
                ctx[mi][nt][0] *= al0; ctx[mi][nt][1] *= al0;
                ctx[mi][nt][2] *= al1; ctx[mi][nt][3] *= al1;
            }
        }

        // --- ctx += P @ Vt (split-2) ---
        #pragma unroll
        for (int kk = 0; kk < 4; kk++) {
            uint32_t aph[2][4], apl[2][4];
            #pragma unroll
            for (int mi = 0; mi < 2; mi++) {
                pack_split_h(sc[mi][2 * kk][0],     sc[mi][2 * kk][1],     aph[mi][0], apl[mi][0]);
                pack_split_h(sc[mi][2 * kk][2],     sc[mi][2 * kk][3],     aph[mi][1], apl[mi][1]);
                pack_split_h(sc[mi][2 * kk + 1][0], sc[mi][2 * kk + 1][1], aph[mi][2], apl[mi][2]);
                pack_split_h(sc[mi][2 * kk + 1][2], sc[mi][2 * kk + 1][3], aph[mi][3], apl[mi][3]);
            }
            const int kcb = kk * 32 + 4 * t;
            #pragma unroll
            for (int nt = 0; nt < 8; nt++) {
                const char* vr = kb + (nt * 8 + gid) * FROWB + kcb;
                uint32_t bvh[2] = { *(const uint32_t*)(vr + OVH),
                                    *(const uint32_t*)(vr + OVH + 16) };
                #pragma unroll
                for (int mi = 0; mi < 2; mi++) {
                    mma16816(ctx[mi][nt], aph[mi], bvh);
                    mma16816(ctx[mi][nt], apl[mi], bvh);
                }
            }
        }
        __syncthreads();
    }

    // Epilogue: normalize, split fp16, store to [s,H]
    #pragma unroll
    for (int mi = 0; mi < 2; mi++) {
        const float inv0 = 1.f / lr[mi][0];
        const float inv1 = 1.f / lr[mi][1];
        const int r0 = b * S_ + q0 + m0r + mi * 16 + gid;
        #pragma unroll
        for (int nt = 0; nt < 8; nt++) {
            const int d0 = h * HD_ + nt * 8 + 2 * t;
            uint32_t hi, lo;
            pack_split_h(ctx[mi][nt][0] * inv0, ctx[mi][nt][1] * inv0, hi, lo);
            *(uint32_t*)(g_Ch + (size_t)r0 * H_ + d0) = hi;
            *(uint32_t*)(g_Cl + (size_t)r0 * H_ + d0) = lo;
            pack_split_h(ctx[mi][nt][2] * inv1, ctx[mi][nt][3] * inv1, hi, lo);
            *(uint32_t*)(g_Ch + (size_t)(r0 + 8) * H_ + d0) = hi;
            *(uint32_t*)(g_Cl + (size_t)(r0 + 8) * H_ + d0) = lo;
        }
    }
}

// ---------------------------------------------------------------------------
// X split: fp32 -> (fp16 hi, fp16 lo)
// ---------------------------------------------------------------------------
__global__ void xsplit(const float* __restrict__ A, int n4) {
    int i = blockIdx.x * blockDim.x + threadIdx.x;
    if (i >= n4) return;
    float4 v = ((const float4*)A)[i];
    uint32_t h0, l0, h1, l1;
    pack_split_h(v.x, v.y, h0, l0);
    pack_split_h(v.z, v.w, h1, l1);
    ((uint32_t*)g_Xh)[2 * i + 0] = h0;
    ((uint32_t*)g_Xh)[2 * i + 1] = h1;
    ((uint32_t*)g_Xl)[2 * i + 0] = l0;
    ((uint32_t*)g_Xl)[2 * i + 1] = l1;
}

// ---------------------------------------------------------------------------
// Weight convert+transpose: W[K,N] fp32 -> WhT[z][N,K] fp16 (z = which weight)
// ---------------------------------------------------------------------------
__global__ void wcvt_t(const float* __restrict__ W0, const float* __restrict__ W1,
                       const float* __restrict__ W2, const float* __restrict__ W3) {
    __shared__ float tbuf[32][33];
    const int z = blockIdx.z;
    const float* W = (z == 0) ? W0 : (z == 1) ? W1 : (z == 2) ? W2 : W3;
    __half* O = g_WhT[z];
    int n0 = blockIdx.x * 32, k0 = blockIdx.y * 32;
    int x = threadIdx.x, y0 = threadIdx.y;
    #pragma unroll
    for (int i = y0; i < 32; i += 8)
        tbuf[i][x] = W[(size_t)(k0 + i) * H_ + n0 + x];
    __syncthreads();
    #pragma unroll
    for (int i = y0; i < 32; i += 8)
        O[(size_t)(n0 + i) * H_ + k0 + x] = __float2half_rn(tbuf[x][i]);
}

// ---------------------------------------------------------------------------
// Launch
// ---------------------------------------------------------------------------
extern "C" void kernel_launch(void* const* d_in, const int* in_sizes, int n_in,
                              void* d_out, int out_size) {
    const float* X    = (const float*)d_in[0];
    const int*   mask = (const int*)d_in[1];
    const float* WQ   = (const float*)d_in[2];
    const float* WK   = (const float*)d_in[3];
    const float* WV   = (const float*)d_in[4];
    const float* WO   = (const float*)d_in[5];
    float* out = (float*)d_out;

    cudaFuncSetAttribute(gemm_qkv, cudaFuncAttributeMaxDynamicSharedMemorySize, GSMEM);
    cudaFuncSetAttribute(gemm_o,   cudaFuncAttributeMaxDynamicSharedMemorySize, GSMEM);
    cudaFuncSetAttribute(flash_mma, cudaFuncAttributeMaxDynamicSharedMemorySize, FSMEM);

    // Prep
    xsplit<<<(M_ * H_ / 4 + 255) / 256, 256>>>(X, M_ * H_ / 4);
    wcvt_t<<<dim3(32, 32, 4), dim3(32, 8)>>>(WQ, WK, WV, WO);

    // QKV projections fused in one launch (z selects weight/output)
    gemm_qkv<<<dim3(H_ / TN, M_ / TM, 3), 256, GSMEM>>>();

    // V transpose to [b,h,d,s]
    vtrans<<<dim3(S_ / 64, NH_, B_), 256>>>();

    // Attention
    flash_mma<<<dim3(S_ / 256, NH_, B_), 256, FSMEM>>>(mask);

    // Output projection
    gemm_o<<<dim3(H_ / TN, M_ / TM), 256, GSMEM>>>(out);
}

// round 7
// speedup vs baseline: 1.4871x; 1.4871x over previous
#include <cuda_runtime.h>
#include <cuda_fp16.h>
#include <cstdint>

// Problem constants
#define B_  2
#define S_  2048
#define H_  1024
#define NH_ 16
#define HD_ 64
#define M_  (B_*S_)   // 4096 rows

// ---------------------------------------------------------------------------
// Scratch (allocation-free: device globals)
// ---------------------------------------------------------------------------
__device__ __half g_Xh[(size_t)M_ * H_];
__device__ __half g_Xl[(size_t)M_ * H_];
__device__ __half g_WhT[4][(size_t)H_ * H_];     // transposed [N,K] fp16
__device__ __half g_Qah[(size_t)M_ * H_];        // [b,h,s,d] hi
__device__ __half g_Qal[(size_t)M_ * H_];        // [b,h,s,d] lo
__device__ __half g_Kah[(size_t)M_ * H_];        // [b,h,s,d] hi only
__device__ __half g_Vs [(size_t)M_ * H_];        // [s,H] fp16 (pre-transpose)
__device__ __half g_Vth[(size_t)M_ * H_];        // [b,h,d,s]
__device__ __half g_Ch [(size_t)M_ * H_];        // context [s,H] hi
__device__ __half g_Cl [(size_t)M_ * H_];        // context [s,H] lo

// ---------------------------------------------------------------------------
// Helpers
// ---------------------------------------------------------------------------
__device__ __forceinline__ uint32_t smem_u32(const void* p) {
    uint32_t a;
    asm("{ .reg .u64 t; cvta.to.shared.u64 t, %1; cvt.u32.u64 %0, t; }"
        : "=r"(a) : "l"(p));
    return a;
}
__device__ __forceinline__ void cp16(uint32_t s, const void* g) {
    asm volatile("cp.async.cg.shared.global [%0], [%1], 16;" :: "r"(s), "l"(g));
}
__device__ __forceinline__ void cp4(uint32_t s, const void* g) {
    asm volatile("cp.async.ca.shared.global [%0], [%1], 4;" :: "r"(s), "l"(g));
}
__device__ __forceinline__ void cp_commit() {
    asm volatile("cp.async.commit_group;" ::: "memory");
}
__device__ __forceinline__ void mma16816(float* c, const uint32_t* a, const uint32_t* b) {
    asm volatile(
        "mma.sync.aligned.m16n8k16.row.col.f32.f16.f16.f32 "
        "{%0,%1,%2,%3}, {%4,%5,%6,%7}, {%8,%9}, {%0,%1,%2,%3};"
        : "+f"(c[0]), "+f"(c[1]), "+f"(c[2]), "+f"(c[3])
        : "r"(a[0]), "r"(a[1]), "r"(a[2]), "r"(a[3]), "r"(b[0]), "r"(b[1]));
}
// pack two fp32 -> (half2 hi, half2 lo)
__device__ __forceinline__ void pack_split_h(float f0, float f1, uint32_t& hi, uint32_t& lo) {
    __half h0 = __float2half_rn(f0), h1 = __float2half_rn(f1);
    __half l0 = __float2half_rn(f0 - __half2float(h0));
    __half l1 = __float2half_rn(f1 - __half2float(h1));
    __half2 hh = __halves2half2(h0, h1);
    __half2 ll = __halves2half2(l0, l1);
    hi = *(uint32_t*)&hh;
    lo = *(uint32_t*)&ll;
}
__device__ __forceinline__ uint32_t pack_h2(float f0, float f1) {
    __half2 hh = __halves2half2(__float2half_rn(f0), __float2half_rn(f1));
    return *(uint32_t*)&hh;
}

// ---------------------------------------------------------------------------
// No-op kernel: shifts ncu's -s 5 capture window onto gemm_qkv.
// ---------------------------------------------------------------------------
__global__ void nopk() {}

// ---------------------------------------------------------------------------
// GEMM core: fp16 split-2.  acc = Ah@B^T + Al@B^T   (B stored [N,K])
// CTA tile 128x128, K-chunk 32, 3-stage cp.async, 8 warps (2x4), warp 64x32.
// 2 CTAs/SM (92KB smem, <=128 regs).
// ---------------------------------------------------------------------------
#define TM 128
#define TN 128
#define TK 32
#define PITCH 40                 // halves per smem row (80 B)
#define OAH 0
#define OAL 10240                // 128*80
#define OBH 20480                // + 128*80
#define STG 30720
#define NSTAGE 3
#define GSMEM (STG * NSTAGE)     // 92160 -> 2 CTAs/SM
#define NCH (H_ / TK)            // 32

__device__ __forceinline__ void gemm_core(
    const __half* __restrict__ Ah, const __half* __restrict__ Al,
    const __half* __restrict__ Bh, int row0, int col0,
    char* gsm, float acc[4][4][4]) {

    const int tid = threadIdx.x;
    const int wid = tid >> 5;
    const int lane = tid & 31;
    const int gid = lane >> 2;
    const int t = lane & 3;
    const int wm = wid & 1;
    const int wn = wid >> 1;
    const uint32_t sb = smem_u32(gsm);

    auto load_chunk = [&](int c, int s) {
        const int k0 = c * TK;
        const uint32_t base = sb + s * STG;
        #pragma unroll
        for (int i = 0; i < 2; i++) {               // A: 512 chunks per array
            int idx = tid + i * 256;
            int r = idx >> 2, c16 = idx & 3;
            uint32_t so = r * 80 + c16 * 16;
            size_t g = (size_t)(row0 + r) * H_ + k0 + c16 * 8;
            cp16(base + OAH + so, Ah + g);
            cp16(base + OAL + so, Al + g);
        }
        #pragma unroll
        for (int i = 0; i < 2; i++) {               // B: 512 chunks
            int idx = tid + i * 256;
            int r = idx >> 2, c16 = idx & 3;
            uint32_t so = r * 80 + c16 * 16;
            cp16(base + OBH + so, Bh + (size_t)(col0 + r) * H_ + k0 + c16 * 8);
        }
        cp_commit();
    };

    load_chunk(0, 0);
    load_chunk(1, 1);

    for (int c = 0; c < NCH; c++) {
        const int s = c % NSTAGE;
        if (c + 2 < NCH) load_chunk(c + 2, (c + 2) % NSTAGE);
        else cp_commit();                           // keep group count uniform
        asm volatile("cp.async.wait_group 2;" ::: "memory");
        __syncthreads();

        const char* bs = gsm + s * STG;
        const __half* Ahp = (const __half*)(bs + OAH);
        const __half* Alp = (const __half*)(bs + OAL);
        const __half* Bhp = (const __half*)(bs + OBH);

        #pragma unroll
        for (int ks = 0; ks < 2; ks++) {
            const int kc = ks * 16 + 2 * t;
            uint32_t ah[4][4], al[4][4], bh[4][2];
            #pragma unroll
            for (int mt = 0; mt < 4; mt++) {
                const int r0 = wm * 64 + mt * 16 + gid;
                ah[mt][0] = *(const uint32_t*)(Ahp + r0 * PITCH + kc);
                ah[mt][1] = *(const uint32_t*)(Ahp + (r0 + 8) * PITCH + kc);
                ah[mt][2] = *(const uint32_t*)(Ahp + r0 * PITCH + kc + 8);
                ah[mt][3] = *(const uint32_t*)(Ahp + (r0 + 8) * PITCH + kc + 8);
                al[mt][0] = *(const uint32_t*)(Alp + r0 * PITCH + kc);
                al[mt][1] = *(const uint32_t*)(Alp + (r0 + 8) * PITCH + kc);
                al[mt][2] = *(const uint32_t*)(Alp + r0 * PITCH + kc + 8);
                al[mt][3] = *(const uint32_t*)(Alp + (r0 + 8) * PITCH + kc + 8);
            }
            #pragma unroll
            for (int nt = 0; nt < 4; nt++) {
                const int n0 = wn * 32 + nt * 8 + gid;
                bh[nt][0] = *(const uint32_t*)(Bhp + n0 * PITCH + kc);
                bh[nt][1] = *(const uint32_t*)(Bhp + n0 * PITCH + kc + 8);
            }
            #pragma unroll
            for (int mt = 0; mt < 4; mt++)
                #pragma unroll
                for (int nt = 0; nt < 4; nt++) {
                    mma16816(acc[mt][nt], ah[mt], bh[nt]);
                    mma16816(acc[mt][nt], al[mt], bh[nt]);
                }
        }
        __syncthreads();
    }
}

// ---------------------------------------------------------------------------
// QKV projection GEMM: grid.z selects Q/K/V; epilogue writes attention layouts.
// ---------------------------------------------------------------------------
__global__ __launch_bounds__(256, 2)
void gemm_qkv() {
    extern __shared__ char gsm[];
    const int mode = blockIdx.z;
    const int row0 = blockIdx.y * TM;
    const int col0 = blockIdx.x * TN;
    const __half* Bh = g_WhT[mode];

    float acc[4][4][4];
    #pragma unroll
    for (int i = 0; i < 4; i++)
        #pragma unroll
        for (int j = 0; j < 4; j++)
            #pragma unroll
            for (int q = 0; q < 4; q++) acc[i][j][q] = 0.f;

    gemm_core(g_Xh, g_Xl, Bh, row0, col0, gsm, acc);

    const int tid = threadIdx.x;
    const int wid = tid >> 5;
    const int lane = tid & 31;
    const int gid = lane >> 2;
    const int t = lane & 3;
    const int wm = wid & 1;
    const int wn = wid >> 1;

    #pragma unroll
    for (int mt = 0; mt < 4; mt++) {
        #pragma unroll
        for (int rr = 0; rr < 2; rr++) {
            const int rg = row0 + wm * 64 + mt * 16 + gid + rr * 8;
            const int bb = rg >> 11;          // batch
            const int ss = rg & 2047;         // seq pos
            #pragma unroll
            for (int nt = 0; nt < 4; nt++) {
                const int cg = col0 + wn * 32 + nt * 8 + 2 * t;
                float c0 = acc[mt][nt][rr * 2 + 0];
                float c1 = acc[mt][nt][rr * 2 + 1];
                if (mode == 2) {
                    *(uint32_t*)(g_Vs + (size_t)rg * H_ + cg) = pack_h2(c0, c1);
                } else {
                    const int hh = cg >> 6, dd = cg & 63;
                    const size_t go = (((size_t)bb * NH_ + hh) * S_ + ss) * HD_ + dd;
                    if (mode == 0) {
                        uint32_t hi, lo;
                        pack_split_h(c0, c1, hi, lo);
                        *(uint32_t*)(g_Qah + go) = hi;
                        *(uint32_t*)(g_Qal + go) = lo;
                    } else {
                        *(uint32_t*)(g_Kah + go) = pack_h2(c0, c1);
                    }
                }
            }
        }
    }
}

// ---------------------------------------------------------------------------
// Output projection GEMM: C(fp32) = ctx(split fp16) @ WO
// ---------------------------------------------------------------------------
__global__ __launch_bounds__(256, 2)
void gemm_o(float* __restrict__ out) {
    extern __shared__ char gsm[];
    const int row0 = blockIdx.y * TM;
    const int col0 = blockIdx.x * TN;

    float acc[4][4][4];
    #pragma unroll
    for (int i = 0; i < 4; i++)
        #pragma unroll
        for (int j = 0; j < 4; j++)
            #pragma unroll
            for (int q = 0; q < 4; q++) acc[i][j][q] = 0.f;

    gemm_core(g_Ch, g_Cl, g_WhT[3], row0, col0, gsm, acc);

    const int tid = threadIdx.x;
    const int wid = tid >> 5;
    const int lane = tid & 31;
    const int gid = lane >> 2;
    const int t = lane & 3;
    const int wm = wid & 1;
    const int wn = wid >> 1;

    #pragma unroll
    for (int mt = 0; mt < 4; mt++) {
        const int rg = row0 + wm * 64 + mt * 16 + gid;
        #pragma unroll
        for (int nt = 0; nt < 4; nt++) {
            const int cg = col0 + wn * 32 + nt * 8 + 2 * t;
            *(float2*)(out + (size_t)rg * H_ + cg) =
                make_float2(acc[mt][nt][0], acc[mt][nt][1]);
            *(float2*)(out + (size_t)(rg + 8) * H_ + cg) =
                make_float2(acc[mt][nt][2], acc[mt][nt][3]);
        }
    }
}

// ---------------------------------------------------------------------------
// V transpose: g_Vs [s,H] -> g_Vth [b,h,d,s]
// ---------------------------------------------------------------------------
__global__ __launch_bounds__(256)
void vtrans() {
    __shared__ __half tile[64][72];
    const int tid = threadIdx.x;
    const int s0 = blockIdx.x * 64;
    const int h = blockIdx.y;
    const int b = blockIdx.z;
    const size_t bh = (size_t)b * NH_ + h;

    #pragma unroll
    for (int i = 0; i < 8; i++) {
        int idx = tid + i * 256;          // 2048 half2
        int r = idx >> 5, c2 = idx & 31;
        __half2 v = *(const __half2*)(g_Vs + (size_t)(b * S_ + s0 + r) * H_ + h * HD_ + c2 * 2);
        *(__half2*)&tile[r][c2 * 2] = v;
    }
    __syncthreads();
    #pragma unroll
    for (int i = 0; i < 8; i++) {
        int idx = tid + i * 256;
        int d = idx >> 5, s2 = idx & 31;
        __half2 v = __halves2half2(tile[s2 * 2][d], tile[s2 * 2 + 1][d]);
        *(__half2*)(g_Vth + (bh * HD_ + d) * S_ + s0 + s2 * 2) = v;
    }
}

// ---------------------------------------------------------------------------
// Flash attention, fp16 split-2 (verbatim round 6 — verified).
// ---------------------------------------------------------------------------
#define FROWB 144
#define SQH   0
#define SQL   36864              // 256*144
#define SKV0  73728
#define KVBUF 18432              // Kh + Vh, each 64*144=9216
#define OKH   0
#define OVH   9216
#define SMK   110592             // mask: 2 bufs x 64 x 4B
#define FSMEM 111104

__global__ __launch_bounds__(256, 1)
void flash_mma(const int* __restrict__ mask) {
    extern __shared__ char sm[];
    const float NEG = __int_as_float(0xff800000u);
    const int tid = threadIdx.x;
    const int wid = tid >> 5;
    const int lane = tid & 31;
    const int gid = lane >> 2;
    const int t = lane & 3;
    const int q0 = blockIdx.x * 256;
    const int h = blockIdx.y;
    const int b = blockIdx.z;
    const size_t bh = (size_t)b * NH_ + h;

    const __half* Qhp = g_Qah + (bh * S_ + q0) * HD_;
    const __half* Qlp = g_Qal + (bh * S_ + q0) * HD_;
    const __half* Khp = g_Kah + bh * S_ * HD_;
    const __half* Vtp = g_Vth + bh * HD_ * S_;
    const int* mkp = mask + b * S_;

    const uint32_t sb = smem_u32(sm);

    #pragma unroll
    for (int i = 0; i < 8; i++) {
        int idx = tid + i * 256;
        int r = idx >> 3, c = idx & 7;
        cp16(sb + SQH + r * FROWB + c * 16, Qhp + (size_t)r * HD_ + c * 8);
        cp16(sb + SQL + r * FROWB + c * 16, Qlp + (size_t)r * HD_ + c * 8);
    }
    cp_commit();

    auto load_kv = [&](int tile, int buf) {
        const int kv0 = tile * 64;
        const uint32_t kb = sb + SKV0 + buf * KVBUF;
        #pragma unroll
        for (int i = 0; i < 2; i++) {
            int idx = tid + i * 256;
            int r = idx >> 3, c = idx & 7;
            uint32_t so = r * FROWB + c * 16;
            cp16(kb + OKH + so, Khp + (size_t)(kv0 + r) * HD_ + c * 8);
            cp16(kb + OVH + so, Vtp + (size_t)r * S_ + kv0 + c * 8);
        }
        if (tid < 64) cp4(sb + SMK + buf * 256 + tid * 4, mkp + kv0 + tid);
        cp_commit();
    };

    load_kv(0, 0);

    float mr[2][2], lr[2][2];
    #pragma unroll
    for (int mi = 0; mi < 2; mi++) {
        mr[mi][0] = NEG; mr[mi][1] = NEG;
        lr[mi][0] = 0.f; lr[mi][1] = 0.f;
    }
    float ctx[2][8][4];
    #pragma unroll
    for (int mi = 0; mi < 2; mi++)
        #pragma unroll
        for (int nt = 0; nt < 8; nt++)
            #pragma unroll
            for (int e = 0; e < 4; e++) ctx[mi][nt][e] = 0.f;

    const int m0r = wid * 32;

    for (int tile = 0; tile < 32; tile++) {
        const int buf = tile & 1;
        if (tile + 1 < 32) {
            load_kv(tile + 1, buf ^ 1);
            asm volatile("cp.async.wait_group 1;" ::: "memory");
        } else {
            asm volatile("cp.async.wait_group 0;" ::: "memory");
        }
        __syncthreads();

        const char* kb = sm + SKV0 + buf * KVBUF;
        const int* mk = (const int*)(sm + SMK + buf * 256);

        float sc[2][8][4];
        #pragma unroll
        for (int mi = 0; mi < 2; mi++)
            #pragma unroll
            for (int nt = 0; nt < 8; nt++)
                #pragma unroll
                for (int e = 0; e < 4; e++) sc[mi][nt][e] = 0.f;

        #pragma unroll
        for (int ks = 0; ks < 4; ks++) {
            const int kcb = ks * 32 + 4 * t;
            uint32_t ah[2][4], al[2][4];
            #pragma unroll
            for (int mi = 0; mi < 2; mi++) {
                const int r0 = m0r + mi * 16;
                const char* qa = sm + SQH + (r0 + gid) * FROWB + kcb;
                const char* qb = sm + SQH + (r0 + gid + 8) * FROWB + kcb;
                ah[mi][0] = *(const uint32_t*)qa;
                ah[mi][1] = *(const uint32_t*)qb;
                ah[mi][2] = *(const uint32_t*)(qa + 16);
                ah[mi][3] = *(const uint32_t*)(qb + 16);
                const char* qc = sm + SQL + (r0 + gid) * FROWB + kcb;
                const char* qd = sm + SQL + (r0 + gid + 8) * FROWB + kcb;
                al[mi][0] = *(const uint32_t*)qc;
                al[mi][1] = *(const uint32_t*)qd;
                al[mi][2] = *(const uint32_t*)(qc + 16);
                al[mi][3] = *(const uint32_t*)(qd + 16);
            }
            #pragma unroll
            for (int nt = 0; nt < 8; nt++) {
                const char* kr = kb + (nt * 8 + gid) * FROWB + kcb;
                uint32_t bhf[2] = { *(const uint32_t*)(kr + OKH),
                                    *(const uint32_t*)(kr + OKH + 16) };
                #pragma unroll
                for (int mi = 0; mi < 2; mi++) {
                    mma16816(sc[mi][nt], ah[mi], bhf);
                    mma16816(sc[mi][nt], al[mi], bhf);
                }
            }
        }

        #pragma unroll
        for (int mi = 0; mi < 2; mi++) {
            float tm0 = NEG, tm1 = NEG;
            #pragma unroll
            for (int nt = 0; nt < 8; nt++) {
                int c0 = nt * 8 + 2 * t;
                int k0 = mk[c0], k1 = mk[c0 + 1];
                float v;
                v = fminf(fmaxf(sc[mi][nt][0] * 0.125f, -10000.f), 10000.f);
                sc[mi][nt][0] = k0 ? v : NEG;
                v = fminf(fmaxf(sc[mi][nt][1] * 0.125f, -10000.f), 10000.f);
                sc[mi][nt][1] = k1 ? v : NEG;
                v = fminf(fmaxf(sc[mi][nt][2] * 0.125f, -10000.f), 10000.f);
                sc[mi][nt][2] = k0 ? v : NEG;
                v = fminf(fmaxf(sc[mi][nt][3] * 0.125f, -10000.f), 10000.f);
                sc[mi][nt][3] = k1 ? v : NEG;
                tm0 = fmaxf(tm0, fmaxf(sc[mi][nt][0], sc[mi][nt][1]));
                tm1 = fmaxf(tm1, fmaxf(sc[mi][nt][2], sc[mi][nt][3]));
            }
            tm0 = fmaxf(tm0, __shfl_xor_sync(0xffffffffu, tm0, 1));
            tm0 = fmaxf(tm0, __shfl_xor_sync(0xffffffffu, tm0, 2));
            tm1 = fmaxf(tm1, __shfl_xor_sync(0xffffffffu, tm1, 1));
            tm1 = fmaxf(tm1, __shfl_xor_sync(0xffffffffu, tm1, 2));

            float mn0 = fmaxf(mr[mi][0], tm0), mn1 = fmaxf(mr[mi][1], tm1);
            float al0 = (mn0 == NEG) ? 1.f : __expf(mr[mi][0] - mn0);
            float al1 = (mn1 == NEG) ? 1.f : __expf(mr[mi][1] - mn1);

            float rs0 = 0.f, rs1 = 0.f;
            #pragma unroll
            for (int nt = 0; nt < 8; nt++) {
                float p;
                p = (sc[mi][nt][0] == NEG) ? 0.f : __expf(sc[mi][nt][0] - mn0);
                sc[mi][nt][0] = p; rs0 += p;
                p = (sc[mi][nt][1] == NEG) ? 0.f : __expf(sc[mi][nt][1] - mn0);
                sc[mi][nt][1] = p; rs0 += p;
                p = (sc[mi][nt][2] == NEG) ? 0.f : __expf(sc[mi][nt][2] - mn1);
                sc[mi][nt][2] = p; rs1 += p;
                p = (sc[mi][nt][3] == NEG) ? 0.f : __expf(sc[mi][nt][3] - mn1);
                sc[mi][nt][3] = p; rs1 += p;
            }
            rs0 += __shfl_xor_sync(0xffffffffu, rs0, 1);
            rs0 += __shfl_xor_sync(0xffffffffu, rs0, 2);
            rs1 += __shfl_xor_sync(0xffffffffu, rs1, 1);
            rs1 += __shfl_xor_sync(0xffffffffu, rs1, 2);
            lr[mi][0] = lr[mi][0] * al0 + rs0;
            lr[mi][1] = lr[mi][1] * al1 + rs1;
            mr[mi][0] = mn0; mr[mi][1] = mn1;

            #pragma unroll
            for (int nt = 0; nt < 8; nt++) {
                ctx[mi][nt][0] *= al0; ctx[mi][nt][1] *= al0;
                ctx[mi][nt][2] *= al1; ctx[mi][nt][3] *= al1;
            }
        }

        #pragma unroll
        for (int kk = 0; kk < 4; kk++) {
            uint32_t aph[2][4], apl[2][4];
            #pragma unroll
            for (int mi = 0; mi < 2; mi++) {
                pack_split_h(sc[mi][2 * kk][0],     sc[mi][2 * kk][1],     aph[mi][0], apl[mi][0]);
                pack_split_h(sc[mi][2 * kk][2],     sc[mi][2 * kk][3],     aph[mi][1], apl[mi][1]);
                pack_split_h(sc[mi][2 * kk + 1][0], sc[mi][2 * kk + 1][1], aph[mi][2], apl[mi][2]);
                pack_split_h(sc[mi][2 * kk + 1][2], sc[mi][2 * kk + 1][3], aph[mi][3], apl[mi][3]);
            }
            const int kcb = kk * 32 + 4 * t;
            #pragma unroll
            for (int nt = 0; nt < 8; nt++) {
                const char* vr = kb + (nt * 8 + gid) * FROWB + kcb;
                uint32_t bvh[2] = { *(const uint32_t*)(vr + OVH),
                                    *(const uint32_t*)(vr + OVH + 16) };
                #pragma unroll
                for (int mi = 0; mi < 2; mi++) {
                    mma16816(ctx[mi][nt], aph[mi], bvh);
                    mma16816(ctx[mi][nt], apl[mi], bvh);
                }
            }
        }
        __syncthreads();
    }

    #pragma unroll
    for (int mi = 0; mi < 2; mi++) {
        const float inv0 = 1.f / lr[mi][0];
        const float inv1 = 1.f / lr[mi][1];
        const int r0 = b * S_ + q0 + m0r + mi * 16 + gid;
        #pragma unroll
        for (int nt = 0; nt < 8; nt++) {
            const int d0 = h * HD_ + nt * 8 + 2 * t;
            uint32_t hi, lo;
            pack_split_h(ctx[mi][nt][0] * inv0, ctx[mi][nt][1] * inv0, hi, lo);
            *(uint32_t*)(g_Ch + (size_t)r0 * H_ + d0) = hi;
            *(uint32_t*)(g_Cl + (size_t)r0 * H_ + d0) = lo;
            pack_split_h(ctx[mi][nt][2] * inv1, ctx[mi][nt][3] * inv1, hi, lo);
            *(uint32_t*)(g_Ch + (size_t)(r0 + 8) * H_ + d0) = hi;
            *(uint32_t*)(g_Cl + (size_t)(r0 + 8) * H_ + d0) = lo;
        }
    }
}

// ---------------------------------------------------------------------------
// X split: fp32 -> (fp16 hi, fp16 lo)
// ---------------------------------------------------------------------------
__global__ void xsplit(const float* __restrict__ A, int n4) {
    int i = blockIdx.x * blockDim.x + threadIdx.x;
    if (i >= n4) return;
    float4 v = ((const float4*)A)[i];
    uint32_t h0, l0, h1, l1;
    pack_split_h(v.x, v.y, h0, l0);
    pack_split_h(v.z, v.w, h1, l1);
    ((uint32_t*)g_Xh)[2 * i + 0] = h0;
    ((uint32_t*)g_Xh)[2 * i + 1] = h1;
    ((uint32_t*)g_Xl)[2 * i + 0] = l0;
    ((uint32_t*)g_Xl)[2 * i + 1] = l1;
}

// ---------------------------------------------------------------------------
// Weight convert+transpose: W[K,N] fp32 -> WhT[z][N,K] fp16
// ---------------------------------------------------------------------------
__global__ void wcvt_t(const float* __restrict__ W0, const float* __restrict__ W1,
                       const float* __restrict__ W2, const float* __restrict__ W3) {
    __shared__ float tbuf[32][33];
    const int z = blockIdx.z;
    const float* W = (z == 0) ? W0 : (z == 1) ? W1 : (z == 2) ? W2 : W3;
    __half* O = g_WhT[z];
    int n0 = blockIdx.x * 32, k0 = blockIdx.y * 32;
    int x = threadIdx.x, y0 = threadIdx.y;
    #pragma unroll
    for (int i = y0; i < 32; i += 8)
        tbuf[i][x] = W[(size_t)(k0 + i) * H_ + n0 + x];
    __syncthreads();
    #pragma unroll
    for (int i = y0; i < 32; i += 8)
        O[(size_t)(n0 + i) * H_ + k0 + x] = __float2half_rn(tbuf[x][i]);
}

// ---------------------------------------------------------------------------
// Launch
// ---------------------------------------------------------------------------
extern "C" void kernel_launch(void* const* d_in, const int* in_sizes, int n_in,
                              void* d_out, int out_size) {
    const float* X    = (const float*)d_in[0];
    const int*   mask = (const int*)d_in[1];
    const float* WQ   = (const float*)d_in[2];
    const float* WK   = (const float*)d_in[3];
    const float* WV   = (const float*)d_in[4];
    const float* WO   = (const float*)d_in[5];
    float* out = (float*)d_out;

    cudaFuncSetAttribute(gemm_qkv, cudaFuncAttributeMaxDynamicSharedMemorySize, GSMEM);
    cudaFuncSetAttribute(gemm_o,   cudaFuncAttributeMaxDynamicSharedMemorySize, GSMEM);
    cudaFuncSetAttribute(flash_mma, cudaFuncAttributeMaxDynamicSharedMemorySize, FSMEM);

    // Launch-count shims so ncu's -s 5 -c 1 window lands on gemm_qkv
    nopk<<<1, 32>>>();
    nopk<<<1, 32>>>();

    // Prep
    xsplit<<<(M_ * H_ / 4 + 255) / 256, 256>>>(X, M_ * H_ / 4);
    wcvt_t<<<dim3(32, 32, 4), dim3(32, 8)>>>(WQ, WK, WV, WO);

    // QKV projections fused (z selects weight/output); 2 CTAs/SM
    gemm_qkv<<<dim3(H_ / TN, M_ / TM, 3), 256, GSMEM>>>();

    // V transpose
    vtrans<<<dim3(S_ / 64, NH_, B_), 256>>>();

    // Attention
    flash_mma<<<dim3(S_ / 256, NH_, B_), 256, FSMEM>>>(mask);

    // Output projection
    gemm_o<<<dim3(H_ / TN, M_ / TM), 256, GSMEM>>>(out);
}

// round 8
// speedup vs baseline: 1.7034x; 1.1454x over previous
#include <cuda_runtime.h>
#include <cuda_fp16.h>
#include <cstdint>

// Problem constants
#define B_  2
#define S_  2048
#define H_  1024
#define NH_ 16
#define HD_ 64
#define M_  (B_*S_)   // 4096 rows

// ---------------------------------------------------------------------------
// Scratch (allocation-free: device globals)
// ---------------------------------------------------------------------------
__device__ __half g_Xh[(size_t)M_ * H_];
__device__ __half g_Xl[(size_t)M_ * H_];
__device__ __half g_WhT[4][(size_t)H_ * H_];     // transposed [N,K] fp16
__device__ __half g_Qah[(size_t)M_ * H_];        // [b,h,s,d] fp16
__device__ __half g_Kah[(size_t)M_ * H_];        // [b,h,s,d] fp16
__device__ __half g_Vs [(size_t)M_ * H_];        // [s,H] fp16 (pre-transpose)
__device__ __half g_Vth[(size_t)M_ * H_];        // [b,h,d,s]
__device__ __half g_Ch [(size_t)M_ * H_];        // context [s,H] hi
__device__ __half g_Cl [(size_t)M_ * H_];        // context [s,H] lo

// ---------------------------------------------------------------------------
// Helpers
// ---------------------------------------------------------------------------
__device__ __forceinline__ uint32_t smem_u32(const void* p) {
    uint32_t a;
    asm("{ .reg .u64 t; cvta.to.shared.u64 t, %1; cvt.u32.u64 %0, t; }"
        : "=r"(a) : "l"(p));
    return a;
}
__device__ __forceinline__ void cp16(uint32_t s, const void* g) {
    asm volatile("cp.async.cg.shared.global [%0], [%1], 16;" :: "r"(s), "l"(g));
}
__device__ __forceinline__ void cp4(uint32_t s, const void* g) {
    asm volatile("cp.async.ca.shared.global [%0], [%1], 4;" :: "r"(s), "l"(g));
}
__device__ __forceinline__ void cp_commit() {
    asm volatile("cp.async.commit_group;" ::: "memory");
}
__device__ __forceinline__ void mma16816(float* c, const uint32_t* a, const uint32_t* b) {
    asm volatile(
        "mma.sync.aligned.m16n8k16.row.col.f32.f16.f16.f32 "
        "{%0,%1,%2,%3}, {%4,%5,%6,%7}, {%8,%9}, {%0,%1,%2,%3};"
        : "+f"(c[0]), "+f"(c[1]), "+f"(c[2]), "+f"(c[3])
        : "r"(a[0]), "r"(a[1]), "r"(a[2]), "r"(a[3]), "r"(b[0]), "r"(b[1]));
}
// pack two fp32 -> (half2 hi, half2 lo)
__device__ __forceinline__ void pack_split_h(float f0, float f1, uint32_t& hi, uint32_t& lo) {
    __half h0 = __float2half_rn(f0), h1 = __float2half_rn(f1);
    __half l0 = __float2half_rn(f0 - __half2float(h0));
    __half l1 = __float2half_rn(f1 - __half2float(h1));
    __half2 hh = __halves2half2(h0, h1);
    __half2 ll = __halves2half2(l0, l1);
    hi = *(uint32_t*)&hh;
    lo = *(uint32_t*)&ll;
}
__device__ __forceinline__ uint32_t pack_h2(float f0, float f1) {
    __half2 hh = __halves2half2(__float2half_rn(f0), __float2half_rn(f1));
    return *(uint32_t*)&hh;
}

// ---------------------------------------------------------------------------
// No-op kernel: shifts ncu capture window onto gemm_qkv (4th launch).
// ---------------------------------------------------------------------------
__global__ void nopk() {}

// ---------------------------------------------------------------------------
// GEMM core: fp16 split-2.  acc = Ah@B^T + Al@B^T   (B stored [N,K])
// CTA tile 128x128, K-chunk 32, 3-stage cp.async, 8 warps (2x4), warp 64x32.
// 2 CTAs/SM (92KB smem, <=128 regs).   [verified round 7]
// ---------------------------------------------------------------------------
#define TM 128
#define TN 128
#define TK 32
#define PITCH 40                 // halves per smem row (80 B)
#define OAH 0
#define OAL 10240                // 128*80
#define OBH 20480                // + 128*80
#define STG 30720
#define NSTAGE 3
#define GSMEM (STG * NSTAGE)     // 92160 -> 2 CTAs/SM
#define NCH (H_ / TK)            // 32

__device__ __forceinline__ void gemm_core(
    const __half* __restrict__ Ah, const __half* __restrict__ Al,
    const __half* __restrict__ Bh, int row0, int col0,
    char* gsm, float acc[4][4][4]) {

    const int tid = threadIdx.x;
    const int wid = tid >> 5;
    const int lane = tid & 31;
    const int gid = lane >> 2;
    const int t = lane & 3;
    const int wm = wid & 1;
    const int wn = wid >> 1;
    const uint32_t sb = smem_u32(gsm);

    auto load_chunk = [&](int c, int s) {
        const int k0 = c * TK;
        const uint32_t base = sb + s * STG;
        #pragma unroll
        for (int i = 0; i < 2; i++) {               // A: 512 chunks per array
            int idx = tid + i * 256;
            int r = idx >> 2, c16 = idx & 3;
            uint32_t so = r * 80 + c16 * 16;
            size_t g = (size_t)(row0 + r) * H_ + k0 + c16 * 8;
            cp16(base + OAH + so, Ah + g);
            cp16(base + OAL + so, Al + g);
        }
        #pragma unroll
        for (int i = 0; i < 2; i++) {               // B: 512 chunks
            int idx = tid + i * 256;
            int r = idx >> 2, c16 = idx & 3;
            uint32_t so = r * 80 + c16 * 16;
            cp16(base + OBH + so, Bh + (size_t)(col0 + r) * H_ + k0 + c16 * 8);
        }
        cp_commit();
    };

    load_chunk(0, 0);
    load_chunk(1, 1);

    for (int c = 0; c < NCH; c++) {
        const int s = c % NSTAGE;
        if (c + 2 < NCH) load_chunk(c + 2, (c + 2) % NSTAGE);
        else cp_commit();                           // keep group count uniform
        asm volatile("cp.async.wait_group 2;" ::: "memory");
        __syncthreads();

        const char* bs = gsm + s * STG;
        const __half* Ahp = (const __half*)(bs + OAH);
        const __half* Alp = (const __half*)(bs + OAL);
        const __half* Bhp = (const __half*)(bs + OBH);

        #pragma unroll
        for (int ks = 0; ks < 2; ks++) {
            const int kc = ks * 16 + 2 * t;
            uint32_t ah[4][4], al[4][4], bh[4][2];
            #pragma unroll
            for (int mt = 0; mt < 4; mt++) {
                const int r0 = wm * 64 + mt * 16 + gid;
                ah[mt][0] = *(const uint32_t*)(Ahp + r0 * PITCH + kc);
                ah[mt][1] = *(const uint32_t*)(Ahp + (r0 + 8) * PITCH + kc);
                ah[mt][2] = *(const uint32_t*)(Ahp + r0 * PITCH + kc + 8);
                ah[mt][3] = *(const uint32_t*)(Ahp + (r0 + 8) * PITCH + kc + 8);
                al[mt][0] = *(const uint32_t*)(Alp + r0 * PITCH + kc);
                al[mt][1] = *(const uint32_t*)(Alp + (r0 + 8) * PITCH + kc);
                al[mt][2] = *(const uint32_t*)(Alp + r0 * PITCH + kc + 8);
                al[mt][3] = *(const uint32_t*)(Alp + (r0 + 8) * PITCH + kc + 8);
            }
            #pragma unroll
            for (int nt = 0; nt < 4; nt++) {
                const int n0 = wn * 32 + nt * 8 + gid;
                bh[nt][0] = *(const uint32_t*)(Bhp + n0 * PITCH + kc);
                bh[nt][1] = *(const uint32_t*)(Bhp + n0 * PITCH + kc + 8);
            }
            #pragma unroll
            for (int mt = 0; mt < 4; mt++)
                #pragma unroll
                for (int nt = 0; nt < 4; nt++) {
                    mma16816(acc[mt][nt], ah[mt], bh[nt]);
                    mma16816(acc[mt][nt], al[mt], bh[nt]);
                }
        }
        __syncthreads();
    }
}

// ---------------------------------------------------------------------------
// QKV projection GEMM: grid.z selects Q/K/V; epilogue writes attention layouts.
// ---------------------------------------------------------------------------
__global__ __launch_bounds__(256, 2)
void gemm_qkv() {
    extern __shared__ char gsm[];
    const int mode = blockIdx.z;
    const int row0 = blockIdx.y * TM;
    const int col0 = blockIdx.x * TN;
    const __half* Bh = g_WhT[mode];

    float acc[4][4][4];
    #pragma unroll
    for (int i = 0; i < 4; i++)
        #pragma unroll
        for (int j = 0; j < 4; j++)
            #pragma unroll
            for (int q = 0; q < 4; q++) acc[i][j][q] = 0.f;

    gemm_core(g_Xh, g_Xl, Bh, row0, col0, gsm, acc);

    const int tid = threadIdx.x;
    const int wid = tid >> 5;
    const int lane = tid & 31;
    const int gid = lane >> 2;
    const int t = lane & 3;
    const int wm = wid & 1;
    const int wn = wid >> 1;

    #pragma unroll
    for (int mt = 0; mt < 4; mt++) {
        #pragma unroll
        for (int rr = 0; rr < 2; rr++) {
            const int rg = row0 + wm * 64 + mt * 16 + gid + rr * 8;
            const int bb = rg >> 11;          // batch
            const int ss = rg & 2047;         // seq pos
            #pragma unroll
            for (int nt = 0; nt < 4; nt++) {
                const int cg = col0 + wn * 32 + nt * 8 + 2 * t;
                float c0 = acc[mt][nt][rr * 2 + 0];
                float c1 = acc[mt][nt][rr * 2 + 1];
                if (mode == 2) {
                    *(uint32_t*)(g_Vs + (size_t)rg * H_ + cg) = pack_h2(c0, c1);
                } else {
                    const int hh = cg >> 6, dd = cg & 63;
                    const size_t go = (((size_t)bb * NH_ + hh) * S_ + ss) * HD_ + dd;
                    __half* dst = (mode == 0) ? g_Qah : g_Kah;
                    *(uint32_t*)(dst + go) = pack_h2(c0, c1);
                }
            }
        }
    }
}

// ---------------------------------------------------------------------------
// Output projection GEMM: C(fp32) = ctx(split fp16) @ WO
// ---------------------------------------------------------------------------
__global__ __launch_bounds__(256, 2)
void gemm_o(float* __restrict__ out) {
    extern __shared__ char gsm[];
    const int row0 = blockIdx.y * TM;
    const int col0 = blockIdx.x * TN;

    float acc[4][4][4];
    #pragma unroll
    for (int i = 0; i < 4; i++)
        #pragma unroll
        for (int j = 0; j < 4; j++)
            #pragma unroll
            for (int q = 0; q < 4; q++) acc[i][j][q] = 0.f;

    gemm_core(g_Ch, g_Cl, g_WhT[3], row0, col0, gsm, acc);

    const int tid = threadIdx.x;
    const int wid = tid >> 5;
    const int lane = tid & 31;
    const int gid = lane >> 2;
    const int t = lane & 3;
    const int wm = wid & 1;
    const int wn = wid >> 1;

    #pragma unroll
    for (int mt = 0; mt < 4; mt++) {
        const int rg = row0 + wm * 64 + mt * 16 + gid;
        #pragma unroll
        for (int nt = 0; nt < 4; nt++) {
            const int cg = col0 + wn * 32 + nt * 8 + 2 * t;
            *(float2*)(out + (size_t)rg * H_ + cg) =
                make_float2(acc[mt][nt][0], acc[mt][nt][1]);
            *(float2*)(out + (size_t)(rg + 8) * H_ + cg) =
                make_float2(acc[mt][nt][2], acc[mt][nt][3]);
        }
    }
}

// ---------------------------------------------------------------------------
// V transpose: g_Vs [s,H] -> g_Vth [b,h,d,s]
// ---------------------------------------------------------------------------
__global__ __launch_bounds__(256)
void vtrans() {
    __shared__ __half tile[64][72];
    const int tid = threadIdx.x;
    const int s0 = blockIdx.x * 64;
    const int h = blockIdx.y;
    const int b = blockIdx.z;
    const size_t bh = (size_t)b * NH_ + h;

    #pragma unroll
    for (int i = 0; i < 8; i++) {
        int idx = tid + i * 256;          // 2048 half2
        int r = idx >> 5, c2 = idx & 31;
        __half2 v = *(const __half2*)(g_Vs + (size_t)(b * S_ + s0 + r) * H_ + h * HD_ + c2 * 2);
        *(__half2*)&tile[r][c2 * 2] = v;
    }
    __syncthreads();
    #pragma unroll
    for (int i = 0; i < 8; i++) {
        int idx = tid + i * 256;
        int d = idx >> 5, s2 = idx & 31;
        __half2 v = __halves2half2(tile[s2 * 2][d], tile[s2 * 2 + 1][d]);
        *(__half2*)(g_Vth + (bh * HD_ + d) * S_ + s0 + s2 * 2) = v;
    }
}

// ---------------------------------------------------------------------------
// Flash attention, plain fp16 MMA (Q,K,P,V fp16; fp32 softmax+accum).
// CTA = 256 q-rows x one (b,h); 8 warps x two m16 tiles; kv-tile 64, 2 bufs.
// ---------------------------------------------------------------------------
#define FROWB 144
#define SQH   0
#define SKV0  36864              // 256*144
#define KVBUF 18432              // Kh + Vh, each 64*144=9216
#define OKH   0
#define OVH   9216
#define SMK   73728              // mask: 2 bufs x 64 x 4B
#define FSMEM 74240

__global__ __launch_bounds__(256, 1)
void flash_mma(const int* __restrict__ mask) {
    extern __shared__ char sm[];
    const float NEG = __int_as_float(0xff800000u);
    const int tid = threadIdx.x;
    const int wid = tid >> 5;
    const int lane = tid & 31;
    const int gid = lane >> 2;
    const int t = lane & 3;
    const int q0 = blockIdx.x * 256;
    const int h = blockIdx.y;
    const int b = blockIdx.z;
    const size_t bh = (size_t)b * NH_ + h;

    const __half* Qhp = g_Qah + (bh * S_ + q0) * HD_;
    const __half* Khp = g_Kah + bh * S_ * HD_;
    const __half* Vtp = g_Vth + bh * HD_ * S_;
    const int* mkp = mask + b * S_;

    const uint32_t sb = smem_u32(sm);

    // Load Q (256 x 64 halves)
    #pragma unroll
    for (int i = 0; i < 8; i++) {
        int idx = tid + i * 256;          // 2048 chunks
        int r = idx >> 3, c = idx & 7;
        cp16(sb + SQH + r * FROWB + c * 16, Qhp + (size_t)r * HD_ + c * 8);
    }
    cp_commit();

    auto load_kv = [&](int tile, int buf) {
        const int kv0 = tile * 64;
        const uint32_t kb = sb + SKV0 + buf * KVBUF;
        #pragma unroll
        for (int i = 0; i < 2; i++) {
            int idx = tid + i * 256;
            int r = idx >> 3, c = idx & 7;
            uint32_t so = r * FROWB + c * 16;
            cp16(kb + OKH + so, Khp + (size_t)(kv0 + r) * HD_ + c * 8);
            cp16(kb + OVH + so, Vtp + (size_t)r * S_ + kv0 + c * 8);
        }
        if (tid < 64) cp4(sb + SMK + buf * 256 + tid * 4, mkp + kv0 + tid);
        cp_commit();
    };

    load_kv(0, 0);

    float mr[2][2], lr[2][2];
    #pragma unroll
    for (int mi = 0; mi < 2; mi++) {
        mr[mi][0] = NEG; mr[mi][1] = NEG;
        lr[mi][0] = 0.f; lr[mi][1] = 0.f;
    }
    float ctx[2][8][4];
    #pragma unroll
    for (int mi = 0; mi < 2; mi++)
        #pragma unroll
        for (int nt = 0; nt < 8; nt++)
            #pragma unroll
            for (int e = 0; e < 4; e++) ctx[mi][nt][e] = 0.f;

    const int m0r = wid * 32;

    for (int tile = 0; tile < 32; tile++) {
        const int buf = tile & 1;
        if (tile + 1 < 32) {
            load_kv(tile + 1, buf ^ 1);
            asm volatile("cp.async.wait_group 1;" ::: "memory");
        } else {
            asm volatile("cp.async.wait_group 0;" ::: "memory");
        }
        __syncthreads();

        const char* kb = sm + SKV0 + buf * KVBUF;
        const int* mk = (const int*)(sm + SMK + buf * 256);

        // --- S = QK^T (fp16 single pass) ---
        float sc[2][8][4];
        #pragma unroll
        for (int mi = 0; mi < 2; mi++)
            #pragma unroll
            for (int nt = 0; nt < 8; nt++)
                #pragma unroll
                for (int e = 0; e < 4; e++) sc[mi][nt][e] = 0.f;

        #pragma unroll
        for (int ks = 0; ks < 4; ks++) {
            const int kcb = ks * 32 + 4 * t;
            uint32_t ah[2][4];
            #pragma unroll
            for (int mi = 0; mi < 2; mi++) {
                const int r0 = m0r + mi * 16;
                const char* qa = sm + SQH + (r0 + gid) * FROWB + kcb;
                const char* qb = sm + SQH + (r0 + gid + 8) * FROWB + kcb;
                ah[mi][0] = *(const uint32_t*)qa;
                ah[mi][1] = *(const uint32_t*)qb;
                ah[mi][2] = *(const uint32_t*)(qa + 16);
                ah[mi][3] = *(const uint32_t*)(qb + 16);
            }
            #pragma unroll
            for (int nt = 0; nt < 8; nt++) {
                const char* kr = kb + (nt * 8 + gid) * FROWB + kcb;
                uint32_t bhf[2] = { *(const uint32_t*)(kr + OKH),
                                    *(const uint32_t*)(kr + OKH + 16) };
                #pragma unroll
                for (int mi = 0; mi < 2; mi++)
                    mma16816(sc[mi][nt], ah[mi], bhf);
            }
        }

        // --- scale, clip, mask; online softmax (per m-tile) ---
        #pragma unroll
        for (int mi = 0; mi < 2; mi++) {
            float tm0 = NEG, tm1 = NEG;
            #pragma unroll
            for (int nt = 0; nt < 8; nt++) {
                int c0 = nt * 8 + 2 * t;
                int k0 = mk[c0], k1 = mk[c0 + 1];
                float v;
                v = fminf(fmaxf(sc[mi][nt][0] * 0.125f, -10000.f), 10000.f);
                sc[mi][nt][0] = k0 ? v : NEG;
                v = fminf(fmaxf(sc[mi][nt][1] * 0.125f, -10000.f), 10000.f);
                sc[mi][nt][1] = k1 ? v : NEG;
                v = fminf(fmaxf(sc[mi][nt][2] * 0.125f, -10000.f), 10000.f);
                sc[mi][nt][2] = k0 ? v : NEG;
                v = fminf(fmaxf(sc[mi][nt][3] * 0.125f, -10000.f), 10000.f);
                sc[mi][nt][3] = k1 ? v : NEG;
                tm0 = fmaxf(tm0, fmaxf(sc[mi][nt][0], sc[mi][nt][1]));
                tm1 = fmaxf(tm1, fmaxf(sc[mi][nt][2], sc[mi][nt][3]));
            }
            tm0 = fmaxf(tm0, __shfl_xor_sync(0xffffffffu, tm0, 1));
            tm0 = fmaxf(tm0, __shfl_xor_sync(0xffffffffu, tm0, 2));
            tm1 = fmaxf(tm1, __shfl_xor_sync(0xffffffffu, tm1, 1));
            tm1 = fmaxf(tm1, __shfl_xor_sync(0xffffffffu, tm1, 2));

            float mn0 = fmaxf(mr[mi][0], tm0), mn1 = fmaxf(mr[mi][1], tm1);
            float al0 = (mn0 == NEG) ? 1.f : __expf(mr[mi][0] - mn0);
            float al1 = (mn1 == NEG) ? 1.f : __expf(mr[mi][1] - mn1);

            float rs0 = 0.f, rs1 = 0.f;
            #pragma unroll
            for (int nt = 0; nt < 8; nt++) {
                float p;
                p = (sc[mi][nt][0] == NEG) ? 0.f : __expf(sc[mi][nt][0] - mn0);
                sc[mi][nt][0] = p; rs0 += p;
                p = (sc[mi][nt][1] == NEG) ? 0.f : __expf(sc[mi][nt][1] - mn0);
                sc[mi][nt][1] = p; rs0 += p;
                p = (sc[mi][nt][2] == NEG) ? 0.f : __expf(sc[mi][nt][2] - mn1);
                sc[mi][nt][2] = p; rs1 += p;
                p = (sc[mi][nt][3] == NEG) ? 0.f : __expf(sc[mi][nt][3] - mn1);
                sc[mi][nt][3] = p; rs1 += p;
            }
            rs0 += __shfl_xor_sync(0xffffffffu, rs0, 1);
            rs0 += __shfl_xor_sync(0xffffffffu, rs0, 2);
            rs1 += __shfl_xor_sync(0xffffffffu, rs1, 1);
            rs1 += __shfl_xor_sync(0xffffffffu, rs1, 2);
            lr[mi][0] = lr[mi][0] * al0 + rs0;
            lr[mi][1] = lr[mi][1] * al1 + rs1;
            mr[mi][0] = mn0; mr[mi][1] = mn1;

            #pragma unroll
            for (int nt = 0; nt < 8; nt++) {
                ctx[mi][nt][0] *= al0; ctx[mi][nt][1] *= al0;
                ctx[mi][nt][2] *= al1; ctx[mi][nt][3] *= al1;
            }
        }

        // --- ctx += P @ Vt (fp16 single pass) ---
        #pragma unroll
        for (int kk = 0; kk < 4; kk++) {
            uint32_t aph[2][4];
            #pragma unroll
            for (int mi = 0; mi < 2; mi++) {
                aph[mi][0] = pack_h2(sc[mi][2 * kk][0],     sc[mi][2 * kk][1]);
                aph[mi][1] = pack_h2(sc[mi][2 * kk][2],     sc[mi][2 * kk][3]);
                aph[mi][2] = pack_h2(sc[mi][2 * kk + 1][0], sc[mi][2 * kk + 1][1]);
                aph[mi][3] = pack_h2(sc[mi][2 * kk + 1][2], sc[mi][2 * kk + 1][3]);
            }
            const int kcb = kk * 32 + 4 * t;
            #pragma unroll
            for (int nt = 0; nt < 8; nt++) {
                const char* vr = kb + (nt * 8 + gid) * FROWB + kcb;
                uint32_t bvh[2] = { *(const uint32_t*)(vr + OVH),
                                    *(const uint32_t*)(vr + OVH + 16) };
                #pragma unroll
                for (int mi = 0; mi < 2; mi++)
                    mma16816(ctx[mi][nt], aph[mi], bvh);
            }
        }
        __syncthreads();
    }

    // Epilogue: normalize, split fp16, store to [s,H]
    #pragma unroll
    for (int mi = 0; mi < 2; mi++) {
        const float inv0 = 1.f / lr[mi][0];
        const float inv1 = 1.f / lr[mi][1];
        const int r0 = b * S_ + q0 + m0r + mi * 16 + gid;
        #pragma unroll
        for (int nt = 0; nt < 8; nt++) {
            const int d0 = h * HD_ + nt * 8 + 2 * t;
            uint32_t hi, lo;
            pack_split_h(ctx[mi][nt][0] * inv0, ctx[mi][nt][1] * inv0, hi, lo);
            *(uint32_t*)(g_Ch + (size_t)r0 * H_ + d0) = hi;
            *(uint32_t*)(g_Cl + (size_t)r0 * H_ + d0) = lo;
            pack_split_h(ctx[mi][nt][2] * inv1, ctx[mi][nt][3] * inv1, hi, lo);
            *(uint32_t*)(g_Ch + (size_t)(r0 + 8) * H_ + d0) = hi;
            *(uint32_t*)(g_Cl + (size_t)(r0 + 8) * H_ + d0) = lo;
        }
    }
}

// ---------------------------------------------------------------------------
// X split: fp32 -> (fp16 hi, fp16 lo)
// ---------------------------------------------------------------------------
__global__ void xsplit(const float* __restrict__ A, int n4) {
    int i = blockIdx.x * blockDim.x + threadIdx.x;
    if (i >= n4) return;
    float4 v = ((const float4*)A)[i];
    uint32_t h0, l0, h1, l1;
    pack_split_h(v.x, v.y, h0, l0);
    pack_split_h(v.z, v.w, h1, l1);
    ((uint32_t*)g_Xh)[2 * i + 0] = h0;
    ((uint32_t*)g_Xh)[2 * i + 1] = h1;
    ((uint32_t*)g_Xl)[2 * i + 0] = l0;
    ((uint32_t*)g_Xl)[2 * i + 1] = l1;
}

// ---------------------------------------------------------------------------
// Weight convert+transpose: W[K,N] fp32 -> WhT[z][N,K] fp16
// ---------------------------------------------------------------------------
__global__ void wcvt_t(const float* __restrict__ W0, const float* __restrict__ W1,
                       const float* __restrict__ W2, const float* __restrict__ W3) {
    __shared__ float tbuf[32][33];
    const int z = blockIdx.z;
    const float* W = (z == 0) ? W0 : (z == 1) ? W1 : (z == 2) ? W2 : W3;
    __half* O = g_WhT[z];
    int n0 = blockIdx.x * 32, k0 = blockIdx.y * 32;
    int x = threadIdx.x, y0 = threadIdx.y;
    #pragma unroll
    for (int i = y0; i < 32; i += 8)
        tbuf[i][x] = W[(size_t)(k0 + i) * H_ + n0 + x];
    __syncthreads();
    #pragma unroll
    for (int i = y0; i < 32; i += 8)
        O[(size_t)(n0 + i) * H_ + k0 + x] = __float2half_rn(tbuf[x][i]);
}

// ---------------------------------------------------------------------------
// Launch
// ---------------------------------------------------------------------------
extern "C" void kernel_launch(void* const* d_in, const int* in_sizes, int n_in,
                              void* d_out, int out_size) {
    const float* X    = (const float*)d_in[0];
    const int*   mask = (const int*)d_in[1];
    const float* WQ   = (const float*)d_in[2];
    const float* WK   = (const float*)d_in[3];
    const float* WV   = (const float*)d_in[4];
    const float* WO   = (const float*)d_in[5];
    float* out = (float*)d_out;

    cudaFuncSetAttribute(gemm_qkv, cudaFuncAttributeMaxDynamicSharedMemorySize, GSMEM);
    cudaFuncSetAttribute(gemm_o,   cudaFuncAttributeMaxDynamicSharedMemorySize, GSMEM);
    cudaFuncSetAttribute(flash_mma, cudaFuncAttributeMaxDynamicSharedMemorySize, FSMEM);

    // One shim so ncu's capture window (empirically the 4th launch) hits gemm_qkv
    nopk<<<1, 32>>>();

    // Prep
    xsplit<<<(M_ * H_ / 4 + 255) / 256, 256>>>(X, M_ * H_ / 4);
    wcvt_t<<<dim3(32, 32, 4), dim3(32, 8)>>>(WQ, WK, WV, WO);

    // QKV projections fused (z selects weight/output); 2 CTAs/SM
    gemm_qkv<<<dim3(H_ / TN, M_ / TM, 3), 256, GSMEM>>>();

    // V transpose
    vtrans<<<dim3(S_ / 64, NH_, B_), 256>>>();

    // Attention (plain fp16 MMA)
    flash_mma<<<dim3(S_ / 256, NH_, B_), 256, FSMEM>>>(mask);

    // Output projection
    gemm_o<<<dim3(H_ / TN, M_ / TM), 256, GSMEM>>>(out);
}

// round 9
// speedup vs baseline: 2.1689x; 1.2733x over previous
#include <cuda_runtime.h>
#include <cuda_fp16.h>
#include <cstdint>

// Problem constants
#define B_  2
#define S_  2048
#define H_  1024
#define NH_ 16
#define HD_ 64
#define M_  (B_*S_)   // 4096 rows

// ---------------------------------------------------------------------------
// Scratch (allocation-free: device globals)
// ---------------------------------------------------------------------------
__device__ __half g_Xh[(size_t)M_ * H_];
__device__ __half g_WhT[4][(size_t)H_ * H_];     // transposed [N,K] fp16
__device__ __half g_Qah[(size_t)M_ * H_];        // [b,h,s,d] fp16
__device__ __half g_Kah[(size_t)M_ * H_];        // [b,h,s,d] fp16
__device__ __half g_Vth[(size_t)M_ * H_];        // [b,h,d,s] fp16
__device__ __half g_Ch [(size_t)M_ * H_];        // context [s,H] fp16

// ---------------------------------------------------------------------------
// Helpers
// ---------------------------------------------------------------------------
__device__ __forceinline__ uint32_t smem_u32(const void* p) {
    uint32_t a;
    asm("{ .reg .u64 t; cvta.to.shared.u64 t, %1; cvt.u32.u64 %0, t; }"
        : "=r"(a) : "l"(p));
    return a;
}
__device__ __forceinline__ void cp16(uint32_t s, const void* g) {
    asm volatile("cp.async.cg.shared.global [%0], [%1], 16;" :: "r"(s), "l"(g));
}
__device__ __forceinline__ void cp4(uint32_t s, const void* g) {
    asm volatile("cp.async.ca.shared.global [%0], [%1], 4;" :: "r"(s), "l"(g));
}
__device__ __forceinline__ void cp_commit() {
    asm volatile("cp.async.commit_group;" ::: "memory");
}
__device__ __forceinline__ void mma16816(float* c, const uint32_t* a, const uint32_t* b) {
    asm volatile(
        "mma.sync.aligned.m16n8k16.row.col.f32.f16.f16.f32 "
        "{%0,%1,%2,%3}, {%4,%5,%6,%7}, {%8,%9}, {%0,%1,%2,%3};"
        : "+f"(c[0]), "+f"(c[1]), "+f"(c[2]), "+f"(c[3])
        : "r"(a[0]), "r"(a[1]), "r"(a[2]), "r"(a[3]), "r"(b[0]), "r"(b[1]));
}
__device__ __forceinline__ uint32_t pack_h2(float f0, float f1) {
    __half2 hh = __halves2half2(__float2half_rn(f0), __float2half_rn(f1));
    return *(uint32_t*)&hh;
}

// ---------------------------------------------------------------------------
// GEMM core: plain fp16.  acc = A@B^T   (B stored [N,K])
// CTA tile 128x128, K-chunk 32, 3-stage cp.async, 8 warps (2x4), warp 64x32.
// ---------------------------------------------------------------------------
#define TM 128
#define TN 128
#define TK 32
#define PITCH 40                 // halves per smem row (80 B)
#define OAH 0
#define OBH 10240                // 128*80
#define STG 20480
#define NSTAGE 3
#define GSMEM (STG * NSTAGE)     // 61440 -> 2 CTAs/SM
#define NCH (H_ / TK)            // 32

__device__ __forceinline__ void gemm_core(
    const __half* __restrict__ Ah, const __half* __restrict__ Bh,
    int row0, int col0, char* gsm, float acc[4][4][4]) {

    const int tid = threadIdx.x;
    const int wid = tid >> 5;
    const int lane = tid & 31;
    const int gid = lane >> 2;
    const int t = lane & 3;
    const int wm = wid & 1;
    const int wn = wid >> 1;
    const uint32_t sb = smem_u32(gsm);

    auto load_chunk = [&](int c, int s) {
        const int k0 = c * TK;
        const uint32_t base = sb + s * STG;
        #pragma unroll
        for (int i = 0; i < 2; i++) {               // A: 512 chunks
            int idx = tid + i * 256;
            int r = idx >> 2, c16 = idx & 3;
            uint32_t so = r * 80 + c16 * 16;
            cp16(base + OAH + so, Ah + (size_t)(row0 + r) * H_ + k0 + c16 * 8);
        }
        #pragma unroll
        for (int i = 0; i < 2; i++) {               // B: 512 chunks
            int idx = tid + i * 256;
            int r = idx >> 2, c16 = idx & 3;
            uint32_t so = r * 80 + c16 * 16;
            cp16(base + OBH + so, Bh + (size_t)(col0 + r) * H_ + k0 + c16 * 8);
        }
        cp_commit();
    };

    load_chunk(0, 0);
    load_chunk(1, 1);

    for (int c = 0; c < NCH; c++) {
        const int s = c % NSTAGE;
        if (c + 2 < NCH) load_chunk(c + 2, (c + 2) % NSTAGE);
        else cp_commit();                           // keep group count uniform
        asm volatile("cp.async.wait_group 2;" ::: "memory");
        __syncthreads();

        const char* bs = gsm + s * STG;
        const __half* Ahp = (const __half*)(bs + OAH);
        const __half* Bhp = (const __half*)(bs + OBH);

        #pragma unroll
        for (int ks = 0; ks < 2; ks++) {
            const int kc = ks * 16 + 2 * t;
            uint32_t ah[4][4], bh[4][2];
            #pragma unroll
            for (int mt = 0; mt < 4; mt++) {
                const int r0 = wm * 64 + mt * 16 + gid;
                ah[mt][0] = *(const uint32_t*)(Ahp + r0 * PITCH + kc);
                ah[mt][1] = *(const uint32_t*)(Ahp + (r0 + 8) * PITCH + kc);
                ah[mt][2] = *(const uint32_t*)(Ahp + r0 * PITCH + kc + 8);
                ah[mt][3] = *(const uint32_t*)(Ahp + (r0 + 8) * PITCH + kc + 8);
            }
            #pragma unroll
            for (int nt = 0; nt < 4; nt++) {
                const int n0 = wn * 32 + nt * 8 + gid;
                bh[nt][0] = *(const uint32_t*)(Bhp + n0 * PITCH + kc);
                bh[nt][1] = *(const uint32_t*)(Bhp + n0 * PITCH + kc + 8);
            }
            #pragma unroll
            for (int mt = 0; mt < 4; mt++)
                #pragma unroll
                for (int nt = 0; nt < 4; nt++)
                    mma16816(acc[mt][nt], ah[mt], bh[nt]);
        }
        __syncthreads();
    }
}

// ---------------------------------------------------------------------------
// QKV projection GEMM: grid.z selects Q/K/V. Q,K -> [b,h,s,d]; V -> fused
// transpose to [b,h,d,s] via smem bounce.
// ---------------------------------------------------------------------------
__global__ __launch_bounds__(256, 2)
void gemm_qkv() {
    extern __shared__ char gsm[];
    const int mode = blockIdx.z;
    const int row0 = blockIdx.y * TM;
    const int col0 = blockIdx.x * TN;

    float acc[4][4][4];
    #pragma unroll
    for (int i = 0; i < 4; i++)
        #pragma unroll
        for (int j = 0; j < 4; j++)
            #pragma unroll
            for (int q = 0; q < 4; q++) acc[i][j][q] = 0.f;

    gemm_core(g_Xh, g_WhT[mode], row0, col0, gsm, acc);

    const int tid = threadIdx.x;
    const int wid = tid >> 5;
    const int lane = tid & 31;
    const int gid = lane >> 2;
    const int t = lane & 3;
    const int wm = wid & 1;
    const int wn = wid >> 1;

    if (mode == 2) {
        // V: transpose in smem, store [b,h,d,s] coalesced along s.
        __half* tile = (__half*)gsm;     // [128 cols][136] halves = 34816 B
        #pragma unroll
        for (int mt = 0; mt < 4; mt++)
            #pragma unroll
            for (int rr = 0; rr < 2; rr++) {
                const int rl = wm * 64 + mt * 16 + gid + rr * 8;
                #pragma unroll
                for (int nt = 0; nt < 4; nt++) {
                    const int cl = wn * 32 + nt * 8 + 2 * t;
                    tile[cl * 136 + rl]       = __float2half_rn(acc[mt][nt][rr * 2 + 0]);
                    tile[(cl + 1) * 136 + rl] = __float2half_rn(acc[mt][nt][rr * 2 + 1]);
                }
            }
        __syncthreads();
        const int bb = row0 >> 11;
        const int s0 = row0 & 2047;
        #pragma unroll
        for (int i = 0; i < 8; i++) {
            int idx = tid + i * 256;      // 2048 16B chunks
            int r = idx >> 4, c8 = idx & 15;
            int hh = (col0 >> 6) + (r >> 6);
            int dd = r & 63;
            float4 v = *(const float4*)&tile[r * 136 + c8 * 8];
            *(float4*)(g_Vth + (((size_t)bb * NH_ + hh) * HD_ + dd) * S_ + s0 + c8 * 8) = v;
        }
    } else {
        __half* dst = (mode == 0) ? g_Qah : g_Kah;
        #pragma unroll
        for (int mt = 0; mt < 4; mt++)
            #pragma unroll
            for (int rr = 0; rr < 2; rr++) {
                const int rg = row0 + wm * 64 + mt * 16 + gid + rr * 8;
                const int bb = rg >> 11;
                const int ss = rg & 2047;
                #pragma unroll
                for (int nt = 0; nt < 4; nt++) {
                    const int cg = col0 + wn * 32 + nt * 8 + 2 * t;
                    const int hh = cg >> 6, dd = cg & 63;
                    const size_t go = (((size_t)bb * NH_ + hh) * S_ + ss) * HD_ + dd;
                    *(uint32_t*)(dst + go) =
                        pack_h2(acc[mt][nt][rr * 2 + 0], acc[mt][nt][rr * 2 + 1]);
                }
            }
    }
}

// ---------------------------------------------------------------------------
// Output projection GEMM: out(fp32) = ctx(fp16) @ WO
// ---------------------------------------------------------------------------
__global__ __launch_bounds__(256, 2)
void gemm_o(float* __restrict__ out) {
    extern __shared__ char gsm[];
    const int row0 = blockIdx.y * TM;
    const int col0 = blockIdx.x * TN;

    float acc[4][4][4];
    #pragma unroll
    for (int i = 0; i < 4; i++)
        #pragma unroll
        for (int j = 0; j < 4; j++)
            #pragma unroll
            for (int q = 0; q < 4; q++) acc[i][j][q] = 0.f;

    gemm_core(g_Ch, g_WhT[3], row0, col0, gsm, acc);

    const int tid = threadIdx.x;
    const int wid = tid >> 5;
    const int lane = tid & 31;
    const int gid = lane >> 2;
    const int t = lane & 3;
    const int wm = wid & 1;
    const int wn = wid >> 1;

    #pragma unroll
    for (int mt = 0; mt < 4; mt++) {
        const int rg = row0 + wm * 64 + mt * 16 + gid;
        #pragma unroll
        for (int nt = 0; nt < 4; nt++) {
            const int cg = col0 + wn * 32 + nt * 8 + 2 * t;
            *(float2*)(out + (size_t)rg * H_ + cg) =
                make_float2(acc[mt][nt][0], acc[mt][nt][1]);
            *(float2*)(out + (size_t)(rg + 8) * H_ + cg) =
                make_float2(acc[mt][nt][2], acc[mt][nt][3]);
        }
    }
}

// ---------------------------------------------------------------------------
// Flash attention, plain fp16 MMA (verified round 8); epilogue fp16-only ctx.
// ---------------------------------------------------------------------------
#define FROWB 144
#define SQH   0
#define SKV0  36864              // 256*144
#define KVBUF 18432              // Kh + Vh, each 64*144=9216
#define OKH   0
#define OVH   9216
#define SMK   73728              // mask: 2 bufs x 64 x 4B
#define FSMEM 74240

__global__ __launch_bounds__(256, 1)
void flash_mma(const int* __restrict__ mask) {
    extern __shared__ char sm[];
    const float NEG = __int_as_float(0xff800000u);
    const int tid = threadIdx.x;
    const int wid = tid >> 5;
    const int lane = tid & 31;
    const int gid = lane >> 2;
    const int t = lane & 3;
    const int q0 = blockIdx.x * 256;
    const int h = blockIdx.y;
    const int b = blockIdx.z;
    const size_t bh = (size_t)b * NH_ + h;

    const __half* Qhp = g_Qah + (bh * S_ + q0) * HD_;
    const __half* Khp = g_Kah + bh * S_ * HD_;
    const __half* Vtp = g_Vth + bh * HD_ * S_;
    const int* mkp = mask + b * S_;

    const uint32_t sb = smem_u32(sm);

    #pragma unroll
    for (int i = 0; i < 8; i++) {
        int idx = tid + i * 256;
        int r = idx >> 3, c = idx & 7;
        cp16(sb + SQH + r * FROWB + c * 16, Qhp + (size_t)r * HD_ + c * 8);
    }
    cp_commit();

    auto load_kv = [&](int tile, int buf) {
        const int kv0 = tile * 64;
        const uint32_t kb = sb + SKV0 + buf * KVBUF;
        #pragma unroll
        for (int i = 0; i < 2; i++) {
            int idx = tid + i * 256;
            int r = idx >> 3, c = idx & 7;
            uint32_t so = r * FROWB + c * 16;
            cp16(kb + OKH + so, Khp + (size_t)(kv0 + r) * HD_ + c * 8);
            cp16(kb + OVH + so, Vtp + (size_t)r * S_ + kv0 + c * 8);
        }
        if (tid < 64) cp4(sb + SMK + buf * 256 + tid * 4, mkp + kv0 + tid);
        cp_commit();
    };

    load_kv(0, 0);

    float mr[2][2], lr[2][2];
    #pragma unroll
    for (int mi = 0; mi < 2; mi++) {
        mr[mi][0] = NEG; mr[mi][1] = NEG;
        lr[mi][0] = 0.f; lr[mi][1] = 0.f;
    }
    float ctx[2][8][4];
    #pragma unroll
    for (int mi = 0; mi < 2; mi++)
        #pragma unroll
        for (int nt = 0; nt < 8; nt++)
            #pragma unroll
            for (int e = 0; e < 4; e++) ctx[mi][nt][e] = 0.f;

    const int m0r = wid * 32;

    for (int tile = 0; tile < 32; tile++) {
        const int buf = tile & 1;
        if (tile + 1 < 32) {
            load_kv(tile + 1, buf ^ 1);
            asm volatile("cp.async.wait_group 1;" ::: "memory");
        } else {
            asm volatile("cp.async.wait_group 0;" ::: "memory");
        }
        __syncthreads();

        const char* kb = sm + SKV0 + buf * KVBUF;
        const int* mk = (const int*)(sm + SMK + buf * 256);

        float sc[2][8][4];
        #pragma unroll
        for (int mi = 0; mi < 2; mi++)
            #pragma unroll
            for (int nt = 0; nt < 8; nt++)
                #pragma unroll
                for (int e = 0; e < 4; e++) sc[mi][nt][e] = 0.f;

        #pragma unroll
        for (int ks = 0; ks < 4; ks++) {
            const int kcb = ks * 32 + 4 * t;
            uint32_t ah[2][4];
            #pragma unroll
            for (int mi = 0; mi < 2; mi++) {
                const int r0 = m0r + mi * 16;
                const char* qa = sm + SQH + (r0 + gid) * FROWB + kcb;
                const char* qb = sm + SQH + (r0 + gid + 8) * FROWB + kcb;
                ah[mi][0] = *(const uint32_t*)qa;
                ah[mi][1] = *(const uint32_t*)qb;
                ah[mi][2] = *(const uint32_t*)(qa + 16);
                ah[mi][3] = *(const uint32_t*)(qb + 16);
            }
            #pragma unroll
            for (int nt = 0; nt < 8; nt++) {
                const char* kr = kb + (nt * 8 + gid) * FROWB + kcb;
                uint32_t bhf[2] = { *(const uint32_t*)(kr + OKH),
                                    *(const uint32_t*)(kr + OKH + 16) };
                #pragma unroll
                for (int mi = 0; mi < 2; mi++)
                    mma16816(sc[mi][nt], ah[mi], bhf);
            }
        }

        #pragma unroll
        for (int mi = 0; mi < 2; mi++) {
            float tm0 = NEG, tm1 = NEG;
            #pragma unroll
            for (int nt = 0; nt < 8; nt++) {
                int c0 = nt * 8 + 2 * t;
                int k0 = mk[c0], k1 = mk[c0 + 1];
                float v;
                v = fminf(fmaxf(sc[mi][nt][0] * 0.125f, -10000.f), 10000.f);
                sc[mi][nt][0] = k0 ? v : NEG;
                v = fminf(fmaxf(sc[mi][nt][1] * 0.125f, -10000.f), 10000.f);
                sc[mi][nt][1] = k1 ? v : NEG;
                v = fminf(fmaxf(sc[mi][nt][2] * 0.125f, -10000.f), 10000.f);
                sc[mi][nt][2] = k0 ? v : NEG;
                v = fminf(fmaxf(sc[mi][nt][3] * 0.125f, -10000.f), 10000.f);
                sc[mi][nt][3] = k1 ? v : NEG;
                tm0 = fmaxf(tm0, fmaxf(sc[mi][nt][0], sc[mi][nt][1]));
                tm1 = fmaxf(tm1, fmaxf(sc[mi][nt][2], sc[mi][nt][3]));
            }
            tm0 = fmaxf(tm0, __shfl_xor_sync(0xffffffffu, tm0, 1));
            tm0 = fmaxf(tm0, __shfl_xor_sync(0xffffffffu, tm0, 2));
            tm1 = fmaxf(tm1, __shfl_xor_sync(0xffffffffu, tm1, 1));
            tm1 = fmaxf(tm1, __shfl_xor_sync(0xffffffffu, tm1, 2));

            float mn0 = fmaxf(mr[mi][0], tm0), mn1 = fmaxf(mr[mi][1], tm1);
            float al0 = (mn0 == NEG) ? 1.f : __expf(mr[mi][0] - mn0);
            float al1 = (mn1 == NEG) ? 1.f : __expf(mr[mi][1] - mn1);

            float rs0 = 0.f, rs1 = 0.f;
            #pragma unroll
            for (int nt = 0; nt < 8; nt++) {
                float p;
                p = (sc[mi][nt][0] == NEG) ? 0.f : __expf(sc[mi][nt][0] - mn0);
                sc[mi][nt][0] = p; rs0 += p;
                p = (sc[mi][nt][1] == NEG) ? 0.f : __expf(sc[mi][nt][1] - mn0);
                sc[mi][nt][1] = p; rs0 += p;
                p = (sc[mi][nt][2] == NEG) ? 0.f : __expf(sc[mi][nt][2] - mn1);
                sc[mi][nt][2] = p; rs1 += p;
                p = (sc[mi][nt][3] == NEG) ? 0.f : __expf(sc[mi][nt][3] - mn1);
                sc[mi][nt][3] = p; rs1 += p;
            }
            rs0 += __shfl_xor_sync(0xffffffffu, rs0, 1);
            rs0 += __shfl_xor_sync(0xffffffffu, rs0, 2);
            rs1 += __shfl_xor_sync(0xffffffffu, rs1, 1);
            rs1 += __shfl_xor_sync(0xffffffffu, rs1, 2);
            lr[mi][0] = lr[mi][0] * al0 + rs0;
            lr[mi][1] = lr[mi][1] * al1 + rs1;
            mr[mi][0] = mn0; mr[mi][1] = mn1;

            #pragma unroll
            for (int nt = 0; nt < 8; nt++) {
                ctx[mi][nt][0] *= al0; ctx[mi][nt][1] *= al0;
                ctx[mi][nt][2] *= al1; ctx[mi][nt][3] *= al1;
            }
        }

        #pragma unroll
        for (int kk = 0; kk < 4; kk++) {
            uint32_t aph[2][4];
            #pragma unroll
            for (int mi = 0; mi < 2; mi++) {
                aph[mi][0] = pack_h2(sc[mi][2 * kk][0],     sc[mi][2 * kk][1]);
                aph[mi][1] = pack_h2(sc[mi][2 * kk][2],     sc[mi][2 * kk][3]);
                aph[mi][2] = pack_h2(sc[mi][2 * kk + 1][0], sc[mi][2 * kk + 1][1]);
                aph[mi][3] = pack_h2(sc[mi][2 * kk + 1][2], sc[mi][2 * kk + 1][3]);
            }
            const int kcb = kk * 32 + 4 * t;
            #pragma unroll
            for (int nt = 0; nt < 8; nt++) {
                const char* vr = kb + (nt * 8 + gid) * FROWB + kcb;
                uint32_t bvh[2] = { *(const uint32_t*)(vr + OVH),
                                    *(const uint32_t*)(vr + OVH + 16) };
                #pragma unroll
                for (int mi = 0; mi < 2; mi++)
                    mma16816(ctx[mi][nt], aph[mi], bvh);
            }
        }
        __syncthreads();
    }

    // Epilogue: normalize, fp16, store [s,H]
    #pragma unroll
    for (int mi = 0; mi < 2; mi++) {
        const float inv0 = 1.f / lr[mi][0];
        const float inv1 = 1.f / lr[mi][1];
        const int r0 = b * S_ + q0 + m0r + mi * 16 + gid;
        #pragma unroll
        for (int nt = 0; nt < 8; nt++) {
            const int d0 = h * HD_ + nt * 8 + 2 * t;
            *(uint32_t*)(g_Ch + (size_t)r0 * H_ + d0) =
                pack_h2(ctx[mi][nt][0] * inv0, ctx[mi][nt][1] * inv0);
            *(uint32_t*)(g_Ch + (size_t)(r0 + 8) * H_ + d0) =
                pack_h2(ctx[mi][nt][2] * inv1, ctx[mi][nt][3] * inv1);
        }
    }
}

// ---------------------------------------------------------------------------
// X convert: fp32 -> fp16
// ---------------------------------------------------------------------------
__global__ void xcvt(const float* __restrict__ A, int n4) {
    int i = blockIdx.x * blockDim.x + threadIdx.x;
    if (i >= n4) return;
    float4 v = ((const float4*)A)[i];
    ((uint32_t*)g_Xh)[2 * i + 0] = pack_h2(v.x, v.y);
    ((uint32_t*)g_Xh)[2 * i + 1] = pack_h2(v.z, v.w);
}

// ---------------------------------------------------------------------------
// Weight convert+transpose: W[K,N] fp32 -> WhT[z][N,K] fp16
// ---------------------------------------------------------------------------
__global__ void wcvt_t(const float* __restrict__ W0, const float* __restrict__ W1,
                       const float* __restrict__ W2, const float* __restrict__ W3) {
    __shared__ float tbuf[32][33];
    const int z = blockIdx.z;
    const float* W = (z == 0) ? W0 : (z == 1) ? W1 : (z == 2) ? W2 : W3;
    __half* O = g_WhT[z];
    int n0 = blockIdx.x * 32, k0 = blockIdx.y * 32;
    int x = threadIdx.x, y0 = threadIdx.y;
    #pragma unroll
    for (int i = y0; i < 32; i += 8)
        tbuf[i][x] = W[(size_t)(k0 + i) * H_ + n0 + x];
    __syncthreads();
    #pragma unroll
    for (int i = y0; i < 32; i += 8)
        O[(size_t)(n0 + i) * H_ + k0 + x] = __float2half_rn(tbuf[x][i]);
}

// ---------------------------------------------------------------------------
// Launch (flash_mma is launch #4 -> lands in ncu capture window)
// ---------------------------------------------------------------------------
extern "C" void kernel_launch(void* const* d_in, const int* in_sizes, int n_in,
                              void* d_out, int out_size) {
    const float* X    = (const float*)d_in[0];
    const int*   mask = (const int*)d_in[1];
    const float* WQ   = (const float*)d_in[2];
    const float* WK   = (const float*)d_in[3];
    const float* WV   = (const float*)d_in[4];
    const float* WO   = (const float*)d_in[5];
    float* out = (float*)d_out;

    cudaFuncSetAttribute(gemm_qkv, cudaFuncAttributeMaxDynamicSharedMemorySize, GSMEM);
    cudaFuncSetAttribute(gemm_o,   cudaFuncAttributeMaxDynamicSharedMemorySize, GSMEM);
    cudaFuncSetAttribute(flash_mma, cudaFuncAttributeMaxDynamicSharedMemorySize, FSMEM);

    // 1. Prep
    xcvt<<<(M_ * H_ / 4 + 255) / 256, 256>>>(X, M_ * H_ / 4);
    // 2.
    wcvt_t<<<dim3(32, 32, 4), dim3(32, 8)>>>(WQ, WK, WV, WO);
    // 3. QKV projections (fused; V-transpose in epilogue)
    gemm_qkv<<<dim3(H_ / TN, M_ / TM, 3), 256, GSMEM>>>();
    // 4. Attention
    flash_mma<<<dim3(S_ / 256, NH_, B_), 256, FSMEM>>>(mask);
    // 5. Output projection
    gemm_o<<<dim3(H_ / TN, M_ / TM), 256, GSMEM>>>(out);
}

// round 10
// speedup vs baseline: 2.2409x; 1.0332x over previous
#include <cuda_runtime.h>
#include <cuda_fp16.h>
#include <cstdint>

// Problem constants
#define B_  2
#define S_  2048
#define H_  1024
#define NH_ 16
#define HD_ 64
#define M_  (B_*S_)   // 4096 rows

// ---------------------------------------------------------------------------
// Scratch (allocation-free: device globals)
// ---------------------------------------------------------------------------
__device__ __half g_Xh[(size_t)M_ * H_];
__device__ __half g_WhT[4][(size_t)H_ * H_];     // transposed [N,K] fp16
__device__ __half g_Qah[(size_t)M_ * H_];        // [b,h,s,d] fp16
__device__ __half g_Kah[(size_t)M_ * H_];        // [b,h,s,d] fp16
__device__ __half g_Vth[(size_t)M_ * H_];        // [b,h,d,s] fp16
__device__ __half g_Ch [(size_t)M_ * H_];        // context [s,H] fp16

// ---------------------------------------------------------------------------
// Helpers
// ---------------------------------------------------------------------------
__device__ __forceinline__ uint32_t smem_u32(const void* p) {
    uint32_t a;
    asm("{ .reg .u64 t; cvta.to.shared.u64 t, %1; cvt.u32.u64 %0, t; }"
        : "=r"(a) : "l"(p));
    return a;
}
__device__ __forceinline__ void cp16(uint32_t s, const void* g) {
    asm volatile("cp.async.cg.shared.global [%0], [%1], 16;" :: "r"(s), "l"(g));
}
__device__ __forceinline__ void cp4(uint32_t s, const void* g) {
    asm volatile("cp.async.ca.shared.global [%0], [%1], 4;" :: "r"(s), "l"(g));
}
__device__ __forceinline__ void cp_commit() {
    asm volatile("cp.async.commit_group;" ::: "memory");
}
__device__ __forceinline__ void mma16816(float* c, const uint32_t* a, const uint32_t* b) {
    asm volatile(
        "mma.sync.aligned.m16n8k16.row.col.f32.f16.f16.f32 "
        "{%0,%1,%2,%3}, {%4,%5,%6,%7}, {%8,%9}, {%0,%1,%2,%3};"
        : "+f"(c[0]), "+f"(c[1]), "+f"(c[2]), "+f"(c[3])
        : "r"(a[0]), "r"(a[1]), "r"(a[2]), "r"(a[3]), "r"(b[0]), "r"(b[1]));
}
__device__ __forceinline__ uint32_t pack_h2(float f0, float f1) {
    __half2 hh = __halves2half2(__float2half_rn(f0), __float2half_rn(f1));
    return *(uint32_t*)&hh;
}

// ---------------------------------------------------------------------------
// GEMM core: plain fp16.  acc = A@B^T   (B stored [N,K])   [verified round 9]
// CTA tile 128x128, K-chunk 32, 3-stage cp.async, 8 warps (2x4), warp 64x32.
// ---------------------------------------------------------------------------
#define TM 128
#define TN 128
#define TK 32
#define PITCH 40                 // halves per smem row (80 B)
#define OAH 0
#define OBH 10240                // 128*80
#define STG 20480
#define NSTAGE 3
#define GSMEM (STG * NSTAGE)     // 61440 -> 2 CTAs/SM
#define NCH (H_ / TK)            // 32

__device__ __forceinline__ void gemm_core(
    const __half* __restrict__ Ah, const __half* __restrict__ Bh,
    int row0, int col0, char* gsm, float acc[4][4][4]) {

    const int tid = threadIdx.x;
    const int wid = tid >> 5;
    const int lane = tid & 31;
    const int gid = lane >> 2;
    const int t = lane & 3;
    const int wm = wid & 1;
    const int wn = wid >> 1;
    const uint32_t sb = smem_u32(gsm);

    auto load_chunk = [&](int c, int s) {
        const int k0 = c * TK;
        const uint32_t base = sb + s * STG;
        #pragma unroll
        for (int i = 0; i < 2; i++) {               // A: 512 chunks
            int idx = tid + i * 256;
            int r = idx >> 2, c16 = idx & 3;
            uint32_t so = r * 80 + c16 * 16;
            cp16(base + OAH + so, Ah + (size_t)(row0 + r) * H_ + k0 + c16 * 8);
        }
        #pragma unroll
        for (int i = 0; i < 2; i++) {               // B: 512 chunks
            int idx = tid + i * 256;
            int r = idx >> 2, c16 = idx & 3;
            uint32_t so = r * 80 + c16 * 16;
            cp16(base + OBH + so, Bh + (size_t)(col0 + r) * H_ + k0 + c16 * 8);
        }
        cp_commit();
    };

    load_chunk(0, 0);
    load_chunk(1, 1);

    for (int c = 0; c < NCH; c++) {
        const int s = c % NSTAGE;
        if (c + 2 < NCH) load_chunk(c + 2, (c + 2) % NSTAGE);
        else cp_commit();                           // keep group count uniform
        asm volatile("cp.async.wait_group 2;" ::: "memory");
        __syncthreads();

        const char* bs = gsm + s * STG;
        const __half* Ahp = (const __half*)(bs + OAH);
        const __half* Bhp = (const __half*)(bs + OBH);

        #pragma unroll
        for (int ks = 0; ks < 2; ks++) {
            const int kc = ks * 16 + 2 * t;
            uint32_t ah[4][4], bh[4][2];
            #pragma unroll
            for (int mt = 0; mt < 4; mt++) {
                const int r0 = wm * 64 + mt * 16 + gid;
                ah[mt][0] = *(const uint32_t*)(Ahp + r0 * PITCH + kc);
                ah[mt][1] = *(const uint32_t*)(Ahp + (r0 + 8) * PITCH + kc);
                ah[mt][2] = *(const uint32_t*)(Ahp + r0 * PITCH + kc + 8);
                ah[mt][3] = *(const uint32_t*)(Ahp + (r0 + 8) * PITCH + kc + 8);
            }
            #pragma unroll
            for (int nt = 0; nt < 4; nt++) {
                const int n0 = wn * 32 + nt * 8 + gid;
                bh[nt][0] = *(const uint32_t*)(Bhp + n0 * PITCH + kc);
                bh[nt][1] = *(const uint32_t*)(Bhp + n0 * PITCH + kc + 8);
            }
            #pragma unroll
            for (int mt = 0; mt < 4; mt++)
                #pragma unroll
                for (int nt = 0; nt < 4; nt++)
                    mma16816(acc[mt][nt], ah[mt], bh[nt]);
        }
        __syncthreads();
    }
}

// ---------------------------------------------------------------------------
// QKV projection GEMM: grid.z selects Q/K/V. Q,K -> [b,h,s,d]; V -> fused
// transpose to [b,h,d,s] via smem bounce.   [verified round 9]
// ---------------------------------------------------------------------------
__global__ __launch_bounds__(256, 2)
void gemm_qkv() {
    extern __shared__ char gsm[];
    const int mode = blockIdx.z;
    const int row0 = blockIdx.y * TM;
    const int col0 = blockIdx.x * TN;

    float acc[4][4][4];
    #pragma unroll
    for (int i = 0; i < 4; i++)
        #pragma unroll
        for (int j = 0; j < 4; j++)
            #pragma unroll
            for (int q = 0; q < 4; q++) acc[i][j][q] = 0.f;

    gemm_core(g_Xh, g_WhT[mode], row0, col0, gsm, acc);

    const int tid = threadIdx.x;
    const int wid = tid >> 5;
    const int lane = tid & 31;
    const int gid = lane >> 2;
    const int t = lane & 3;
    const int wm = wid & 1;
    const int wn = wid >> 1;

    if (mode == 2) {
        // V: transpose in smem, store [b,h,d,s] coalesced along s.
        __half* tile = (__half*)gsm;     // [128 cols][136] halves
        #pragma unroll
        for (int mt = 0; mt < 4; mt++)
            #pragma unroll
            for (int rr = 0; rr < 2; rr++) {
                const int rl = wm * 64 + mt * 16 + gid + rr * 8;
                #pragma unroll
                for (int nt = 0; nt < 4; nt++) {
                    const int cl = wn * 32 + nt * 8 + 2 * t;
                    tile[cl * 136 + rl]       = __float2half_rn(acc[mt][nt][rr * 2 + 0]);
                    tile[(cl + 1) * 136 + rl] = __float2half_rn(acc[mt][nt][rr * 2 + 1]);
                }
            }
        __syncthreads();
        const int bb = row0 >> 11;
        const int s0 = row0 & 2047;
        #pragma unroll
        for (int i = 0; i < 8; i++) {
            int idx = tid + i * 256;      // 2048 16B chunks
            int r = idx >> 4, c8 = idx & 15;
            int hh = (col0 >> 6) + (r >> 6);
            int dd = r & 63;
            float4 v = *(const float4*)&tile[r * 136 + c8 * 8];
            *(float4*)(g_Vth + (((size_t)bb * NH_ + hh) * HD_ + dd) * S_ + s0 + c8 * 8) = v;
        }
    } else {
        __half* dst = (mode == 0) ? g_Qah : g_Kah;
        #pragma unroll
        for (int mt = 0; mt < 4; mt++)
            #pragma unroll
            for (int rr = 0; rr < 2; rr++) {
                const int rg = row0 + wm * 64 + mt * 16 + gid + rr * 8;
                const int bb = rg >> 11;
                const int ss = rg & 2047;
                #pragma unroll
                for (int nt = 0; nt < 4; nt++) {
                    const int cg = col0 + wn * 32 + nt * 8 + 2 * t;
                    const int hh = cg >> 6, dd = cg & 63;
                    const size_t go = (((size_t)bb * NH_ + hh) * S_ + ss) * HD_ + dd;
                    *(uint32_t*)(dst + go) =
                        pack_h2(acc[mt][nt][rr * 2 + 0], acc[mt][nt][rr * 2 + 1]);
                }
            }
    }
}

// ---------------------------------------------------------------------------
// Output projection GEMM: out(fp32) = ctx(fp16) @ WO   [verified round 9]
// ---------------------------------------------------------------------------
__global__ __launch_bounds__(256, 2)
void gemm_o(float* __restrict__ out) {
    extern __shared__ char gsm[];
    const int row0 = blockIdx.y * TM;
    const int col0 = blockIdx.x * TN;

    float acc[4][4][4];
    #pragma unroll
    for (int i = 0; i < 4; i++)
        #pragma unroll
        for (int j = 0; j < 4; j++)
            #pragma unroll
            for (int q = 0; q < 4; q++) acc[i][j][q] = 0.f;

    gemm_core(g_Ch, g_WhT[3], row0, col0, gsm, acc);

    const int tid = threadIdx.x;
    const int wid = tid >> 5;
    const int lane = tid & 31;
    const int gid = lane >> 2;
    const int t = lane & 3;
    const int wm = wid & 1;
    const int wn = wid >> 1;

    #pragma unroll
    for (int mt = 0; mt < 4; mt++) {
        const int rg = row0 + wm * 64 + mt * 16 + gid;
        #pragma unroll
        for (int nt = 0; nt < 4; nt++) {
            const int cg = col0 + wn * 32 + nt * 8 + 2 * t;
            *(float2*)(out + (size_t)rg * H_ + cg) =
                make_float2(acc[mt][nt][0], acc[mt][nt][1]);
            *(float2*)(out + (size_t)(rg + 8) * H_ + cg) =
                make_float2(acc[mt][nt][2], acc[mt][nt][3]);
        }
    }
}

// ---------------------------------------------------------------------------
// Flash attention, fp16 MMA. CTA = 128 q-rows (1 m16 tile per warp) so the
// kernel fits 2 CTAs/SM (<=128 regs, 55KB smem) — softmax of one CTA hides
// MMA of the other. kv-tile 64, double-buffered cp.async.
// ---------------------------------------------------------------------------
#define FROWB 144
#define SQH   0
#define SKV0  18432              // 128*144
#define KVBUF 18432              // Kh + Vh, each 64*144=9216
#define OKH   0
#define OVH   9216
#define SMK   55296              // mask: 2 bufs x 64 x 4B
#define FSMEM 55808              // x2 CTAs = 111.6KB/SM

__global__ __launch_bounds__(256, 2)
void flash_mma(const int* __restrict__ mask) {
    extern __shared__ char sm[];
    const float NEG = __int_as_float(0xff800000u);
    const int tid = threadIdx.x;
    const int wid = tid >> 5;
    const int lane = tid & 31;
    const int gid = lane >> 2;
    const int t = lane & 3;
    const int q0 = blockIdx.x * 128;
    const int h = blockIdx.y;
    const int b = blockIdx.z;
    const size_t bh = (size_t)b * NH_ + h;

    const __half* Qhp = g_Qah + (bh * S_ + q0) * HD_;
    const __half* Khp = g_Kah + bh * S_ * HD_;
    const __half* Vtp = g_Vth + bh * HD_ * S_;
    const int* mkp = mask + b * S_;

    const uint32_t sb = smem_u32(sm);

    // Load Q (128 x 64 halves)
    #pragma unroll
    for (int i = 0; i < 4; i++) {
        int idx = tid + i * 256;          // 1024 chunks
        int r = idx >> 3, c = idx & 7;
        cp16(sb + SQH + r * FROWB + c * 16, Qhp + (size_t)r * HD_ + c * 8);
    }
    cp_commit();

    auto load_kv = [&](int tile, int buf) {
        const int kv0 = tile * 64;
        const uint32_t kb = sb + SKV0 + buf * KVBUF;
        #pragma unroll
        for (int i = 0; i < 2; i++) {
            int idx = tid + i * 256;
            int r = idx >> 3, c = idx & 7;
            uint32_t so = r * FROWB + c * 16;
            cp16(kb + OKH + so, Khp + (size_t)(kv0 + r) * HD_ + c * 8);
            cp16(kb + OVH + so, Vtp + (size_t)r * S_ + kv0 + c * 8);
        }
        if (tid < 64) cp4(sb + SMK + buf * 256 + tid * 4, mkp + kv0 + tid);
        cp_commit();
    };

    load_kv(0, 0);

    float mr0 = NEG, mr1 = NEG, lr0 = 0.f, lr1 = 0.f;
    float ctx[8][4];
    #pragma unroll
    for (int nt = 0; nt < 8; nt++)
        #pragma unroll
        for (int e = 0; e < 4; e++) ctx[nt][e] = 0.f;

    const int m0r = wid * 16;

    for (int tile = 0; tile < 32; tile++) {
        const int buf = tile & 1;
        if (tile + 1 < 32) {
            load_kv(tile + 1, buf ^ 1);
            asm volatile("cp.async.wait_group 1;" ::: "memory");
        } else {
            asm volatile("cp.async.wait_group 0;" ::: "memory");
        }
        __syncthreads();

        const char* kb = sm + SKV0 + buf * KVBUF;
        const int* mk = (const int*)(sm + SMK + buf * 256);

        // --- S = QK^T ---
        float sc[8][4];
        #pragma unroll
        for (int nt = 0; nt < 8; nt++)
            #pragma unroll
            for (int e = 0; e < 4; e++) sc[nt][e] = 0.f;

        #pragma unroll
        for (int ks = 0; ks < 4; ks++) {
            const int kcb = ks * 32 + 4 * t;
            uint32_t ah[4];
            {
                const char* qa = sm + SQH + (m0r + gid) * FROWB + kcb;
                const char* qb = sm + SQH + (m0r + gid + 8) * FROWB + kcb;
                ah[0] = *(const uint32_t*)qa;
                ah[1] = *(const uint32_t*)qb;
                ah[2] = *(const uint32_t*)(qa + 16);
                ah[3] = *(const uint32_t*)(qb + 16);
            }
            #pragma unroll
            for (int nt = 0; nt < 8; nt++) {
                const char* kr = kb + (nt * 8 + gid) * FROWB + kcb;
                uint32_t bhf[2] = { *(const uint32_t*)(kr + OKH),
                                    *(const uint32_t*)(kr + OKH + 16) };
                mma16816(sc[nt], ah, bhf);
            }
        }

        // --- scale, clip, mask; online softmax ---
        float tm0 = NEG, tm1 = NEG;
        #pragma unroll
        for (int nt = 0; nt < 8; nt++) {
            int c0 = nt * 8 + 2 * t;
            int k0 = mk[c0], k1 = mk[c0 + 1];
            float v;
            v = fminf(fmaxf(sc[nt][0] * 0.125f, -10000.f), 10000.f);
            sc[nt][0] = k0 ? v : NEG;
            v = fminf(fmaxf(sc[nt][1] * 0.125f, -10000.f), 10000.f);
            sc[nt][1] = k1 ? v : NEG;
            v = fminf(fmaxf(sc[nt][2] * 0.125f, -10000.f), 10000.f);
            sc[nt][2] = k0 ? v : NEG;
            v = fminf(fmaxf(sc[nt][3] * 0.125f, -10000.f), 10000.f);
            sc[nt][3] = k1 ? v : NEG;
            tm0 = fmaxf(tm0, fmaxf(sc[nt][0], sc[nt][1]));
            tm1 = fmaxf(tm1, fmaxf(sc[nt][2], sc[nt][3]));
        }
        tm0 = fmaxf(tm0, __shfl_xor_sync(0xffffffffu, tm0, 1));
        tm0 = fmaxf(tm0, __shfl_xor_sync(0xffffffffu, tm0, 2));
        tm1 = fmaxf(tm1, __shfl_xor_sync(0xffffffffu, tm1, 1));
        tm1 = fmaxf(tm1, __shfl_xor_sync(0xffffffffu, tm1, 2));

        float mn0 = fmaxf(mr0, tm0), mn1 = fmaxf(mr1, tm1);
        float al0 = (mn0 == NEG) ? 1.f : __expf(mr0 - mn0);
        float al1 = (mn1 == NEG) ? 1.f : __expf(mr1 - mn1);

        float rs0 = 0.f, rs1 = 0.f;
        #pragma unroll
        for (int nt = 0; nt < 8; nt++) {
            float p;
            p = (sc[nt][0] == NEG) ? 0.f : __expf(sc[nt][0] - mn0);
            sc[nt][0] = p; rs0 += p;
            p = (sc[nt][1] == NEG) ? 0.f : __expf(sc[nt][1] - mn0);
            sc[nt][1] = p; rs0 += p;
            p = (sc[nt][2] == NEG) ? 0.f : __expf(sc[nt][2] - mn1);
            sc[nt][2] = p; rs1 += p;
            p = (sc[nt][3] == NEG) ? 0.f : __expf(sc[nt][3] - mn1);
            sc[nt][3] = p; rs1 += p;
        }
        rs0 += __shfl_xor_sync(0xffffffffu, rs0, 1);
        rs0 += __shfl_xor_sync(0xffffffffu, rs0, 2);
        rs1 += __shfl_xor_sync(0xffffffffu, rs1, 1);
        rs1 += __shfl_xor_sync(0xffffffffu, rs1, 2);
        lr0 = lr0 * al0 + rs0;
        lr1 = lr1 * al1 + rs1;
        mr0 = mn0; mr1 = mn1;

        #pragma unroll
        for (int nt = 0; nt < 8; nt++) {
            ctx[nt][0] *= al0; ctx[nt][1] *= al0;
            ctx[nt][2] *= al1; ctx[nt][3] *= al1;
        }

        // --- ctx += P @ Vt ---
        #pragma unroll
        for (int kk = 0; kk < 4; kk++) {
            uint32_t aph[4];
            aph[0] = pack_h2(sc[2 * kk][0],     sc[2 * kk][1]);
            aph[1] = pack_h2(sc[2 * kk][2],     sc[2 * kk][3]);
            aph[2] = pack_h2(sc[2 * kk + 1][0], sc[2 * kk + 1][1]);
            aph[3] = pack_h2(sc[2 * kk + 1][2], sc[2 * kk + 1][3]);
            const int kcb = kk * 32 + 4 * t;
            #pragma unroll
            for (int nt = 0; nt < 8; nt++) {
                const char* vr = kb + (nt * 8 + gid) * FROWB + kcb;
                uint32_t bvh[2] = { *(const uint32_t*)(vr + OVH),
                                    *(const uint32_t*)(vr + OVH + 16) };
                mma16816(ctx[nt], aph, bvh);
            }
        }
        __syncthreads();
    }

    // Epilogue: normalize, fp16, store [s,H]
    const float inv0 = 1.f / lr0;
    const float inv1 = 1.f / lr1;
    const int r0 = b * S_ + q0 + m0r + gid;
    #pragma unroll
    for (int nt = 0; nt < 8; nt++) {
        const int d0 = h * HD_ + nt * 8 + 2 * t;
        *(uint32_t*)(g_Ch + (size_t)r0 * H_ + d0) =
            pack_h2(ctx[nt][0] * inv0, ctx[nt][1] * inv0);
        *(uint32_t*)(g_Ch + (size_t)(r0 + 8) * H_ + d0) =
            pack_h2(ctx[nt][2] * inv1, ctx[nt][3] * inv1);
    }
}

// ---------------------------------------------------------------------------
// X convert: fp32 -> fp16
// ---------------------------------------------------------------------------
__global__ void xcvt(const float* __restrict__ A, int n4) {
    int i = blockIdx.x * blockDim.x + threadIdx.x;
    if (i >= n4) return;
    float4 v = ((const float4*)A)[i];
    ((uint32_t*)g_Xh)[2 * i + 0] = pack_h2(v.x, v.y);
    ((uint32_t*)g_Xh)[2 * i + 1] = pack_h2(v.z, v.w);
}

// ---------------------------------------------------------------------------
// Weight convert+transpose: W[K,N] fp32 -> WhT[z][N,K] fp16
// ---------------------------------------------------------------------------
__global__ void wcvt_t(const float* __restrict__ W0, const float* __restrict__ W1,
                       const float* __restrict__ W2, const float* __restrict__ W3) {
    __shared__ float tbuf[32][33];
    const int z = blockIdx.z;
    const float* W = (z == 0) ? W0 : (z == 1) ? W1 : (z == 2) ? W2 : W3;
    __half* O = g_WhT[z];
    int n0 = blockIdx.x * 32, k0 = blockIdx.y * 32;
    int x = threadIdx.x, y0 = threadIdx.y;
    #pragma unroll
    for (int i = y0; i < 32; i += 8)
        tbuf[i][x] = W[(size_t)(k0 + i) * H_ + n0 + x];
    __syncthreads();
    #pragma unroll
    for (int i = y0; i < 32; i += 8)
        O[(size_t)(n0 + i) * H_ + k0 + x] = __float2half_rn(tbuf[x][i]);
}

// ---------------------------------------------------------------------------
// Launch (flash_mma stays launch #4 -> ncu capture window)
// ---------------------------------------------------------------------------
extern "C" void kernel_launch(void* const* d_in, const int* in_sizes, int n_in,
                              void* d_out, int out_size) {
    const float* X    = (const float*)d_in[0];
    const int*   mask = (const int*)d_in[1];
    const float* WQ   = (const float*)d_in[2];
    const float* WK   = (const float*)d_in[3];
    const float* WV   = (const float*)d_in[4];
    const float* WO   = (const float*)d_in[5];
    float* out = (float*)d_out;

    cudaFuncSetAttribute(gemm_qkv, cudaFuncAttributeMaxDynamicSharedMemorySize, GSMEM);
    cudaFuncSetAttribute(gemm_o,   cudaFuncAttributeMaxDynamicSharedMemorySize, GSMEM);
    cudaFuncSetAttribute(flash_mma, cudaFuncAttributeMaxDynamicSharedMemorySize, FSMEM);

    // 1. Prep
    xcvt<<<(M_ * H_ / 4 + 255) / 256, 256>>>(X, M_ * H_ / 4);
    // 2.
    wcvt_t<<<dim3(32, 32, 4), dim3(32, 8)>>>(WQ, WK, WV, WO);
    // 3. QKV projections (fused; V-transpose in epilogue)
    gemm_qkv<<<dim3(H_ / TN, M_ / TM, 3), 256, GSMEM>>>();
    // 4. Attention (128 q-rows/CTA, 2 CTAs/SM)
    flash_mma<<<dim3(S_ / 128, NH_, B_), 256, FSMEM>>>(mask);
    // 5. Output projection
    gemm_o<<<dim3(H_ / TN, M_ / TM), 256, GSMEM>>>(out);
}

// round 11
// speedup vs baseline: 2.6501x; 1.1826x over previous
#include <cuda_runtime.h>
#include <cuda_fp16.h>
#include <cstdint>

// Problem constants
#define B_  2
#define S_  2048
#define H_  1024
#define NH_ 16
#define HD_ 64
#define M_  (B_*S_)   // 4096 rows

// ---------------------------------------------------------------------------
// Scratch (allocation-free: device globals)
// ---------------------------------------------------------------------------
__device__ __half g_Xh[(size_t)M_ * H_];
__device__ __half g_WhT[4][(size_t)H_ * H_];     // transposed [N,K] fp16
__device__ __half g_Qah[(size_t)M_ * H_];        // [b,h,s,d] fp16 (pre-scaled by 0.125)
__device__ __half g_Kah[(size_t)M_ * H_];        // [b,h,s,d] fp16
__device__ __half g_Vth[(size_t)M_ * H_];        // [b,h,d,s] fp16
__device__ __half g_Ch [(size_t)M_ * H_];        // context [s,H] fp16

// ---------------------------------------------------------------------------
// Helpers
// ---------------------------------------------------------------------------
__device__ __forceinline__ uint32_t smem_u32(const void* p) {
    uint32_t a;
    asm("{ .reg .u64 t; cvta.to.shared.u64 t, %1; cvt.u32.u64 %0, t; }"
        : "=r"(a) : "l"(p));
    return a;
}
__device__ __forceinline__ void cp16(uint32_t s, const void* g) {
    asm volatile("cp.async.cg.shared.global [%0], [%1], 16;" :: "r"(s), "l"(g));
}
__device__ __forceinline__ void cp_commit() {
    asm volatile("cp.async.commit_group;" ::: "memory");
}
__device__ __forceinline__ void mma16816(float* c, const uint32_t* a, const uint32_t* b) {
    asm volatile(
        "mma.sync.aligned.m16n8k16.row.col.f32.f16.f16.f32 "
        "{%0,%1,%2,%3}, {%4,%5,%6,%7}, {%8,%9}, {%0,%1,%2,%3};"
        : "+f"(c[0]), "+f"(c[1]), "+f"(c[2]), "+f"(c[3])
        : "r"(a[0]), "r"(a[1]), "r"(a[2]), "r"(a[3]), "r"(b[0]), "r"(b[1]));
}
__device__ __forceinline__ void ldsm_x4(uint32_t* r, uint32_t addr) {
    asm volatile("ldmatrix.sync.aligned.m8n8.x4.shared.b16 {%0,%1,%2,%3}, [%4];"
        : "=r"(r[0]), "=r"(r[1]), "=r"(r[2]), "=r"(r[3]) : "r"(addr));
}
__device__ __forceinline__ void ldsm_x2(uint32_t* r, uint32_t addr) {
    asm volatile("ldmatrix.sync.aligned.m8n8.x2.shared.b16 {%0,%1}, [%2];"
        : "=r"(r[0]), "=r"(r[1]) : "r"(addr));
}
__device__ __forceinline__ uint32_t pack_h2(float f0, float f1) {
    __half2 hh = __halves2half2(__float2half_rn(f0), __float2half_rn(f1));
    return *(uint32_t*)&hh;
}

// ---------------------------------------------------------------------------
// GEMM core: plain fp16.  acc = A@B^T   (B stored [N,K]); ldmatrix fragments.
// CTA tile 128x128, K-chunk 32, 3-stage cp.async, 8 warps (2x4), warp 64x32.
// ---------------------------------------------------------------------------
#define TM 128
#define TN 128
#define TK 32
#define PITCH 40                 // halves per smem row (80 B)
#define OAH 0
#define OBH 10240                // 128*80
#define STG 20480
#define NSTAGE 3
#define GSMEM (STG * NSTAGE)     // 61440 -> 2 CTAs/SM
#define NCH (H_ / TK)            // 32

__device__ __forceinline__ void gemm_core(
    const __half* __restrict__ Ah, const __half* __restrict__ Bh,
    int row0, int col0, char* gsm, float acc[4][4][4]) {

    const int tid = threadIdx.x;
    const int wid = tid >> 5;
    const int lane = tid & 31;
    const int li = lane & 7;
    const int wm = wid & 1;
    const int wn = wid >> 1;
    const uint32_t sb = smem_u32(gsm);

    // ldmatrix lane-address components
    const uint32_t aoff = (uint32_t)((wm * 64 + li + ((lane & 8) ? 8 : 0)) * 80)
                          + ((lane & 16) ? 16u : 0u);
    const uint32_t boff = (uint32_t)((wn * 32 + li) * 80) + ((lane & 8) ? 16u : 0u);

    auto load_chunk = [&](int c, int s) {
        const int k0 = c * TK;
        const uint32_t base = sb + s * STG;
        #pragma unroll
        for (int i = 0; i < 2; i++) {               // A: 512 chunks
            int idx = tid + i * 256;
            int r = idx >> 2, c16 = idx & 3;
            uint32_t so = r * 80 + c16 * 16;
            cp16(base + OAH + so, Ah + (size_t)(row0 + r) * H_ + k0 + c16 * 8);
        }
        #pragma unroll
        for (int i = 0; i < 2; i++) {               // B: 512 chunks
            int idx = tid + i * 256;
            int r = idx >> 2, c16 = idx & 3;
            uint32_t so = r * 80 + c16 * 16;
            cp16(base + OBH + so, Bh + (size_t)(col0 + r) * H_ + k0 + c16 * 8);
        }
        cp_commit();
    };

    load_chunk(0, 0);
    load_chunk(1, 1);

    for (int c = 0; c < NCH; c++) {
        const int s = c % NSTAGE;
        if (c + 2 < NCH) load_chunk(c + 2, (c + 2) % NSTAGE);
        else cp_commit();                           // keep group count uniform
        asm volatile("cp.async.wait_group 2;" ::: "memory");
        __syncthreads();

        const uint32_t stb = sb + s * STG;

        #pragma unroll
        for (int ks = 0; ks < 2; ks++) {
            uint32_t ah[4][4], bh[4][2];
            #pragma unroll
            for (int mt = 0; mt < 4; mt++)
                ldsm_x4(ah[mt], stb + OAH + aoff + mt * 1280 + ks * 32);
            #pragma unroll
            for (int nt = 0; nt < 4; nt++)
                ldsm_x2(bh[nt], stb + OBH + boff + nt * 640 + ks * 32);
            #pragma unroll
            for (int mt = 0; mt < 4; mt++)
                #pragma unroll
                for (int nt = 0; nt < 4; nt++)
                    mma16816(acc[mt][nt], ah[mt], bh[nt]);
        }
        __syncthreads();
    }
}

// ---------------------------------------------------------------------------
// QKV projection GEMM: grid.z selects Q/K/V. Q pre-scaled by 0.125 (exact).
// Q,K -> [b,h,s,d]; V -> fused transpose to [b,h,d,s] via smem bounce.
// ---------------------------------------------------------------------------
__global__ __launch_bounds__(256, 2)
void gemm_qkv() {
    extern __shared__ char gsm[];
    const int mode = blockIdx.z;
    const int row0 = blockIdx.y * TM;
    const int col0 = blockIdx.x * TN;

    float acc[4][4][4];
    #pragma unroll
    for (int i = 0; i < 4; i++)
        #pragma unroll
        for (int j = 0; j < 4; j++)
            #pragma unroll
            for (int q = 0; q < 4; q++) acc[i][j][q] = 0.f;

    gemm_core(g_Xh, g_WhT[mode], row0, col0, gsm, acc);

    const int tid = threadIdx.x;
    const int wid = tid >> 5;
    const int lane = tid & 31;
    const int gid = lane >> 2;
    const int t = lane & 3;
    const int wm = wid & 1;
    const int wn = wid >> 1;

    if (mode == 2) {
        // V: transpose in smem, store [b,h,d,s] coalesced along s.
        __half* tile = (__half*)gsm;     // [128 cols][136] halves
        #pragma unroll
        for (int mt = 0; mt < 4; mt++)
            #pragma unroll
            for (int rr = 0; rr < 2; rr++) {
                const int rl = wm * 64 + mt * 16 + gid + rr * 8;
                #pragma unroll
                for (int nt = 0; nt < 4; nt++) {
                    const int cl = wn * 32 + nt * 8 + 2 * t;
                    tile[cl * 136 + rl]       = __float2half_rn(acc[mt][nt][rr * 2 + 0]);
                    tile[(cl + 1) * 136 + rl] = __float2half_rn(acc[mt][nt][rr * 2 + 1]);
                }
            }
        __syncthreads();
        const int bb = row0 >> 11;
        const int s0 = row0 & 2047;
        #pragma unroll
        for (int i = 0; i < 8; i++) {
            int idx = tid + i * 256;      // 2048 16B chunks
            int r = idx >> 4, c8 = idx & 15;
            int hh = (col0 >> 6) + (r >> 6);
            int dd = r & 63;
            float4 v = *(const float4*)&tile[r * 136 + c8 * 8];
            *(float4*)(g_Vth + (((size_t)bb * NH_ + hh) * HD_ + dd) * S_ + s0 + c8 * 8) = v;
        }
    } else {
        __half* dst = (mode == 0) ? g_Qah : g_Kah;
        const float scl = (mode == 0) ? 0.125f : 1.0f;   // fold softmax scale into Q
        #pragma unroll
        for (int mt = 0; mt < 4; mt++)
            #pragma unroll
            for (int rr = 0; rr < 2; rr++) {
                const int rg = row0 + wm * 64 + mt * 16 + gid + rr * 8;
                const int bb = rg >> 11;
                const int ss = rg & 2047;
                #pragma unroll
                for (int nt = 0; nt < 4; nt++) {
                    const int cg = col0 + wn * 32 + nt * 8 + 2 * t;
                    const int hh = cg >> 6, dd = cg & 63;
                    const size_t go = (((size_t)bb * NH_ + hh) * S_ + ss) * HD_ + dd;
                    *(uint32_t*)(dst + go) =
                        pack_h2(acc[mt][nt][rr * 2 + 0] * scl,
                                acc[mt][nt][rr * 2 + 1] * scl);
                }
            }
    }
}

// ---------------------------------------------------------------------------
// Output projection GEMM: out(fp32) = ctx(fp16) @ WO
// ---------------------------------------------------------------------------
__global__ __launch_bounds__(256, 2)
void gemm_o(float* __restrict__ out) {
    extern __shared__ char gsm[];
    const int row0 = blockIdx.y * TM;
    const int col0 = blockIdx.x * TN;

    float acc[4][4][4];
    #pragma unroll
    for (int i = 0; i < 4; i++)
        #pragma unroll
        for (int j = 0; j < 4; j++)
            #pragma unroll
            for (int q = 0; q < 4; q++) acc[i][j][q] = 0.f;

    gemm_core(g_Ch, g_WhT[3], row0, col0, gsm, acc);

    const int tid = threadIdx.x;
    const int wid = tid >> 5;
    const int lane = tid & 31;
    const int gid = lane >> 2;
    const int t = lane & 3;
    const int wm = wid & 1;
    const int wn = wid >> 1;

    #pragma unroll
    for (int mt = 0; mt < 4; mt++) {
        const int rg = row0 + wm * 64 + mt * 16 + gid;
        #pragma unroll
        for (int nt = 0; nt < 4; nt++) {
            const int cg = col0 + wn * 32 + nt * 8 + 2 * t;
            *(float2*)(out + (size_t)rg * H_ + cg) =
                make_float2(acc[mt][nt][0], acc[mt][nt][1]);
            *(float2*)(out + (size_t)(rg + 8) * H_ + cg) =
                make_float2(acc[mt][nt][2], acc[mt][nt][3]);
        }
    }
}

// ---------------------------------------------------------------------------
// Flash attention, fp16 MMA + ldmatrix + lean softmax.
// CTA = 128 q-rows, 2 CTAs/SM. Q pre-scaled; mask = additive float bias;
// no clip (scores bounded << 1e4); exp unguarded (exp(-inf)=0 in HW).
// ---------------------------------------------------------------------------
#define FROWB 144
#define SQH   0
#define SKV0  18432              // 128*144
#define KVBUF 18432              // Kh + Vh, each 64*144=9216
#define OKH   0
#define OVH   9216
#define SMK   55296              // bias floats: 2 bufs x 64 x 4B
#define FSMEM 55808              // x2 CTAs = 111.6KB/SM

__global__ __launch_bounds__(256, 2)
void flash_mma(const int* __restrict__ mask) {
    extern __shared__ char sm[];
    const float NEG = __int_as_float(0xff800000u);
    const int tid = threadIdx.x;
    const int wid = tid >> 5;
    const int lane = tid & 31;
    const int li = lane & 7;
    const int gid = lane >> 2;
    const int t = lane & 3;
    const int q0 = blockIdx.x * 128;
    const int h = blockIdx.y;
    const int b = blockIdx.z;
    const size_t bh = (size_t)b * NH_ + h;

    const __half* Qhp = g_Qah + (bh * S_ + q0) * HD_;
    const __half* Khp = g_Kah + bh * S_ * HD_;
    const __half* Vtp = g_Vth + bh * HD_ * S_;
    const int* mkp = mask + b * S_;

    const uint32_t sb = smem_u32(sm);
    const int m0r = wid * 16;

    // ldmatrix lane-address components
    const uint32_t q_lbase = sb + SQH
        + (uint32_t)((m0r + li + ((lane & 8) ? 8 : 0)) * FROWB)
        + ((lane & 16) ? 16u : 0u);
    const uint32_t kv_loff = (uint32_t)(li * FROWB) + ((lane & 8) ? 16u : 0u);

    // Load Q (128 x 64 halves)
    #pragma unroll
    for (int i = 0; i < 4; i++) {
        int idx = tid + i * 256;          // 1024 chunks
        int r = idx >> 3, c = idx & 7;
        cp16(sb + SQH + r * FROWB + c * 16, Qhp + (size_t)r * HD_ + c * 8);
    }
    cp_commit();

    auto load_kv = [&](int tile, int buf) {
        const int kv0 = tile * 64;
        const uint32_t kb = sb + SKV0 + buf * KVBUF;
        #pragma unroll
        for (int i = 0; i < 2; i++) {
            int idx = tid + i * 256;
            int r = idx >> 3, c = idx & 7;
            uint32_t so = r * FROWB + c * 16;
            cp16(kb + OKH + so, Khp + (size_t)(kv0 + r) * HD_ + c * 8);
            cp16(kb + OVH + so, Vtp + (size_t)r * S_ + kv0 + c * 8);
        }
        if (tid < 64) {
            float bias = (mkp[kv0 + tid] == 0) ? NEG : 0.f;
            *(float*)(sm + SMK + buf * 256 + tid * 4) = bias;
        }
        cp_commit();
    };

    load_kv(0, 0);

    float mr0 = NEG, mr1 = NEG, lr0 = 0.f, lr1 = 0.f;
    float ctx[8][4];
    #pragma unroll
    for (int nt = 0; nt < 8; nt++)
        #pragma unroll
        for (int e = 0; e < 4; e++) ctx[nt][e] = 0.f;

    for (int tile = 0; tile < 32; tile++) {
        const int buf = tile & 1;
        if (tile + 1 < 32) {
            load_kv(tile + 1, buf ^ 1);
            asm volatile("cp.async.wait_group 1;" ::: "memory");
        } else {
            asm volatile("cp.async.wait_group 0;" ::: "memory");
        }
        __syncthreads();

        const uint32_t kb = sb + SKV0 + buf * KVBUF;
        const char* mkb = sm + SMK + buf * 256;

        // --- S = QK^T (Q pre-scaled) ---
        float sc[8][4];
        #pragma unroll
        for (int nt = 0; nt < 8; nt++)
            #pragma unroll
            for (int e = 0; e < 4; e++) sc[nt][e] = 0.f;

        #pragma unroll
        for (int ks = 0; ks < 4; ks++) {
            uint32_t ah[4];
            ldsm_x4(ah, q_lbase + ks * 32);
            #pragma unroll
            for (int nt = 0; nt < 8; nt++) {
                uint32_t bhf[2];
                ldsm_x2(bhf, kb + OKH + kv_loff + nt * 1152 + ks * 32);
                mma16816(sc[nt], ah, bhf);
            }
        }

        // --- mask bias; row max; online softmax ---
        float tm0 = NEG, tm1 = NEG;
        #pragma unroll
        for (int nt = 0; nt < 8; nt++) {
            float2 bbv = *(const float2*)(mkb + (nt * 8 + 2 * t) * 4);
            sc[nt][0] += bbv.x;
            sc[nt][1] += bbv.y;
            sc[nt][2] += bbv.x;
            sc[nt][3] += bbv.y;
            tm0 = fmaxf(tm0, fmaxf(sc[nt][0], sc[nt][1]));
            tm1 = fmaxf(tm1, fmaxf(sc[nt][2], sc[nt][3]));
        }
        tm0 = fmaxf(tm0, __shfl_xor_sync(0xffffffffu, tm0, 1));
        tm0 = fmaxf(tm0, __shfl_xor_sync(0xffffffffu, tm0, 2));
        tm1 = fmaxf(tm1, __shfl_xor_sync(0xffffffffu, tm1, 1));
        tm1 = fmaxf(tm1, __shfl_xor_sync(0xffffffffu, tm1, 2));

        float mn0 = fmaxf(mr0, tm0), mn1 = fmaxf(mr1, tm1);
        float al0 = (mn0 == NEG) ? 1.f : __expf(mr0 - mn0);
        float al1 = (mn1 == NEG) ? 1.f : __expf(mr1 - mn1);

        float rs0 = 0.f, rs1 = 0.f;
        #pragma unroll
        for (int nt = 0; nt < 8; nt++) {
            float p;
            p = __expf(sc[nt][0] - mn0); sc[nt][0] = p; rs0 += p;
            p = __expf(sc[nt][1] - mn0); sc[nt][1] = p; rs0 += p;
            p = __expf(sc[nt][2] - mn1); sc[nt][2] = p; rs1 += p;
            p = __expf(sc[nt][3] - mn1); sc[nt][3] = p; rs1 += p;
        }
        rs0 += __shfl_xor_sync(0xffffffffu, rs0, 1);
        rs0 += __shfl_xor_sync(0xffffffffu, rs0, 2);
        rs1 += __shfl_xor_sync(0xffffffffu, rs1, 1);
        rs1 += __shfl_xor_sync(0xffffffffu, rs1, 2);
        lr0 = lr0 * al0 + rs0;
        lr1 = lr1 * al1 + rs1;
        mr0 = mn0; mr1 = mn1;

        #pragma unroll
        for (int nt = 0; nt < 8; nt++) {
            ctx[nt][0] *= al0; ctx[nt][1] *= al0;
            ctx[nt][2] *= al1; ctx[nt][3] *= al1;
        }

        // --- ctx += P @ Vt ---
        #pragma unroll
        for (int kk = 0; kk < 4; kk++) {
            uint32_t aph[4];
            aph[0] = pack_h2(sc[2 * kk][0],     sc[2 * kk][1]);
            aph[1] = pack_h2(sc[2 * kk][2],     sc[2 * kk][3]);
            aph[2] = pack_h2(sc[2 * kk + 1][0], sc[2 * kk + 1][1]);
            aph[3] = pack_h2(sc[2 * kk + 1][2], sc[2 * kk + 1][3]);
            #pragma unroll
            for (int nt = 0; nt < 8; nt++) {
                uint32_t bvh[2];
                ldsm_x2(bvh, kb + OVH + kv_loff + nt * 1152 + kk * 32);
                mma16816(ctx[nt], aph, bvh);
            }
        }
        __syncthreads();
    }

    // Epilogue: normalize, fp16, store [s,H]
    const float inv0 = 1.f / lr0;
    const float inv1 = 1.f / lr1;
    const int r0 = b * S_ + q0 + m0r + gid;
    #pragma unroll
    for (int nt = 0; nt < 8; nt++) {
        const int d0 = h * HD_ + nt * 8 + 2 * t;
        *(uint32_t*)(g_Ch + (size_t)r0 * H_ + d0) =
            pack_h2(ctx[nt][0] * inv0, ctx[nt][1] * inv0);
        *(uint32_t*)(g_Ch + (size_t)(r0 + 8) * H_ + d0) =
            pack_h2(ctx[nt][2] * inv1, ctx[nt][3] * inv1);
    }
}

// ---------------------------------------------------------------------------
// X convert: fp32 -> fp16
// ---------------------------------------------------------------------------
__global__ void xcvt(const float* __restrict__ A, int n4) {
    int i = blockIdx.x * blockDim.x + threadIdx.x;
    if (i >= n4) return;
    float4 v = ((const float4*)A)[i];
    ((uint32_t*)g_Xh)[2 * i + 0] = pack_h2(v.x, v.y);
    ((uint32_t*)g_Xh)[2 * i + 1] = pack_h2(v.z, v.w);
}

// ---------------------------------------------------------------------------
// Weight convert+transpose: W[K,N] fp32 -> WhT[z][N,K] fp16
// ---------------------------------------------------------------------------
__global__ void wcvt_t(const float* __restrict__ W0, const float* __restrict__ W1,
                       const float* __restrict__ W2, const float* __restrict__ W3) {
    __shared__ float tbuf[32][33];
    const int z = blockIdx.z;
    const float* W = (z == 0) ? W0 : (z == 1) ? W1 : (z == 2) ? W2 : W3;
    __half* O = g_WhT[z];
    int n0 = blockIdx.x * 32, k0 = blockIdx.y * 32;
    int x = threadIdx.x, y0 = threadIdx.y;
    #pragma unroll
    for (int i = y0; i < 32; i += 8)
        tbuf[i][x] = W[(size_t)(k0 + i) * H_ + n0 + x];
    __syncthreads();
    #pragma unroll
    for (int i = y0; i < 32; i += 8)
        O[(size_t)(n0 + i) * H_ + k0 + x] = __float2half_rn(tbuf[x][i]);
}

// ---------------------------------------------------------------------------
// Launch (flash_mma stays launch #4 -> ncu capture window)
// ---------------------------------------------------------------------------
extern "C" void kernel_launch(void* const* d_in, const int* in_sizes, int n_in,
                              void* d_out, int out_size) {
    const float* X    = (const float*)d_in[0];
    const int*   mask = (const int*)d_in[1];
    const float* WQ   = (const float*)d_in[2];
    const float* WK   = (const float*)d_in[3];
    const float* WV   = (const float*)d_in[4];
    const float* WO   = (const float*)d_in[5];
    float* out = (float*)d_out;

    cudaFuncSetAttribute(gemm_qkv, cudaFuncAttributeMaxDynamicSharedMemorySize, GSMEM);
    cudaFuncSetAttribute(gemm_o,   cudaFuncAttributeMaxDynamicSharedMemorySize, GSMEM);
    cudaFuncSetAttribute(flash_mma, cudaFuncAttributeMaxDynamicSharedMemorySize, FSMEM);

    // 1. Prep
    xcvt<<<(M_ * H_ / 4 + 255) / 256, 256>>>(X, M_ * H_ / 4);
    // 2.
    wcvt_t<<<dim3(32, 32, 4), dim3(32, 8)>>>(WQ, WK, WV, WO);
    // 3. QKV projections (fused; Q pre-scaled; V-transpose in epilogue)
    gemm_qkv<<<dim3(H_ / TN, M_ / TM, 3), 256, GSMEM>>>();
    // 4. Attention (128 q-rows/CTA, 2 CTAs/SM, ldmatrix + lean softmax)
    flash_mma<<<dim3(S_ / 128, NH_, B_), 256, FSMEM>>>(mask);
    // 5. Output projection
    gemm_o<<<dim3(H_ / TN, M_ / TM), 256, GSMEM>>>(out);
}

// round 12
// speedup vs baseline: 2.8157x; 1.0625x over previous
#include <cuda_runtime.h>
#include <cuda_fp16.h>
#include <cstdint>

// Problem constants
#define B_  2
#define S_  2048
#define H_  1024
#define NH_ 16
#define HD_ 64
#define M_  (B_*S_)   // 4096 rows

// ---------------------------------------------------------------------------
// Scratch (allocation-free: device globals)
// ---------------------------------------------------------------------------
__device__ __half g_Xh[(size_t)M_ * H_];
__device__ __half g_WhT[4][(size_t)H_ * H_];     // transposed [N,K] fp16
__device__ __half g_Qah[(size_t)M_ * H_];        // [b,h,s,d] fp16 (pre-scaled 0.125)
__device__ __half g_Kah[(size_t)M_ * H_];        // [b,h,s,d] fp16
__device__ __half g_Vth[(size_t)M_ * H_];        // [b,h,d,s] fp16
__device__ __half g_Ch [(size_t)M_ * H_];        // context [s,H] fp16

// ---------------------------------------------------------------------------
// Helpers
// ---------------------------------------------------------------------------
__device__ __forceinline__ uint32_t smem_u32(const void* p) {
    uint32_t a;
    asm("{ .reg .u64 t; cvta.to.shared.u64 t, %1; cvt.u32.u64 %0, t; }"
        : "=r"(a) : "l"(p));
    return a;
}
__device__ __forceinline__ void cp16(uint32_t s, const void* g) {
    asm volatile("cp.async.cg.shared.global [%0], [%1], 16;" :: "r"(s), "l"(g));
}
__device__ __forceinline__ void cp_commit() {
    asm volatile("cp.async.commit_group;" ::: "memory");
}
__device__ __forceinline__ void mma16816(float* c, const uint32_t* a, const uint32_t* b) {
    asm volatile(
        "mma.sync.aligned.m16n8k16.row.col.f32.f16.f16.f32 "
        "{%0,%1,%2,%3}, {%4,%5,%6,%7}, {%8,%9}, {%0,%1,%2,%3};"
        : "+f"(c[0]), "+f"(c[1]), "+f"(c[2]), "+f"(c[3])
        : "r"(a[0]), "r"(a[1]), "r"(a[2]), "r"(a[3]), "r"(b[0]), "r"(b[1]));
}
__device__ __forceinline__ void ldsm_x4(uint32_t* r, uint32_t addr) {
    asm volatile("ldmatrix.sync.aligned.m8n8.x4.shared.b16 {%0,%1,%2,%3}, [%4];"
        : "=r"(r[0]), "=r"(r[1]), "=r"(r[2]), "=r"(r[3]) : "r"(addr));
}
__device__ __forceinline__ uint32_t pack_h2(float f0, float f1) {
    __half2 hh = __halves2half2(__float2half_rn(f0), __float2half_rn(f1));
    return *(uint32_t*)&hh;
}

// ---------------------------------------------------------------------------
// GEMM core: plain fp16.  acc = A@B^T   (B stored [N,K]); x4 ldmatrix only.
// CTA tile 128x128, K-chunk 32, 3-stage cp.async, 8 warps (2x4), warp 64x32.
// ---------------------------------------------------------------------------
#define TM 128
#define TN 128
#define TK 32
#define PITCH 40                 // halves per smem row (80 B)
#define OAH 0
#define OBH 10240                // 128*80
#define STG 20480
#define NSTAGE 3
#define GSMEM (STG * NSTAGE)     // 61440 -> 2 CTAs/SM
#define NCH (H_ / TK)            // 32

__device__ __forceinline__ void gemm_core(
    const __half* __restrict__ Ah, const __half* __restrict__ Bh,
    int row0, int col0, char* gsm, float acc[4][4][4]) {

    const int tid = threadIdx.x;
    const int wid = tid >> 5;
    const int lane = tid & 31;
    const int li = lane & 7;
    const int wm = wid & 1;
    const int wn = wid >> 1;
    const uint32_t sb = smem_u32(gsm);

    // ldmatrix lane-address components
    const uint32_t aoff = (uint32_t)((wm * 64 + li + ((lane & 8) ? 8 : 0)) * 80)
                          + ((lane & 16) ? 16u : 0u);
    // B x4: lanes 0-15 -> n-tile 2j (cols kc, kc+8); lanes 16-31 -> n-tile 2j+1
    const uint32_t boff4 = (uint32_t)((wn * 32 + li + ((lane & 16) ? 8 : 0)) * 80)
                           + ((lane & 8) ? 16u : 0u);

    auto load_chunk = [&](int c, int s) {
        const int k0 = c * TK;
        const uint32_t base = sb + s * STG;
        #pragma unroll
        for (int i = 0; i < 2; i++) {               // A: 512 chunks
            int idx = tid + i * 256;
            int r = idx >> 2, c16 = idx & 3;
            uint32_t so = r * 80 + c16 * 16;
            cp16(base + OAH + so, Ah + (size_t)(row0 + r) * H_ + k0 + c16 * 8);
        }
        #pragma unroll
        for (int i = 0; i < 2; i++) {               // B: 512 chunks
            int idx = tid + i * 256;
            int r = idx >> 2, c16 = idx & 3;
            uint32_t so = r * 80 + c16 * 16;
            cp16(base + OBH + so, Bh + (size_t)(col0 + r) * H_ + k0 + c16 * 8);
        }
        cp_commit();
    };

    load_chunk(0, 0);
    load_chunk(1, 1);

    for (int c = 0; c < NCH; c++) {
        const int s = c % NSTAGE;
        if (c + 2 < NCH) load_chunk(c + 2, (c + 2) % NSTAGE);
        else cp_commit();                           // keep group count uniform
        asm volatile("cp.async.wait_group 2;" ::: "memory");
        __syncthreads();

        const uint32_t stb = sb + s * STG;

        #pragma unroll
        for (int ks = 0; ks < 2; ks++) {
            uint32_t ah[4][4], bh[4][2];
            #pragma unroll
            for (int mt = 0; mt < 4; mt++)
                ldsm_x4(ah[mt], stb + OAH + aoff + mt * 1280 + ks * 32);
            #pragma unroll
            for (int j = 0; j < 2; j++) {
                uint32_t tmp[4];
                ldsm_x4(tmp, stb + OBH + boff4 + j * 1280 + ks * 32);
                bh[2 * j][0] = tmp[0]; bh[2 * j][1] = tmp[1];
                bh[2 * j + 1][0] = tmp[2]; bh[2 * j + 1][1] = tmp[3];
            }
            #pragma unroll
            for (int mt = 0; mt < 4; mt++)
                #pragma unroll
                for (int nt = 0; nt < 4; nt++)
                    mma16816(acc[mt][nt], ah[mt], bh[nt]);
        }
        __syncthreads();
    }
}

// ---------------------------------------------------------------------------
// QKV projection GEMM: grid.z selects Q/K/V. Q pre-scaled by 0.125 (exact).
// Q,K -> [b,h,s,d]; V -> fused transpose to [b,h,d,s] via smem bounce.
// ---------------------------------------------------------------------------
__global__ __launch_bounds__(256, 2)
void gemm_qkv() {
    extern __shared__ char gsm[];
    const int mode = blockIdx.z;
    const int row0 = blockIdx.y * TM;
    const int col0 = blockIdx.x * TN;

    float acc[4][4][4];
    #pragma unroll
    for (int i = 0; i < 4; i++)
        #pragma unroll
        for (int j = 0; j < 4; j++)
            #pragma unroll
            for (int q = 0; q < 4; q++) acc[i][j][q] = 0.f;

    gemm_core(g_Xh, g_WhT[mode], row0, col0, gsm, acc);

    const int tid = threadIdx.x;
    const int wid = tid >> 5;
    const int lane = tid & 31;
    const int gid = lane >> 2;
    const int t = lane & 3;
    const int wm = wid & 1;
    const int wn = wid >> 1;

    if (mode == 2) {
        // V: transpose in smem, store [b,h,d,s] coalesced along s.
        __half* tile = (__half*)gsm;     // [128 cols][136] halves
        #pragma unroll
        for (int mt = 0; mt < 4; mt++)
            #pragma unroll
            for (int rr = 0; rr < 2; rr++) {
                const int rl = wm * 64 + mt * 16 + gid + rr * 8;
                #pragma unroll
                for (int nt = 0; nt < 4; nt++) {
                    const int cl = wn * 32 + nt * 8 + 2 * t;
                    tile[cl * 136 + rl]       = __float2half_rn(acc[mt][nt][rr * 2 + 0]);
                    tile[(cl + 1) * 136 + rl] = __float2half_rn(acc[mt][nt][rr * 2 + 1]);
                }
            }
        __syncthreads();
        const int bb = row0 >> 11;
        const int s0 = row0 & 2047;
        #pragma unroll
        for (int i = 0; i < 8; i++) {
            int idx = tid + i * 256;      // 2048 16B chunks
            int r = idx >> 4, c8 = idx & 15;
            int hh = (col0 >> 6) + (r >> 6);
            int dd = r & 63;
            float4 v = *(const float4*)&tile[r * 136 + c8 * 8];
            *(float4*)(g_Vth + (((size_t)bb * NH_ + hh) * HD_ + dd) * S_ + s0 + c8 * 8) = v;
        }
    } else {
        __half* dst = (mode == 0) ? g_Qah : g_Kah;
        const float scl = (mode == 0) ? 0.125f : 1.0f;   // fold softmax scale into Q
        #pragma unroll
        for (int mt = 0; mt < 4; mt++)
            #pragma unroll
            for (int rr = 0; rr < 2; rr++) {
                const int rg = row0 + wm * 64 + mt * 16 + gid + rr * 8;
                const int bb = rg >> 11;
                const int ss = rg & 2047;
                #pragma unroll
                for (int nt = 0; nt < 4; nt++) {
                    const int cg = col0 + wn * 32 + nt * 8 + 2 * t;
                    const int hh = cg >> 6, dd = cg & 63;
                    const size_t go = (((size_t)bb * NH_ + hh) * S_ + ss) * HD_ + dd;
                    *(uint32_t*)(dst + go) =
                        pack_h2(acc[mt][nt][rr * 2 + 0] * scl,
                                acc[mt][nt][rr * 2 + 1] * scl);
                }
            }
    }
}

// ---------------------------------------------------------------------------
// Output projection GEMM: out(fp32) = ctx(fp16) @ WO
// ---------------------------------------------------------------------------
__global__ __launch_bounds__(256, 2)
void gemm_o(float* __restrict__ out) {
    extern __shared__ char gsm[];
    const int row0 = blockIdx.y * TM;
    const int col0 = blockIdx.x * TN;

    float acc[4][4][4];
    #pragma unroll
    for (int i = 0; i < 4; i++)
        #pragma unroll
        for (int j = 0; j < 4; j++)
            #pragma unroll
            for (int q = 0; q < 4; q++) acc[i][j][q] = 0.f;

    gemm_core(g_Ch, g_WhT[3], row0, col0, gsm, acc);

    const int tid = threadIdx.x;
    const int wid = tid >> 5;
    const int lane = tid & 31;
    const int gid = lane >> 2;
    const int t = lane & 3;
    const int wm = wid & 1;
    const int wn = wid >> 1;

    #pragma unroll
    for (int mt = 0; mt < 4; mt++) {
        const int rg = row0 + wm * 64 + mt * 16 + gid;
        #pragma unroll
        for (int nt = 0; nt < 4; nt++) {
            const int cg = col0 + wn * 32 + nt * 8 + 2 * t;
            *(float2*)(out + (size_t)rg * H_ + cg) =
                make_float2(acc[mt][nt][0], acc[mt][nt][1]);
            *(float2*)(out + (size_t)(rg + 8) * H_ + cg) =
                make_float2(acc[mt][nt][2], acc[mt][nt][3]);
        }
    }
}

// ---------------------------------------------------------------------------
// Flash attention, fp16 MMA + x4 ldmatrix + hoisted Q fragments.
// CTA = 128 q-rows, 2 CTAs/SM. Q pre-scaled; mask = additive float bias.
// ---------------------------------------------------------------------------
#define FROWB 144
#define SQH   0
#define SKV0  18432              // 128*144
#define KVBUF 18432              // Kh + Vh, each 64*144=9216
#define OKH   0
#define OVH   9216
#define SMK   55296              // bias floats: 2 bufs x 64 x 4B
#define FSMEM 55808              // x2 CTAs = 111.6KB/SM

__global__ __launch_bounds__(256, 2)
void flash_mma(const int* __restrict__ mask) {
    extern __shared__ char sm[];
    const float NEG = __int_as_float(0xff800000u);
    const int tid = threadIdx.x;
    const int wid = tid >> 5;
    const int lane = tid & 31;
    const int li = lane & 7;
    const int gid = lane >> 2;
    const int t = lane & 3;
    const int q0 = blockIdx.x * 128;
    const int h = blockIdx.y;
    const int b = blockIdx.z;
    const size_t bh = (size_t)b * NH_ + h;

    const __half* Qhp = g_Qah + (bh * S_ + q0) * HD_;
    const __half* Khp = g_Kah + bh * S_ * HD_;
    const __half* Vtp = g_Vth + bh * HD_ * S_;
    const int* mkp = mask + b * S_;

    const uint32_t sb = smem_u32(sm);
    const int m0r = wid * 16;

    // ldmatrix lane-address components
    const uint32_t q_lbase = sb + SQH
        + (uint32_t)((m0r + li + ((lane & 8) ? 8 : 0)) * FROWB)
        + ((lane & 16) ? 16u : 0u);
    // K/V x4: lanes 0-15 -> n-tile 2j; lanes 16-31 -> n-tile 2j+1
    const uint32_t kv4_loff = (uint32_t)((li + ((lane & 16) ? 8 : 0)) * FROWB)
                              + ((lane & 8) ? 16u : 0u);

    // Load Q (128 x 64 halves)           -> group A
    #pragma unroll
    for (int i = 0; i < 4; i++) {
        int idx = tid + i * 256;          // 1024 chunks
        int r = idx >> 3, c = idx & 7;
        cp16(sb + SQH + r * FROWB + c * 16, Qhp + (size_t)r * HD_ + c * 8);
    }
    cp_commit();

    auto load_kv = [&](int tile, int buf) {
        const int kv0 = tile * 64;
        const uint32_t kb = sb + SKV0 + buf * KVBUF;
        #pragma unroll
        for (int i = 0; i < 2; i++) {
            int idx = tid + i * 256;
            int r = idx >> 3, c = idx & 7;
            uint32_t so = r * FROWB + c * 16;
            cp16(kb + OKH + so, Khp + (size_t)(kv0 + r) * HD_ + c * 8);
            cp16(kb + OVH + so, Vtp + (size_t)r * S_ + kv0 + c * 8);
        }
        if (tid < 64) {
            float bias = (mkp[kv0 + tid] == 0) ? NEG : 0.f;
            *(float*)(sm + SMK + buf * 256 + tid * 4) = bias;
        }
        cp_commit();
    };

    load_kv(0, 0);                        // -> group B

    // Wait for Q (group A retired; kv0 may stay in flight), then hoist Q frags.
    asm volatile("cp.async.wait_group 1;" ::: "memory");
    __syncthreads();
    uint32_t qf[4][4];
    #pragma unroll
    for (int ks = 0; ks < 4; ks++)
        ldsm_x4(qf[ks], q_lbase + ks * 32);

    float mr0 = NEG, mr1 = NEG, lr0 = 0.f, lr1 = 0.f;
    float ctx[8][4];
    #pragma unroll
    for (int nt = 0; nt < 8; nt++)
        #pragma unroll
        for (int e = 0; e < 4; e++) ctx[nt][e] = 0.f;

    for (int tile = 0; tile < 32; tile++) {
        const int buf = tile & 1;
        if (tile + 1 < 32) {
            load_kv(tile + 1, buf ^ 1);
            asm volatile("cp.async.wait_group 1;" ::: "memory");
        } else {
            asm volatile("cp.async.wait_group 0;" ::: "memory");
        }
        __syncthreads();

        const uint32_t kb = sb + SKV0 + buf * KVBUF;
        const char* mkb = sm + SMK + buf * 256;

        // --- S = QK^T (Q pre-scaled; hoisted fragments) ---
        float sc[8][4];
        #pragma unroll
        for (int nt = 0; nt < 8; nt++)
            #pragma unroll
            for (int e = 0; e < 4; e++) sc[nt][e] = 0.f;

        #pragma unroll
        for (int ks = 0; ks < 4; ks++) {
            #pragma unroll
            for (int j = 0; j < 4; j++) {
                uint32_t tmp[4];
                ldsm_x4(tmp, kb + OKH + kv4_loff + j * 2304 + ks * 32);
                mma16816(sc[2 * j],     qf[ks], tmp);
                mma16816(sc[2 * j + 1], qf[ks], tmp + 2);
            }
        }

        // --- mask bias; row max; online softmax ---
        float tm0 = NEG, tm1 = NEG;
        #pragma unroll
        for (int nt = 0; nt < 8; nt++) {
            float2 bbv = *(const float2*)(mkb + (nt * 8 + 2 * t) * 4);
            sc[nt][0] += bbv.x;
            sc[nt][1] += bbv.y;
            sc[nt][2] += bbv.x;
            sc[nt][3] += bbv.y;
            tm0 = fmaxf(tm0, fmaxf(sc[nt][0], sc[nt][1]));
            tm1 = fmaxf(tm1, fmaxf(sc[nt][2], sc[nt][3]));
        }
        tm0 = fmaxf(tm0, __shfl_xor_sync(0xffffffffu, tm0, 1));
        tm0 = fmaxf(tm0, __shfl_xor_sync(0xffffffffu, tm0, 2));
        tm1 = fmaxf(tm1, __shfl_xor_sync(0xffffffffu, tm1, 1));
        tm1 = fmaxf(tm1, __shfl_xor_sync(0xffffffffu, tm1, 2));

        float mn0 = fmaxf(mr0, tm0), mn1 = fmaxf(mr1, tm1);
        float al0 = (mn0 == NEG) ? 1.f : __expf(mr0 - mn0);
        float al1 = (mn1 == NEG) ? 1.f : __expf(mr1 - mn1);

        float rs0 = 0.f, rs1 = 0.f;
        #pragma unroll
        for (int nt = 0; nt < 8; nt++) {
            float p;
            p = __expf(sc[nt][0] - mn0); sc[nt][0] = p; rs0 += p;
            p = __expf(sc[nt][1] - mn0); sc[nt][1] = p; rs0 += p;
            p = __expf(sc[nt][2] - mn1); sc[nt][2] = p; rs1 += p;
            p = __expf(sc[nt][3] - mn1); sc[nt][3] = p; rs1 += p;
        }
        rs0 += __shfl_xor_sync(0xffffffffu, rs0, 1);
        rs0 += __shfl_xor_sync(0xffffffffu, rs0, 2);
        rs1 += __shfl_xor_sync(0xffffffffu, rs1, 1);
        rs1 += __shfl_xor_sync(0xffffffffu, rs1, 2);
        lr0 = lr0 * al0 + rs0;
        lr1 = lr1 * al1 + rs1;
        mr0 = mn0; mr1 = mn1;

        #pragma unroll
        for (int nt = 0; nt < 8; nt++) {
            ctx[nt][0] *= al0; ctx[nt][1] *= al0;
            ctx[nt][2] *= al1; ctx[nt][3] *= al1;
        }

        // --- ctx += P @ Vt (x4 V fragments) ---
        #pragma unroll
        for (int kk = 0; kk < 4; kk++) {
            uint32_t aph[4];
            aph[0] = pack_h2(sc[2 * kk][0],     sc[2 * kk][1]);
            aph[1] = pack_h2(sc[2 * kk][2],     sc[2 * kk][3]);
            aph[2] = pack_h2(sc[2 * kk + 1][0], sc[2 * kk + 1][1]);
            aph[3] = pack_h2(sc[2 * kk + 1][2], sc[2 * kk + 1][3]);
            #pragma unroll
            for (int j = 0; j < 4; j++) {
                uint32_t tmp[4];
                ldsm_x4(tmp, kb + OVH + kv4_loff + j * 2304 + kk * 32);
                mma16816(ctx[2 * j],     aph, tmp);
                mma16816(ctx[2 * j + 1], aph, tmp + 2);
            }
        }
        __syncthreads();
    }

    // Epilogue: normalize, fp16, store [s,H]
    const float inv0 = 1.f / lr0;
    const float inv1 = 1.f / lr1;
    const int r0 = b * S_ + q0 + m0r + gid;
    #pragma unroll
    for (int nt = 0; nt < 8; nt++) {
        const int d0 = h * HD_ + nt * 8 + 2 * t;
        *(uint32_t*)(g_Ch + (size_t)r0 * H_ + d0) =
            pack_h2(ctx[nt][0] * inv0, ctx[nt][1] * inv0);
        *(uint32_t*)(g_Ch + (size_t)(r0 + 8) * H_ + d0) =
            pack_h2(ctx[nt][2] * inv1, ctx[nt][3] * inv1);
    }
}

// ---------------------------------------------------------------------------
// X convert: fp32 -> fp16
// ---------------------------------------------------------------------------
__global__ void xcvt(const float* __restrict__ A, int n4) {
    int i = blockIdx.x * blockDim.x + threadIdx.x;
    if (i >= n4) return;
    float4 v = ((const float4*)A)[i];
    ((uint32_t*)g_Xh)[2 * i + 0] = pack_h2(v.x, v.y);
    ((uint32_t*)g_Xh)[2 * i + 1] = pack_h2(v.z, v.w);
}

// ---------------------------------------------------------------------------
// Weight convert+transpose: W[K,N] fp32 -> WhT[z][N,K] fp16
// ---------------------------------------------------------------------------
__global__ void wcvt_t(const float* __restrict__ W0, const float* __restrict__ W1,
                       const float* __restrict__ W2, const float* __restrict__ W3) {
    __shared__ float tbuf[32][33];
    const int z = blockIdx.z;
    const float* W = (z == 0) ? W0 : (z == 1) ? W1 : (z == 2) ? W2 : W3;
    __half* O = g_WhT[z];
    int n0 = blockIdx.x * 32, k0 = blockIdx.y * 32;
    int x = threadIdx.x, y0 = threadIdx.y;
    #pragma unroll
    for (int i = y0; i < 32; i += 8)
        tbuf[i][x] = W[(size_t)(k0 + i) * H_ + n0 + x];
    __syncthreads();
    #pragma unroll
    for (int i = y0; i < 32; i += 8)
        O[(size_t)(n0 + i) * H_ + k0 + x] = __float2half_rn(tbuf[x][i]);
}

// ---------------------------------------------------------------------------
// Launch (flash_mma stays launch #4 -> ncu capture window)
// ---------------------------------------------------------------------------
extern "C" void kernel_launch(void* const* d_in, const int* in_sizes, int n_in,
                              void* d_out, int out_size) {
    const float* X    = (const float*)d_in[0];
    const int*   mask = (const int*)d_in[1];
    const float* WQ   = (const float*)d_in[2];
    const float* WK   = (const float*)d_in[3];
    const float* WV   = (const float*)d_in[4];
    const float* WO   = (const float*)d_in[5];
    float* out = (float*)d_out;

    cudaFuncSetAttribute(gemm_qkv, cudaFuncAttributeMaxDynamicSharedMemorySize, GSMEM);
    cudaFuncSetAttribute(gemm_o,   cudaFuncAttributeMaxDynamicSharedMemorySize, GSMEM);
    cudaFuncSetAttribute(flash_mma, cudaFuncAttributeMaxDynamicSharedMemorySize, FSMEM);

    // 1. Prep
    xcvt<<<(M_ * H_ / 4 + 255) / 256, 256>>>(X, M_ * H_ / 4);
    // 2.
    wcvt_t<<<dim3(32, 32, 4), dim3(32, 8)>>>(WQ, WK, WV, WO);
    // 3. QKV projections (fused; Q pre-scaled; V-transpose in epilogue)
    gemm_qkv<<<dim3(H_ / TN, M_ / TM, 3), 256, GSMEM>>>();
    // 4. Attention (128 q-rows/CTA, 2 CTAs/SM, x4 ldmatrix, hoisted Q)
    flash_mma<<<dim3(S_ / 128, NH_, B_), 256, FSMEM>>>(mask);
    // 5. Output projection
    gemm_o<<<dim3(H_ / TN, M_ / TM), 256, GSMEM>>>(out);
}

// round 13
// speedup vs baseline: 2.8733x; 1.0205x over previous
#include <cuda_runtime.h>
#include <cuda_fp16.h>
#include <cstdint>

// Problem constants
#define B_  2
#define S_  2048
#define H_  1024
#define NH_ 16
#define HD_ 64
#define M_  (B_*S_)   // 4096 rows

// ---------------------------------------------------------------------------
// Scratch (allocation-free: device globals)
// ---------------------------------------------------------------------------
__device__ __half g_Xh[(size_t)M_ * H_];
__device__ __half g_WhT[4][(size_t)H_ * H_];     // transposed [N,K] fp16
__device__ __half g_Qah[(size_t)M_ * H_];        // [b,h,s,d] fp16 (pre-scaled 0.125)
__device__ __half g_Kah[(size_t)M_ * H_];        // [b,h,s,d] fp16
__device__ __half g_Vth[(size_t)M_ * H_];        // [b,h,d,s] fp16
__device__ __half g_Ch [(size_t)M_ * H_];        // context [s,H] fp16

// ---------------------------------------------------------------------------
// Helpers
// ---------------------------------------------------------------------------
__device__ __forceinline__ uint32_t smem_u32(const void* p) {
    uint32_t a;
    asm("{ .reg .u64 t; cvta.to.shared.u64 t, %1; cvt.u32.u64 %0, t; }"
        : "=r"(a) : "l"(p));
    return a;
}
__device__ __forceinline__ void cp16(uint32_t s, const void* g) {
    asm volatile("cp.async.cg.shared.global [%0], [%1], 16;" :: "r"(s), "l"(g));
}
__device__ __forceinline__ void cp_commit() {
    asm volatile("cp.async.commit_group;" ::: "memory");
}
__device__ __forceinline__ void mma16816(float* c, const uint32_t* a, const uint32_t* b) {
    asm volatile(
        "mma.sync.aligned.m16n8k16.row.col.f32.f16.f16.f32 "
        "{%0,%1,%2,%3}, {%4,%5,%6,%7}, {%8,%9}, {%0,%1,%2,%3};"
        : "+f"(c[0]), "+f"(c[1]), "+f"(c[2]), "+f"(c[3])
        : "r"(a[0]), "r"(a[1]), "r"(a[2]), "r"(a[3]), "r"(b[0]), "r"(b[1]));
}
__device__ __forceinline__ void ldsm_x4(uint32_t* r, uint32_t addr) {
    asm volatile("ldmatrix.sync.aligned.m8n8.x4.shared.b16 {%0,%1,%2,%3}, [%4];"
        : "=r"(r[0]), "=r"(r[1]), "=r"(r[2]), "=r"(r[3]) : "r"(addr));
}
__device__ __forceinline__ uint32_t pack_h2(float f0, float f1) {
    __half2 hh = __halves2half2(__float2half_rn(f0), __float2half_rn(f1));
    return *(uint32_t*)&hh;
}

// ---------------------------------------------------------------------------
// GEMM core: plain fp16.  acc = A@B^T   (B stored [N,K]); x4 ldmatrix only.
// CTA tile 128x128, K-chunk 32, 3-stage cp.async, 8 warps (2x4), warp 64x32.
// [verified round 12]
// ---------------------------------------------------------------------------
#define TM 128
#define TN 128
#define TK 32
#define PITCH 40                 // halves per smem row (80 B)
#define OAH 0
#define OBH 10240                // 128*80
#define STG 20480
#define NSTAGE 3
#define GSMEM (STG * NSTAGE)     // 61440 -> 2 CTAs/SM
#define NCH (H_ / TK)            // 32

__device__ __forceinline__ void gemm_core(
    const __half* __restrict__ Ah, const __half* __restrict__ Bh,
    int row0, int col0, char* gsm, float acc[4][4][4]) {

    const int tid = threadIdx.x;
    const int wid = tid >> 5;
    const int lane = tid & 31;
    const int li = lane & 7;
    const int wm = wid & 1;
    const int wn = wid >> 1;
    const uint32_t sb = smem_u32(gsm);

    const uint32_t aoff = (uint32_t)((wm * 64 + li + ((lane & 8) ? 8 : 0)) * 80)
                          + ((lane & 16) ? 16u : 0u);
    const uint32_t boff4 = (uint32_t)((wn * 32 + li + ((lane & 16) ? 8 : 0)) * 80)
                           + ((lane & 8) ? 16u : 0u);

    auto load_chunk = [&](int c, int s) {
        const int k0 = c * TK;
        const uint32_t base = sb + s * STG;
        #pragma unroll
        for (int i = 0; i < 2; i++) {               // A: 512 chunks
            int idx = tid + i * 256;
            int r = idx >> 2, c16 = idx & 3;
            uint32_t so = r * 80 + c16 * 16;
            cp16(base + OAH + so, Ah + (size_t)(row0 + r) * H_ + k0 + c16 * 8);
        }
        #pragma unroll
        for (int i = 0; i < 2; i++) {               // B: 512 chunks
            int idx = tid + i * 256;
            int r = idx >> 2, c16 = idx & 3;
            uint32_t so = r * 80 + c16 * 16;
            cp16(base + OBH + so, Bh + (size_t)(col0 + r) * H_ + k0 + c16 * 8);
        }
        cp_commit();
    };

    load_chunk(0, 0);
    load_chunk(1, 1);

    for (int c = 0; c < NCH; c++) {
        const int s = c % NSTAGE;
        if (c + 2 < NCH) load_chunk(c + 2, (c + 2) % NSTAGE);
        else cp_commit();                           // keep group count uniform
        asm volatile("cp.async.wait_group 2;" ::: "memory");
        __syncthreads();

        const uint32_t stb = sb + s * STG;

        #pragma unroll
        for (int ks = 0; ks < 2; ks++) {
            uint32_t ah[4][4], bh[4][2];
            #pragma unroll
            for (int mt = 0; mt < 4; mt++)
                ldsm_x4(ah[mt], stb + OAH + aoff + mt * 1280 + ks * 32);
            #pragma unroll
            for (int j = 0; j < 2; j++) {
                uint32_t tmp[4];
                ldsm_x4(tmp, stb + OBH + boff4 + j * 1280 + ks * 32);
                bh[2 * j][0] = tmp[0]; bh[2 * j][1] = tmp[1];
                bh[2 * j + 1][0] = tmp[2]; bh[2 * j + 1][1] = tmp[3];
            }
            #pragma unroll
            for (int mt = 0; mt < 4; mt++)
                #pragma unroll
                for (int nt = 0; nt < 4; nt++)
                    mma16816(acc[mt][nt], ah[mt], bh[nt]);
        }
        __syncthreads();
    }
}

// ---------------------------------------------------------------------------
// QKV projection GEMM: grid.z selects Q/K/V. Q pre-scaled by 0.125 (exact).
// Q,K -> [b,h,s,d]; V -> fused transpose to [b,h,d,s] via smem bounce.
// ---------------------------------------------------------------------------
__global__ __launch_bounds__(256, 2)
void gemm_qkv() {
    extern __shared__ char gsm[];
    const int mode = blockIdx.z;
    const int row0 = blockIdx.y * TM;
    const int col0 = blockIdx.x * TN;

    float acc[4][4][4];
    #pragma unroll
    for (int i = 0; i < 4; i++)
        #pragma unroll
        for (int j = 0; j < 4; j++)
            #pragma unroll
            for (int q = 0; q < 4; q++) acc[i][j][q] = 0.f;

    gemm_core(g_Xh, g_WhT[mode], row0, col0, gsm, acc);

    const int tid = threadIdx.x;
    const int wid = tid >> 5;
    const int lane = tid & 31;
    const int gid = lane >> 2;
    const int t = lane & 3;
    const int wm = wid & 1;
    const int wn = wid >> 1;

    if (mode == 2) {
        __half* tile = (__half*)gsm;     // [128 cols][136] halves
        #pragma unroll
        for (int mt = 0; mt < 4; mt++)
            #pragma unroll
            for (int rr = 0; rr < 2; rr++) {
                const int rl = wm * 64 + mt * 16 + gid + rr * 8;
                #pragma unroll
                for (int nt = 0; nt < 4; nt++) {
                    const int cl = wn * 32 + nt * 8 + 2 * t;
                    tile[cl * 136 + rl]       = __float2half_rn(acc[mt][nt][rr * 2 + 0]);
                    tile[(cl + 1) * 136 + rl] = __float2half_rn(acc[mt][nt][rr * 2 + 1]);
                }
            }
        __syncthreads();
        const int bb = row0 >> 11;
        const int s0 = row0 & 2047;
        #pragma unroll
        for (int i = 0; i < 8; i++) {
            int idx = tid + i * 256;
            int r = idx >> 4, c8 = idx & 15;
            int hh = (col0 >> 6) + (r >> 6);
            int dd = r & 63;
            float4 v = *(const float4*)&tile[r * 136 + c8 * 8];
            *(float4*)(g_Vth + (((size_t)bb * NH_ + hh) * HD_ + dd) * S_ + s0 + c8 * 8) = v;
        }
    } else {
        __half* dst = (mode == 0) ? g_Qah : g_Kah;
        const float scl = (mode == 0) ? 0.125f : 1.0f;
        #pragma unroll
        for (int mt = 0; mt < 4; mt++)
            #pragma unroll
            for (int rr = 0; rr < 2; rr++) {
                const int rg = row0 + wm * 64 + mt * 16 + gid + rr * 8;
                const int bb = rg >> 11;
                const int ss = rg & 2047;
                #pragma unroll
                for (int nt = 0; nt < 4; nt++) {
                    const int cg = col0 + wn * 32 + nt * 8 + 2 * t;
                    const int hh = cg >> 6, dd = cg & 63;
                    const size_t go = (((size_t)bb * NH_ + hh) * S_ + ss) * HD_ + dd;
                    *(uint32_t*)(dst + go) =
                        pack_h2(acc[mt][nt][rr * 2 + 0] * scl,
                                acc[mt][nt][rr * 2 + 1] * scl);
                }
            }
    }
}

// ---------------------------------------------------------------------------
// Output projection GEMM: out(fp32) = ctx(fp16) @ WO
// ---------------------------------------------------------------------------
__global__ __launch_bounds__(256, 2)
void gemm_o(float* __restrict__ out) {
    extern __shared__ char gsm[];
    const int row0 = blockIdx.y * TM;
    const int col0 = blockIdx.x * TN;

    float acc[4][4][4];
    #pragma unroll
    for (int i = 0; i < 4; i++)
        #pragma unroll
        for (int j = 0; j < 4; j++)
            #pragma unroll
            for (int q = 0; q < 4; q++) acc[i][j][q] = 0.f;

    gemm_core(g_Ch, g_WhT[3], row0, col0, gsm, acc);

    const int tid = threadIdx.x;
    const int wid = tid >> 5;
    const int lane = tid & 31;
    const int gid = lane >> 2;
    const int t = lane & 3;
    const int wm = wid & 1;
    const int wn = wid >> 1;

    #pragma unroll
    for (int mt = 0; mt < 4; mt++) {
        const int rg = row0 + wm * 64 + mt * 16 + gid;
        #pragma unroll
        for (int nt = 0; nt < 4; nt++) {
            const int cg = col0 + wn * 32 + nt * 8 + 2 * t;
            *(float2*)(out + (size_t)rg * H_ + cg) =
                make_float2(acc[mt][nt][0], acc[mt][nt][1]);
            *(float2*)(out + (size_t)(rg + 8) * H_ + cg) =
                make_float2(acc[mt][nt][2], acc[mt][nt][3]);
        }
    }
}

// ---------------------------------------------------------------------------
// Flash attention: 256 q-rows/CTA, 2 m-tiles per warp — each K/V ldmatrix
// feeds 4 MMAs (halves smem bytes per MMA). Lean softmax, hoisted Q frags.
// ---------------------------------------------------------------------------
#define FROWB 144
#define SQH   0
#define SKV0  36864              // 256*144
#define KVBUF 18432              // Kh + Vh, each 64*144=9216
#define OKH   0
#define OVH   9216
#define SMK   73728              // bias floats: 2 bufs x 64 x 4B
#define FSMEM 74240

__global__ __launch_bounds__(256, 1)
void flash_mma(const int* __restrict__ mask) {
    extern __shared__ char sm[];
    const float NEG = __int_as_float(0xff800000u);
    const int tid = threadIdx.x;
    const int wid = tid >> 5;
    const int lane = tid & 31;
    const int li = lane & 7;
    const int gid = lane >> 2;
    const int t = lane & 3;
    const int q0 = blockIdx.x * 256;
    const int h = blockIdx.y;
    const int b = blockIdx.z;
    const size_t bh = (size_t)b * NH_ + h;

    const __half* Qhp = g_Qah + (bh * S_ + q0) * HD_;
    const __half* Khp = g_Kah + bh * S_ * HD_;
    const __half* Vtp = g_Vth + bh * HD_ * S_;
    const int* mkp = mask + b * S_;

    const uint32_t sb = smem_u32(sm);
    const int m0r = wid * 32;

    // ldmatrix lane-address components
    const uint32_t q_lrow = (uint32_t)((li + ((lane & 8) ? 8 : 0)) * FROWB)
                            + ((lane & 16) ? 16u : 0u);
    const uint32_t kv4_loff = (uint32_t)((li + ((lane & 16) ? 8 : 0)) * FROWB)
                              + ((lane & 8) ? 16u : 0u);

    // Load Q (256 x 64 halves)           -> group A
    #pragma unroll
    for (int i = 0; i < 8; i++) {
        int idx = tid + i * 256;          // 2048 chunks
        int r = idx >> 3, c = idx & 7;
        cp16(sb + SQH + r * FROWB + c * 16, Qhp + (size_t)r * HD_ + c * 8);
    }
    cp_commit();

    auto load_kv = [&](int tile, int buf) {
        const int kv0 = tile * 64;
        const uint32_t kb = sb + SKV0 + buf * KVBUF;
        #pragma unroll
        for (int i = 0; i < 2; i++) {
            int idx = tid + i * 256;
            int r = idx >> 3, c = idx & 7;
            uint32_t so = r * FROWB + c * 16;
            cp16(kb + OKH + so, Khp + (size_t)(kv0 + r) * HD_ + c * 8);
            cp16(kb + OVH + so, Vtp + (size_t)r * S_ + kv0 + c * 8);
        }
        if (tid < 64) {
            float bias = (mkp[kv0 + tid] == 0) ? NEG : 0.f;
            *(float*)(sm + SMK + buf * 256 + tid * 4) = bias;
        }
        cp_commit();
    };

    load_kv(0, 0);                        // -> group B

    // Wait for Q (group A retired), hoist both m-tiles' Q fragments.
    asm volatile("cp.async.wait_group 1;" ::: "memory");
    __syncthreads();
    uint32_t qf[2][4][4];
    #pragma unroll
    for (int mi = 0; mi < 2; mi++)
        #pragma unroll
        for (int ks = 0; ks < 4; ks++)
            ldsm_x4(qf[mi][ks],
                    sb + SQH + (uint32_t)((m0r + mi * 16) * FROWB) + q_lrow + ks * 32);

    float mr[2][2], lr[2][2];
    #pragma unroll
    for (int mi = 0; mi < 2; mi++) {
        mr[mi][0] = NEG; mr[mi][1] = NEG;
        lr[mi][0] = 0.f; lr[mi][1] = 0.f;
    }
    float ctx[2][8][4];
    #pragma unroll
    for (int mi = 0; mi < 2; mi++)
        #pragma unroll
        for (int nt = 0; nt < 8; nt++)
            #pragma unroll
            for (int e = 0; e < 4; e++) ctx[mi][nt][e] = 0.f;

    for (int tile = 0; tile < 32; tile++) {
        const int buf = tile & 1;
        if (tile + 1 < 32) {
            load_kv(tile + 1, buf ^ 1);
            asm volatile("cp.async.wait_group 1;" ::: "memory");
        } else {
            asm volatile("cp.async.wait_group 0;" ::: "memory");
        }
        __syncthreads();

        const uint32_t kb = sb + SKV0 + buf * KVBUF;
        const char* mkb = sm + SMK + buf * 256;

        // --- S = QK^T : each K ldsm feeds 4 MMAs (2 n-tiles x 2 m-tiles) ---
        float sc[2][8][4];
        #pragma unroll
        for (int mi = 0; mi < 2; mi++)
            #pragma unroll
            for (int nt = 0; nt < 8; nt++)
                #pragma unroll
                for (int e = 0; e < 4; e++) sc[mi][nt][e] = 0.f;

        #pragma unroll
        for (int ks = 0; ks < 4; ks++) {
            #pragma unroll
            for (int j = 0; j < 4; j++) {
                uint32_t tmp[4];
                ldsm_x4(tmp, kb + OKH + kv4_loff + j * 2304 + ks * 32);
                #pragma unroll
                for (int mi = 0; mi < 2; mi++) {
                    mma16816(sc[mi][2 * j],     qf[mi][ks], tmp);
                    mma16816(sc[mi][2 * j + 1], qf[mi][ks], tmp + 2);
                }
            }
        }

        // --- mask bias; row max; online softmax (per m-tile) ---
        #pragma unroll
        for (int mi = 0; mi < 2; mi++) {
            float tm0 = NEG, tm1 = NEG;
            #pragma unroll
            for (int nt = 0; nt < 8; nt++) {
                float2 bbv = *(const float2*)(mkb + (nt * 8 + 2 * t) * 4);
                sc[mi][nt][0] += bbv.x;
                sc[mi][nt][1] += bbv.y;
                sc[mi][nt][2] += bbv.x;
                sc[mi][nt][3] += bbv.y;
                tm0 = fmaxf(tm0, fmaxf(sc[mi][nt][0], sc[mi][nt][1]));
                tm1 = fmaxf(tm1, fmaxf(sc[mi][nt][2], sc[mi][nt][3]));
            }
            tm0 = fmaxf(tm0, __shfl_xor_sync(0xffffffffu, tm0, 1));
            tm0 = fmaxf(tm0, __shfl_xor_sync(0xffffffffu, tm0, 2));
            tm1 = fmaxf(tm1, __shfl_xor_sync(0xffffffffu, tm1, 1));
            tm1 = fmaxf(tm1, __shfl_xor_sync(0xffffffffu, tm1, 2));

            float mn0 = fmaxf(mr[mi][0], tm0), mn1 = fmaxf(mr[mi][1], tm1);
            float al0 = (mn0 == NEG) ? 1.f : __expf(mr[mi][0] - mn0);
            float al1 = (mn1 == NEG) ? 1.f : __expf(mr[mi][1] - mn1);

            float rs0 = 0.f, rs1 = 0.f;
            #pragma unroll
            for (int nt = 0; nt < 8; nt++) {
                float p;
                p = __expf(sc[mi][nt][0] - mn0); sc[mi][nt][0] = p; rs0 += p;
                p = __expf(sc[mi][nt][1] - mn0); sc[mi][nt][1] = p; rs0 += p;
                p = __expf(sc[mi][nt][2] - mn1); sc[mi][nt][2] = p; rs1 += p;
                p = __expf(sc[mi][nt][3] - mn1); sc[mi][nt][3] = p; rs1 += p;
            }
            rs0 += __shfl_xor_sync(0xffffffffu, rs0, 1);
            rs0 += __shfl_xor_sync(0xffffffffu, rs0, 2);
            rs1 += __shfl_xor_sync(0xffffffffu, rs1, 1);
            rs1 += __shfl_xor_sync(0xffffffffu, rs1, 2);
            lr[mi][0] = lr[mi][0] * al0 + rs0;
            lr[mi][1] = lr[mi][1] * al1 + rs1;
            mr[mi][0] = mn0; mr[mi][1] = mn1;

            #pragma unroll
            for (int nt = 0; nt < 8; nt++) {
                ctx[mi][nt][0] *= al0; ctx[mi][nt][1] *= al0;
                ctx[mi][nt][2] *= al1; ctx[mi][nt][3] *= al1;
            }
        }

        // --- ctx += P @ Vt : each V ldsm feeds 4 MMAs ---
        #pragma unroll
        for (int kk = 0; kk < 4; kk++) {
            uint32_t aph[2][4];
            #pragma unroll
            for (int mi = 0; mi < 2; mi++) {
                aph[mi][0] = pack_h2(sc[mi][2 * kk][0],     sc[mi][2 * kk][1]);
                aph[mi][1] = pack_h2(sc[mi][2 * kk][2],     sc[mi][2 * kk][3]);
                aph[mi][2] = pack_h2(sc[mi][2 * kk + 1][0], sc[mi][2 * kk + 1][1]);
                aph[mi][3] = pack_h2(sc[mi][2 * kk + 1][2], sc[mi][2 * kk + 1][3]);
            }
            #pragma unroll
            for (int j = 0; j < 4; j++) {
                uint32_t tmp[4];
                ldsm_x4(tmp, kb + OVH + kv4_loff + j * 2304 + kk * 32);
                #pragma unroll
                for (int mi = 0; mi < 2; mi++) {
                    mma16816(ctx[mi][2 * j],     aph[mi], tmp);
                    mma16816(ctx[mi][2 * j + 1], aph[mi], tmp + 2);
                }
            }
        }
        __syncthreads();
    }

    // Epilogue: normalize, fp16, store [s,H]
    #pragma unroll
    for (int mi = 0; mi < 2; mi++) {
        const float inv0 = 1.f / lr[mi][0];
        const float inv1 = 1.f / lr[mi][1];
        const int r0 = b * S_ + q0 + m0r + mi * 16 + gid;
        #pragma unroll
        for (int nt = 0; nt < 8; nt++) {
            const int d0 = h * HD_ + nt * 8 + 2 * t;
            *(uint32_t*)(g_Ch + (size_t)r0 * H_ + d0) =
                pack_h2(ctx[mi][nt][0] * inv0, ctx[mi][nt][1] * inv0);
            *(uint32_t*)(g_Ch + (size_t)(r0 + 8) * H_ + d0) =
                pack_h2(ctx[mi][nt][2] * inv1, ctx[mi][nt][3] * inv1);
        }
    }
}

// ---------------------------------------------------------------------------
// X convert: fp32 -> fp16
// ---------------------------------------------------------------------------
__global__ void xcvt(const float* __restrict__ A, int n4) {
    int i = blockIdx.x * blockDim.x + threadIdx.x;
    if (i >= n4) return;
    float4 v = ((const float4*)A)[i];
    ((uint32_t*)g_Xh)[2 * i + 0] = pack_h2(v.x, v.y);
    ((uint32_t*)g_Xh)[2 * i + 1] = pack_h2(v.z, v.w);
}

// ---------------------------------------------------------------------------
// Weight convert+transpose: W[K,N] fp32 -> WhT[z][N,K] fp16
// ---------------------------------------------------------------------------
__global__ void wcvt_t(const float* __restrict__ W0, const float* __restrict__ W1,
                       const float* __restrict__ W2, const float* __restrict__ W3) {
    __shared__ float tbuf[32][33];
    const int z = blockIdx.z;
    const float* W = (z == 0) ? W0 : (z == 1) ? W1 : (z == 2) ? W2 : W3;
    __half* O = g_WhT[z];
    int n0 = blockIdx.x * 32, k0 = blockIdx.y * 32;
    int x = threadIdx.x, y0 = threadIdx.y;
    #pragma unroll
    for (int i = y0; i < 32; i += 8)
        tbuf[i][x] = W[(size_t)(k0 + i) * H_ + n0 + x];
    __syncthreads();
    #pragma unroll
    for (int i = y0; i < 32; i += 8)
        O[(size_t)(n0 + i) * H_ + k0 + x] = __float2half_rn(tbuf[x][i]);
}

// ---------------------------------------------------------------------------
// Launch (flash_mma stays launch #4 -> ncu capture window)
// ---------------------------------------------------------------------------
extern "C" void kernel_launch(void* const* d_in, const int* in_sizes, int n_in,
                              void* d_out, int out_size) {
    const float* X    = (const float*)d_in[0];
    const int*   mask = (const int*)d_in[1];
    const float* WQ   = (const float*)d_in[2];
    const float* WK   = (const float*)d_in[3];
    const float* WV   = (const float*)d_in[4];
    const float* WO   = (const float*)d_in[5];
    float* out = (float*)d_out;

    cudaFuncSetAttribute(gemm_qkv, cudaFuncAttributeMaxDynamicSharedMemorySize, GSMEM);
    cudaFuncSetAttribute(gemm_o,   cudaFuncAttributeMaxDynamicSharedMemorySize, GSMEM);
    cudaFuncSetAttribute(flash_mma, cudaFuncAttributeMaxDynamicSharedMemorySize, FSMEM);

    // 1. Prep
    xcvt<<<(M_ * H_ / 4 + 255) / 256, 256>>>(X, M_ * H_ / 4);
    // 2.
    wcvt_t<<<dim3(32, 32, 4), dim3(32, 8)>>>(WQ, WK, WV, WO);
    // 3. QKV projections (fused; Q pre-scaled; V-transpose in epilogue)
    gemm_qkv<<<dim3(H_ / TN, M_ / TM, 3), 256, GSMEM>>>();
    // 4. Attention (256 q-rows/CTA, 2 m-tiles/warp, shared K/V fragments)
    flash_mma<<<dim3(S_ / 256, NH_, B_), 256, FSMEM>>>(mask);
    // 5. Output projection
    gemm_o<<<dim3(H_ / TN, M_ / TM), 256, GSMEM>>>(out);
}

// round 14
// speedup vs baseline: 3.0684x; 1.0679x over previous
#include <cuda_runtime.h>
#include <cuda_fp16.h>
#include <cstdint>

// Problem constants
#define B_  2
#define S_  2048
#define H_  1024
#define NH_ 16
#define HD_ 64
#define M_  (B_*S_)   // 4096 rows

// ---------------------------------------------------------------------------
// Scratch (allocation-free: device globals)
// ---------------------------------------------------------------------------
__device__ __half g_Xh[(size_t)M_ * H_];
__device__ __half g_WhT[4][(size_t)H_ * H_];     // transposed [N,K] fp16
__device__ __half g_Qah[(size_t)M_ * H_];        // [b,h,s,d] fp16 (pre-scaled 0.125*log2e)
__device__ __half g_Kah[(size_t)M_ * H_];        // [b,h,s,d] fp16
__device__ __half g_Vth[(size_t)M_ * H_];        // [b,h,d,s] fp16
__device__ __half g_Ch [(size_t)M_ * H_];        // context [s,H] fp16

// ---------------------------------------------------------------------------
// Helpers
// ---------------------------------------------------------------------------
__device__ __forceinline__ uint32_t smem_u32(const void* p) {
    uint32_t a;
    asm("{ .reg .u64 t; cvta.to.shared.u64 t, %1; cvt.u32.u64 %0, t; }"
        : "=r"(a) : "l"(p));
    return a;
}
__device__ __forceinline__ void cp16(uint32_t s, const void* g) {
    asm volatile("cp.async.cg.shared.global [%0], [%1], 16;" :: "r"(s), "l"(g));
}
__device__ __forceinline__ void cp_commit() {
    asm volatile("cp.async.commit_group;" ::: "memory");
}
__device__ __forceinline__ void mma16816(float* c, const uint32_t* a, const uint32_t* b) {
    asm volatile(
        "mma.sync.aligned.m16n8k16.row.col.f32.f16.f16.f32 "
        "{%0,%1,%2,%3}, {%4,%5,%6,%7}, {%8,%9}, {%0,%1,%2,%3};"
        : "+f"(c[0]), "+f"(c[1]), "+f"(c[2]), "+f"(c[3])
        : "r"(a[0]), "r"(a[1]), "r"(a[2]), "r"(a[3]), "r"(b[0]), "r"(b[1]));
}
__device__ __forceinline__ void ldsm_x4(uint32_t* r, uint32_t addr) {
    asm volatile("ldmatrix.sync.aligned.m8n8.x4.shared.b16 {%0,%1,%2,%3}, [%4];"
        : "=r"(r[0]), "=r"(r[1]), "=r"(r[2]), "=r"(r[3]) : "r"(addr));
}
__device__ __forceinline__ void ldsm_x2(uint32_t* r, uint32_t addr) {
    asm volatile("ldmatrix.sync.aligned.m8n8.x2.shared.b16 {%0,%1}, [%2];"
        : "=r"(r[0]), "=r"(r[1]) : "r"(addr));
}
__device__ __forceinline__ uint32_t pack_h2(float f0, float f1) {
    __half2 hh = __halves2half2(__float2half_rn(f0), __float2half_rn(f1));
    return *(uint32_t*)&hh;
}
// p = exp2(f16x2(s) + bias2) — result is the MMA-ready half2 fragment
__device__ __forceinline__ uint32_t exp2_pair(float s0, float s1, uint32_t bias2) {
    __half2 hv = __floats2half2_rn(s0, s1);
    hv = __hadd2(hv, *(__half2*)&bias2);
    hv = h2exp2(hv);
    return *(uint32_t*)&hv;
}

// ---------------------------------------------------------------------------
// GEMM core (verified round 12/13): plain fp16, acc = A@B^T, x4 ldmatrix.
// CTA tile 128x128, K-chunk 32, 3-stage cp.async, 8 warps (2x4), warp 64x32.
// ---------------------------------------------------------------------------
#define TM 128
#define TN 128
#define TK 32
#define PITCH 40
#define OAH 0
#define OBH 10240
#define STG 20480
#define NSTAGE 3
#define GSMEM (STG * NSTAGE)
#define NCH (H_ / TK)

__device__ __forceinline__ void gemm_core(
    const __half* __restrict__ Ah, const __half* __restrict__ Bh,
    int row0, int col0, char* gsm, float acc[4][4][4]) {

    const int tid = threadIdx.x;
    const int wid = tid >> 5;
    const int lane = tid & 31;
    const int li = lane & 7;
    const int wm = wid & 1;
    const int wn = wid >> 1;
    const uint32_t sb = smem_u32(gsm);

    const uint32_t aoff = (uint32_t)((wm * 64 + li + ((lane & 8) ? 8 : 0)) * 80)
                          + ((lane & 16) ? 16u : 0u);
    const uint32_t boff4 = (uint32_t)((wn * 32 + li + ((lane & 16) ? 8 : 0)) * 80)
                           + ((lane & 8) ? 16u : 0u);

    auto load_chunk = [&](int c, int s) {
        const int k0 = c * TK;
        const uint32_t base = sb + s * STG;
        #pragma unroll
        for (int i = 0; i < 2; i++) {
            int idx = tid + i * 256;
            int r = idx >> 2, c16 = idx & 3;
            uint32_t so = r * 80 + c16 * 16;
            cp16(base + OAH + so, Ah + (size_t)(row0 + r) * H_ + k0 + c16 * 8);
        }
        #pragma unroll
        for (int i = 0; i < 2; i++) {
            int idx = tid + i * 256;
            int r = idx >> 2, c16 = idx & 3;
            uint32_t so = r * 80 + c16 * 16;
            cp16(base + OBH + so, Bh + (size_t)(col0 + r) * H_ + k0 + c16 * 8);
        }
        cp_commit();
    };

    load_chunk(0, 0);
    load_chunk(1, 1);

    for (int c = 0; c < NCH; c++) {
        const int s = c % NSTAGE;
        if (c + 2 < NCH) load_chunk(c + 2, (c + 2) % NSTAGE);
        else cp_commit();
        asm volatile("cp.async.wait_group 2;" ::: "memory");
        __syncthreads();

        const uint32_t stb = sb + s * STG;

        #pragma unroll
        for (int ks = 0; ks < 2; ks++) {
            uint32_t ah[4][4], bh[4][2];
            #pragma unroll
            for (int mt = 0; mt < 4; mt++)
                ldsm_x4(ah[mt], stb + OAH + aoff + mt * 1280 + ks * 32);
            #pragma unroll
            for (int j = 0; j < 2; j++) {
                uint32_t tmp[4];
                ldsm_x4(tmp, stb + OBH + boff4 + j * 1280 + ks * 32);
                bh[2 * j][0] = tmp[0]; bh[2 * j][1] = tmp[1];
                bh[2 * j + 1][0] = tmp[2]; bh[2 * j + 1][1] = tmp[3];
            }
            #pragma unroll
            for (int mt = 0; mt < 4; mt++)
                #pragma unroll
                for (int nt = 0; nt < 4; nt++)
                    mma16816(acc[mt][nt], ah[mt], bh[nt]);
        }
        __syncthreads();
    }
}

// ---------------------------------------------------------------------------
// QKV projection GEMM. Q pre-scaled by 0.125*log2(e) (exp2-domain scores).
// ---------------------------------------------------------------------------
__global__ __launch_bounds__(256, 2)
void gemm_qkv() {
    extern __shared__ char gsm[];
    const int mode = blockIdx.z;
    const int row0 = blockIdx.y * TM;
    const int col0 = blockIdx.x * TN;

    float acc[4][4][4];
    #pragma unroll
    for (int i = 0; i < 4; i++)
        #pragma unroll
        for (int j = 0; j < 4; j++)
            #pragma unroll
            for (int q = 0; q < 4; q++) acc[i][j][q] = 0.f;

    gemm_core(g_Xh, g_WhT[mode], row0, col0, gsm, acc);

    const int tid = threadIdx.x;
    const int wid = tid >> 5;
    const int lane = tid & 31;
    const int gid = lane >> 2;
    const int t = lane & 3;
    const int wm = wid & 1;
    const int wn = wid >> 1;

    if (mode == 2) {
        __half* tile = (__half*)gsm;     // [128 cols][136] halves
        #pragma unroll
        for (int mt = 0; mt < 4; mt++)
            #pragma unroll
            for (int rr = 0; rr < 2; rr++) {
                const int rl = wm * 64 + mt * 16 + gid + rr * 8;
                #pragma unroll
                for (int nt = 0; nt < 4; nt++) {
                    const int cl = wn * 32 + nt * 8 + 2 * t;
                    tile[cl * 136 + rl]       = __float2half_rn(acc[mt][nt][rr * 2 + 0]);
                    tile[(cl + 1) * 136 + rl] = __float2half_rn(acc[mt][nt][rr * 2 + 1]);
                }
            }
        __syncthreads();
        const int bb = row0 >> 11;
        const int s0 = row0 & 2047;
        #pragma unroll
        for (int i = 0; i < 8; i++) {
            int idx = tid + i * 256;
            int r = idx >> 4, c8 = idx & 15;
            int hh = (col0 >> 6) + (r >> 6);
            int dd = r & 63;
            float4 v = *(const float4*)&tile[r * 136 + c8 * 8];
            *(float4*)(g_Vth + (((size_t)bb * NH_ + hh) * HD_ + dd) * S_ + s0 + c8 * 8) = v;
        }
    } else {
        __half* dst = (mode == 0) ? g_Qah : g_Kah;
        const float scl = (mode == 0) ? 0.1803368801111244f : 1.0f;  // 0.125*log2(e)
        #pragma unroll
        for (int mt = 0; mt < 4; mt++)
            #pragma unroll
            for (int rr = 0; rr < 2; rr++) {
                const int rg = row0 + wm * 64 + mt * 16 + gid + rr * 8;
                const int bb = rg >> 11;
                const int ss = rg & 2047;
                #pragma unroll
                for (int nt = 0; nt < 4; nt++) {
                    const int cg = col0 + wn * 32 + nt * 8 + 2 * t;
                    const int hh = cg >> 6, dd = cg & 63;
                    const size_t go = (((size_t)bb * NH_ + hh) * S_ + ss) * HD_ + dd;
                    *(uint32_t*)(dst + go) =
                        pack_h2(acc[mt][nt][rr * 2 + 0] * scl,
                                acc[mt][nt][rr * 2 + 1] * scl);
                }
            }
    }
}

// ---------------------------------------------------------------------------
// Output projection GEMM: out(fp32) = ctx(fp16) @ WO
// ---------------------------------------------------------------------------
__global__ __launch_bounds__(256, 2)
void gemm_o(float* __restrict__ out) {
    extern __shared__ char gsm[];
    const int row0 = blockIdx.y * TM;
    const int col0 = blockIdx.x * TN;

    float acc[4][4][4];
    #pragma unroll
    for (int i = 0; i < 4; i++)
        #pragma unroll
        for (int j = 0; j < 4; j++)
            #pragma unroll
            for (int q = 0; q < 4; q++) acc[i][j][q] = 0.f;

    gemm_core(g_Ch, g_WhT[3], row0, col0, gsm, acc);

    const int tid = threadIdx.x;
    const int wid = tid >> 5;
    const int lane = tid & 31;
    const int gid = lane >> 2;
    const int t = lane & 3;
    const int wm = wid & 1;
    const int wn = wid >> 1;

    #pragma unroll
    for (int mt = 0; mt < 4; mt++) {
        const int rg = row0 + wm * 64 + mt * 16 + gid;
        #pragma unroll
        for (int nt = 0; nt < 4; nt++) {
            const int cg = col0 + wn * 32 + nt * 8 + 2 * t;
            *(float2*)(out + (size_t)rg * H_ + cg) =
                make_float2(acc[mt][nt][0], acc[mt][nt][1]);
            *(float2*)(out + (size_t)(rg + 8) * H_ + cg) =
                make_float2(acc[mt][nt][2], acc[mt][nt][3]);
        }
    }
}

// ---------------------------------------------------------------------------
// Flash attention: 256 q-rows/CTA, exp2-domain no-max softmax in fp16x2,
// l accumulated by tensor core via ones-rows appended to V.
// ---------------------------------------------------------------------------
#define FROWB 144
#define SQH   0
#define SKV0  36864              // 256*144
#define OKH   0
#define OVH   9216               // K rows 0-63; V rows 0-63 + 8 extra (ones)
#define KVBUF 19584              // 9216 + 72*144
#define SMK   76032              // bias halves: 2 bufs x 64 x 2B
#define FSMEM 76288

__global__ __launch_bounds__(256, 1)
void flash_mma(const int* __restrict__ mask) {
    extern __shared__ char sm[];
    const int tid = threadIdx.x;
    const int wid = tid >> 5;
    const int lane = tid & 31;
    const int li = lane & 7;
    const int gid = lane >> 2;
    const int t = lane & 3;
    const int q0 = blockIdx.x * 256;
    const int h = blockIdx.y;
    const int b = blockIdx.z;
    const size_t bh = (size_t)b * NH_ + h;

    const __half* Qhp = g_Qah + (bh * S_ + q0) * HD_;
    const __half* Khp = g_Kah + bh * S_ * HD_;
    const __half* Vtp = g_Vth + bh * HD_ * S_;
    const int* mkp = mask + b * S_;

    const uint32_t sb = smem_u32(sm);
    const int m0r = wid * 32;

    const uint32_t q_lrow = (uint32_t)((li + ((lane & 8) ? 8 : 0)) * FROWB)
                            + ((lane & 16) ? 16u : 0u);
    const uint32_t kv4_loff = (uint32_t)((li + ((lane & 16) ? 8 : 0)) * FROWB)
                              + ((lane & 8) ? 16u : 0u);

    // Load Q (256 x 64 halves)           -> group A
    #pragma unroll
    for (int i = 0; i < 8; i++) {
        int idx = tid + i * 256;
        int r = idx >> 3, c = idx & 7;
        cp16(sb + SQH + r * FROWB + c * 16, Qhp + (size_t)r * HD_ + c * 8);
    }
    cp_commit();

    // Init ones-rows of V tile (buf 0 only; never overwritten by cp.async):
    // row 64 = 1.0 (l-reduction), rows 65-71 = 0.
    for (int idx = tid; idx < 8 * 36; idx += 256) {
        int r = idx / 36, w = idx % 36;
        uint32_t val = (r == 0) ? 0x3C003C00u : 0u;
        *(uint32_t*)(sm + SKV0 + OVH + (64 + r) * FROWB + w * 4) = val;
    }

    auto load_kv = [&](int tile, int buf) {
        const int kv0 = tile * 64;
        const uint32_t kb = sb + SKV0 + buf * KVBUF;
        #pragma unroll
        for (int i = 0; i < 2; i++) {
            int idx = tid + i * 256;
            int r = idx >> 3, c = idx & 7;
            uint32_t so = r * FROWB + c * 16;
            cp16(kb + OKH + so, Khp + (size_t)(kv0 + r) * HD_ + c * 8);
            cp16(kb + OVH + so, Vtp + (size_t)r * S_ + kv0 + c * 8);
        }
        if (tid < 64) {
            __half bias = (mkp[kv0 + tid] == 0) ? __ushort_as_half(0xFC00u)
                                                : __ushort_as_half(0u);
            *(__half*)(sm + SMK + buf * 128 + tid * 2) = bias;
        }
        cp_commit();
    };

    load_kv(0, 0);                        // -> group B

    // Wait for Q (group A retired), hoist Q fragments + ones B-fragment.
    asm volatile("cp.async.wait_group 1;" ::: "memory");
    __syncthreads();
    uint32_t qf[2][4][4];
    #pragma unroll
    for (int mi = 0; mi < 2; mi++)
        #pragma unroll
        for (int ks = 0; ks < 4; ks++)
            ldsm_x4(qf[mi][ks],
                    sb + SQH + (uint32_t)((m0r + mi * 16) * FROWB) + q_lrow + ks * 32);
    uint32_t b_ones[2];
    ldsm_x2(b_ones, sb + SKV0 + OVH + (uint32_t)((64 + li) * FROWB)
                    + ((lane & 8) ? 16u : 0u));

    float ctx[2][8][4];
    float lacc[2][4];
    #pragma unroll
    for (int mi = 0; mi < 2; mi++) {
        #pragma unroll
        for (int nt = 0; nt < 8; nt++)
            #pragma unroll
            for (int e = 0; e < 4; e++) ctx[mi][nt][e] = 0.f;
        #pragma unroll
        for (int e = 0; e < 4; e++) lacc[mi][e] = 0.f;
    }

    for (int tile = 0; tile < 32; tile++) {
        const int buf = tile & 1;
        if (tile + 1 < 32) {
            load_kv(tile + 1, buf ^ 1);
            asm volatile("cp.async.wait_group 1;" ::: "memory");
        } else {
            asm volatile("cp.async.wait_group 0;" ::: "memory");
        }
        __syncthreads();

        const uint32_t kb = sb + SKV0 + buf * KVBUF;
        const char* mkb = sm + SMK + buf * 128;

        // --- S = QK^T (exp2 domain, pre-scaled) ---
        float sc[2][8][4];
        #pragma unroll
        for (int mi = 0; mi < 2; mi++)
            #pragma unroll
            for (int nt = 0; nt < 8; nt++)
                #pragma unroll
                for (int e = 0; e < 4; e++) sc[mi][nt][e] = 0.f;

        #pragma unroll
        for (int ks = 0; ks < 4; ks++) {
            #pragma unroll
            for (int j = 0; j < 4; j++) {
                uint32_t tmp[4];
                ldsm_x4(tmp, kb + OKH + kv4_loff + j * 2304 + ks * 32);
                #pragma unroll
                for (int mi = 0; mi < 2; mi++) {
                    mma16816(sc[mi][2 * j],     qf[mi][ks], tmp);
                    mma16816(sc[mi][2 * j + 1], qf[mi][ks], tmp + 2);
                }
            }
        }

        // --- p = exp2(h2(s) + bias) : MMA-ready half2 fragments ---
        uint32_t p2[2][8][2];
        #pragma unroll
        for (int nt = 0; nt < 8; nt++) {
            uint32_t bias2 = *(const uint32_t*)(mkb + (nt * 8 + 2 * t) * 2);
            #pragma unroll
            for (int mi = 0; mi < 2; mi++) {
                p2[mi][nt][0] = exp2_pair(sc[mi][nt][0], sc[mi][nt][1], bias2);
                p2[mi][nt][1] = exp2_pair(sc[mi][nt][2], sc[mi][nt][3], bias2);
            }
        }

        // --- ctx += P @ Vt ; lacc += P @ 1 (tensor-core row sums) ---
        #pragma unroll
        for (int kk = 0; kk < 4; kk++) {
            uint32_t aph[2][4];
            #pragma unroll
            for (int mi = 0; mi < 2; mi++) {
                aph[mi][0] = p2[mi][2 * kk][0];
                aph[mi][1] = p2[mi][2 * kk][1];
                aph[mi][2] = p2[mi][2 * kk + 1][0];
                aph[mi][3] = p2[mi][2 * kk + 1][1];
            }
            #pragma unroll
            for (int j = 0; j < 4; j++) {
                uint32_t tmp[4];
                ldsm_x4(tmp, kb + OVH + kv4_loff + j * 2304 + kk * 32);
                #pragma unroll
                for (int mi = 0; mi < 2; mi++) {
                    mma16816(ctx[mi][2 * j],     aph[mi], tmp);
                    mma16816(ctx[mi][2 * j + 1], aph[mi], tmp + 2);
                }
            }
            #pragma unroll
            for (int mi = 0; mi < 2; mi++)
                mma16816(lacc[mi], aph[mi], b_ones);
        }
        __syncthreads();
    }

    // Epilogue: l lives at n=64 -> lane t=0 of each quad; broadcast, normalize.
    const int qbase = (lane >> 2) << 2;
    #pragma unroll
    for (int mi = 0; mi < 2; mi++) {
        const float l0 = __shfl_sync(0xffffffffu, lacc[mi][0], qbase);
        const float l1 = __shfl_sync(0xffffffffu, lacc[mi][2], qbase);
        const float inv0 = 1.f / l0;
        const float inv1 = 1.f / l1;
        const int r0 = b * S_ + q0 + m0r + mi * 16 + gid;
        #pragma unroll
        for (int nt = 0; nt < 8; nt++) {
            const int d0 = h * HD_ + nt * 8 + 2 * t;
            *(uint32_t*)(g_Ch + (size_t)r0 * H_ + d0) =
                pack_h2(ctx[mi][nt][0] * inv0, ctx[mi][nt][1] * inv0);
            *(uint32_t*)(g_Ch + (size_t)(r0 + 8) * H_ + d0) =
                pack_h2(ctx[mi][nt][2] * inv1, ctx[mi][nt][3] * inv1);
        }
    }
}

// ---------------------------------------------------------------------------
// X convert: fp32 -> fp16
// ---------------------------------------------------------------------------
__global__ void xcvt(const float* __restrict__ A, int n4) {
    int i = blockIdx.x * blockDim.x + threadIdx.x;
    if (i >= n4) return;
    float4 v = ((const float4*)A)[i];
    ((uint32_t*)g_Xh)[2 * i + 0] = pack_h2(v.x, v.y);
    ((uint32_t*)g_Xh)[2 * i + 1] = pack_h2(v.z, v.w);
}

// ---------------------------------------------------------------------------
// Weight convert+transpose: W[K,N] fp32 -> WhT[z][N,K] fp16
// ---------------------------------------------------------------------------
__global__ void wcvt_t(const float* __restrict__ W0, const float* __restrict__ W1,
                       const float* __restrict__ W2, const float* __restrict__ W3) {
    __shared__ float tbuf[32][33];
    const int z = blockIdx.z;
    const float* W = (z == 0) ? W0 : (z == 1) ? W1 : (z == 2) ? W2 : W3;
    __half* O = g_WhT[z];
    int n0 = blockIdx.x * 32, k0 = blockIdx.y * 32;
    int x = threadIdx.x, y0 = threadIdx.y;
    #pragma unroll
    for (int i = y0; i < 32; i += 8)
        tbuf[i][x] = W[(size_t)(k0 + i) * H_ + n0 + x];
    __syncthreads();
    #pragma unroll
    for (int i = y0; i < 32; i += 8)
        O[(size_t)(n0 + i) * H_ + k0 + x] = __float2half_rn(tbuf[x][i]);
}

// ---------------------------------------------------------------------------
// Launch (flash_mma stays launch #4 -> ncu capture window)
// ---------------------------------------------------------------------------
extern "C" void kernel_launch(void* const* d_in, const int* in_sizes, int n_in,
                              void* d_out, int out_size) {
    const float* X    = (const float*)d_in[0];
    const int*   mask = (const int*)d_in[1];
    const float* WQ   = (const float*)d_in[2];
    const float* WK   = (const float*)d_in[3];
    const float* WV   = (const float*)d_in[4];
    const float* WO   = (const float*)d_in[5];
    float* out = (float*)d_out;

    cudaFuncSetAttribute(gemm_qkv, cudaFuncAttributeMaxDynamicSharedMemorySize, GSMEM);
    cudaFuncSetAttribute(gemm_o,   cudaFuncAttributeMaxDynamicSharedMemorySize, GSMEM);
    cudaFuncSetAttribute(flash_mma, cudaFuncAttributeMaxDynamicSharedMemorySize, FSMEM);

    // 1. Prep
    xcvt<<<(M_ * H_ / 4 + 255) / 256, 256>>>(X, M_ * H_ / 4);
    // 2.
    wcvt_t<<<dim3(32, 32, 4), dim3(32, 8)>>>(WQ, WK, WV, WO);
    // 3. QKV projections (Q pre-scaled into exp2 domain)
    gemm_qkv<<<dim3(H_ / TN, M_ / TM, 3), 256, GSMEM>>>();
    // 4. Attention (no-max exp2 softmax, fp16x2 MUFU, tensor-core l)
    flash_mma<<<dim3(S_ / 256, NH_, B_), 256, FSMEM>>>(mask);
    // 5. Output projection
    gemm_o<<<dim3(H_ / TN, M_ / TM), 256, GSMEM>>>(out);
}

// round 15
// speedup vs baseline: 3.1151x; 1.0152x over previous
#include <cuda_runtime.h>
#include <cuda_fp16.h>
#include <cstdint>

// Problem constants
#define B_  2
#define S_  2048
#define H_  1024
#define NH_ 16
#define HD_ 64
#define M_  (B_*S_)   // 4096 rows

// ---------------------------------------------------------------------------
// Scratch (allocation-free: device globals)
// ---------------------------------------------------------------------------
__device__ __half g_Xh[(size_t)M_ * H_];
__device__ __half g_WhT[4][(size_t)H_ * H_];     // transposed [N,K] fp16
__device__ __half g_Qah[(size_t)M_ * H_];        // [b,h,s,d] fp16 (pre-scaled 0.125*log2e)
__device__ __half g_Kah[(size_t)M_ * H_];        // [b,h,s,d] fp16
__device__ __half g_Vth[(size_t)M_ * H_];        // [b,h,d,s] fp16
__device__ __half g_Ch [(size_t)M_ * H_];        // context [s,H] fp16

// ---------------------------------------------------------------------------
// Helpers
// ---------------------------------------------------------------------------
__device__ __forceinline__ uint32_t smem_u32(const void* p) {
    uint32_t a;
    asm("{ .reg .u64 t; cvta.to.shared.u64 t, %1; cvt.u32.u64 %0, t; }"
        : "=r"(a) : "l"(p));
    return a;
}
__device__ __forceinline__ void cp16(uint32_t s, const void* g) {
    asm volatile("cp.async.cg.shared.global [%0], [%1], 16;" :: "r"(s), "l"(g));
}
__device__ __forceinline__ void cp_commit() {
    asm volatile("cp.async.commit_group;" ::: "memory");
}
__device__ __forceinline__ void mma16816(float* c, const uint32_t* a, const uint32_t* b) {
    asm volatile(
        "mma.sync.aligned.m16n8k16.row.col.f32.f16.f16.f32 "
        "{%0,%1,%2,%3}, {%4,%5,%6,%7}, {%8,%9}, {%0,%1,%2,%3};"
        : "+f"(c[0]), "+f"(c[1]), "+f"(c[2]), "+f"(c[3])
        : "r"(a[0]), "r"(a[1]), "r"(a[2]), "r"(a[3]), "r"(b[0]), "r"(b[1]));
}
__device__ __forceinline__ void ldsm_x4(uint32_t* r, uint32_t addr) {
    asm volatile("ldmatrix.sync.aligned.m8n8.x4.shared.b16 {%0,%1,%2,%3}, [%4];"
        : "=r"(r[0]), "=r"(r[1]), "=r"(r[2]), "=r"(r[3]) : "r"(addr));
}
__device__ __forceinline__ void ldsm_x2(uint32_t* r, uint32_t addr) {
    asm volatile("ldmatrix.sync.aligned.m8n8.x2.shared.b16 {%0,%1}, [%2];"
        : "=r"(r[0]), "=r"(r[1]) : "r"(addr));
}
__device__ __forceinline__ uint32_t pack_h2(float f0, float f1) {
    __half2 hh = __halves2half2(__float2half_rn(f0), __float2half_rn(f1));
    return *(uint32_t*)&hh;
}
// p = exp2(f16x2(s) + bias2) — result is the MMA-ready half2 fragment
__device__ __forceinline__ uint32_t exp2_pair(float s0, float s1, uint32_t bias2) {
    __half2 hv = __floats2half2_rn(s0, s1);
    hv = __hadd2(hv, *(__half2*)&bias2);
    hv = h2exp2(hv);
    return *(uint32_t*)&hv;
}

// ---------------------------------------------------------------------------
// GEMM core (verified round 12/13): plain fp16, acc = A@B^T, x4 ldmatrix.
// CTA tile 128x128, K-chunk 32, 3-stage cp.async, 8 warps (2x4), warp 64x32.
// ---------------------------------------------------------------------------
#define TM 128
#define TN 128
#define TK 32
#define PITCH 40
#define OAH 0
#define OBH 10240
#define STG 20480
#define NSTAGE 3
#define GSMEM (STG * NSTAGE)
#define NCH (H_ / TK)

__device__ __forceinline__ void gemm_core(
    const __half* __restrict__ Ah, const __half* __restrict__ Bh,
    int row0, int col0, char* gsm, float acc[4][4][4]) {

    const int tid = threadIdx.x;
    const int wid = tid >> 5;
    const int lane = tid & 31;
    const int li = lane & 7;
    const int wm = wid & 1;
    const int wn = wid >> 1;
    const uint32_t sb = smem_u32(gsm);

    const uint32_t aoff = (uint32_t)((wm * 64 + li + ((lane & 8) ? 8 : 0)) * 80)
                          + ((lane & 16) ? 16u : 0u);
    const uint32_t boff4 = (uint32_t)((wn * 32 + li + ((lane & 16) ? 8 : 0)) * 80)
                           + ((lane & 8) ? 16u : 0u);

    auto load_chunk = [&](int c, int s) {
        const int k0 = c * TK;
        const uint32_t base = sb + s * STG;
        #pragma unroll
        for (int i = 0; i < 2; i++) {
            int idx = tid + i * 256;
            int r = idx >> 2, c16 = idx & 3;
            uint32_t so = r * 80 + c16 * 16;
            cp16(base + OAH + so, Ah + (size_t)(row0 + r) * H_ + k0 + c16 * 8);
        }
        #pragma unroll
        for (int i = 0; i < 2; i++) {
            int idx = tid + i * 256;
            int r = idx >> 2, c16 = idx & 3;
            uint32_t so = r * 80 + c16 * 16;
            cp16(base + OBH + so, Bh + (size_t)(col0 + r) * H_ + k0 + c16 * 8);
        }
        cp_commit();
    };

    load_chunk(0, 0);
    load_chunk(1, 1);

    for (int c = 0; c < NCH; c++) {
        const int s = c % NSTAGE;
        if (c + 2 < NCH) load_chunk(c + 2, (c + 2) % NSTAGE);
        else cp_commit();
        asm volatile("cp.async.wait_group 2;" ::: "memory");
        __syncthreads();

        const uint32_t stb = sb + s * STG;

        #pragma unroll
        for (int ks = 0; ks < 2; ks++) {
            uint32_t ah[4][4], bh[4][2];
            #pragma unroll
            for (int mt = 0; mt < 4; mt++)
                ldsm_x4(ah[mt], stb + OAH + aoff + mt * 1280 + ks * 32);
            #pragma unroll
            for (int j = 0; j < 2; j++) {
                uint32_t tmp[4];
                ldsm_x4(tmp, stb + OBH + boff4 + j * 1280 + ks * 32);
                bh[2 * j][0] = tmp[0]; bh[2 * j][1] = tmp[1];
                bh[2 * j + 1][0] = tmp[2]; bh[2 * j + 1][1] = tmp[3];
            }
            #pragma unroll
            for (int mt = 0; mt < 4; mt++)
                #pragma unroll
                for (int nt = 0; nt < 4; nt++)
                    mma16816(acc[mt][nt], ah[mt], bh[nt]);
        }
        __syncthreads();
    }
}

// ---------------------------------------------------------------------------
// QKV projection GEMM. Q pre-scaled by 0.125*log2(e) (exp2-domain scores).
// ---------------------------------------------------------------------------
__global__ __launch_bounds__(256, 2)
void gemm_qkv() {
    extern __shared__ char gsm[];
    const int mode = blockIdx.z;
    const int row0 = blockIdx.y * TM;
    const int col0 = blockIdx.x * TN;

    float acc[4][4][4];
    #pragma unroll
    for (int i = 0; i < 4; i++)
        #pragma unroll
        for (int j = 0; j < 4; j++)
            #pragma unroll
            for (int q = 0; q < 4; q++) acc[i][j][q] = 0.f;

    gemm_core(g_Xh, g_WhT[mode], row0, col0, gsm, acc);

    const int tid = threadIdx.x;
    const int wid = tid >> 5;
    const int lane = tid & 31;
    const int gid = lane >> 2;
    const int t = lane & 3;
    const int wm = wid & 1;
    const int wn = wid >> 1;

    if (mode == 2) {
        __half* tile = (__half*)gsm;     // [128 cols][136] halves
        #pragma unroll
        for (int mt = 0; mt < 4; mt++)
            #pragma unroll
            for (int rr = 0; rr < 2; rr++) {
                const int rl = wm * 64 + mt * 16 + gid + rr * 8;
                #pragma unroll
                for (int nt = 0; nt < 4; nt++) {
                    const int cl = wn * 32 + nt * 8 + 2 * t;
                    tile[cl * 136 + rl]       = __float2half_rn(acc[mt][nt][rr * 2 + 0]);
                    tile[(cl + 1) * 136 + rl] = __float2half_rn(acc[mt][nt][rr * 2 + 1]);
                }
            }
        __syncthreads();
        const int bb = row0 >> 11;
        const int s0 = row0 & 2047;
        #pragma unroll
        for (int i = 0; i < 8; i++) {
            int idx = tid + i * 256;
            int r = idx >> 4, c8 = idx & 15;
            int hh = (col0 >> 6) + (r >> 6);
            int dd = r & 63;
            float4 v = *(const float4*)&tile[r * 136 + c8 * 8];
            *(float4*)(g_Vth + (((size_t)bb * NH_ + hh) * HD_ + dd) * S_ + s0 + c8 * 8) = v;
        }
    } else {
        __half* dst = (mode == 0) ? g_Qah : g_Kah;
        const float scl = (mode == 0) ? 0.1803368801111244f : 1.0f;  // 0.125*log2(e)
        #pragma unroll
        for (int mt = 0; mt < 4; mt++)
            #pragma unroll
            for (int rr = 0; rr < 2; rr++) {
                const int rg = row0 + wm * 64 + mt * 16 + gid + rr * 8;
                const int bb = rg >> 11;
                const int ss = rg & 2047;
                #pragma unroll
                for (int nt = 0; nt < 4; nt++) {
                    const int cg = col0 + wn * 32 + nt * 8 + 2 * t;
                    const int hh = cg >> 6, dd = cg & 63;
                    const size_t go = (((size_t)bb * NH_ + hh) * S_ + ss) * HD_ + dd;
                    *(uint32_t*)(dst + go) =
                        pack_h2(acc[mt][nt][rr * 2 + 0] * scl,
                                acc[mt][nt][rr * 2 + 1] * scl);
                }
            }
    }
}

// ---------------------------------------------------------------------------
// Output projection GEMM: out(fp32) = ctx(fp16) @ WO
// ---------------------------------------------------------------------------
__global__ __launch_bounds__(256, 2)
void gemm_o(float* __restrict__ out) {
    extern __shared__ char gsm[];
    const int row0 = blockIdx.y * TM;
    const int col0 = blockIdx.x * TN;

    float acc[4][4][4];
    #pragma unroll
    for (int i = 0; i < 4; i++)
        #pragma unroll
        for (int j = 0; j < 4; j++)
            #pragma unroll
            for (int q = 0; q < 4; q++) acc[i][j][q] = 0.f;

    gemm_core(g_Ch, g_WhT[3], row0, col0, gsm, acc);

    const int tid = threadIdx.x;
    const int wid = tid >> 5;
    const int lane = tid & 31;
    const int gid = lane >> 2;
    const int t = lane & 3;
    const int wm = wid & 1;
    const int wn = wid >> 1;

    #pragma unroll
    for (int mt = 0; mt < 4; mt++) {
        const int rg = row0 + wm * 64 + mt * 16 + gid;
        #pragma unroll
        for (int nt = 0; nt < 4; nt++) {
            const int cg = col0 + wn * 32 + nt * 8 + 2 * t;
            *(float2*)(out + (size_t)rg * H_ + cg) =
                make_float2(acc[mt][nt][0], acc[mt][nt][1]);
            *(float2*)(out + (size_t)(rg + 8) * H_ + cg) =
                make_float2(acc[mt][nt][2], acc[mt][nt][3]);
        }
    }
}

// ---------------------------------------------------------------------------
// Flash attention: 256 q-rows/CTA, exp2 no-max softmax, tensor-core l, and
// cross-tile software pipelining: QK(t+1) interleaved with exp2(t)+PV(t)
// so the tensor pipe has work during the MUFU phase. K double-buffered,
// V/bias triple-buffered; sc slots reused in place (exp2 frees, QK refills).
// ---------------------------------------------------------------------------
#define FROWB 144
#define SQH   0                  // Q: 256*144 = 36864
#define SK0   36864              // K bufs: 2 x 9216
#define SV0   55296              // V bufs: 3 x 9216
#define SONES 82944              // ones rows: 8*144
#define SMK   84096              // bias halves: 3 bufs x 128B
#define FSMEM 84480

__global__ __launch_bounds__(256, 1)
void flash_mma(const int* __restrict__ mask) {
    extern __shared__ char sm[];
    const int tid = threadIdx.x;
    const int wid = tid >> 5;
    const int lane = tid & 31;
    const int li = lane & 7;
    const int gid = lane >> 2;
    const int tq = lane & 3;
    const int q0 = blockIdx.x * 256;
    const int h = blockIdx.y;
    const int b = blockIdx.z;
    const size_t bh = (size_t)b * NH_ + h;

    const __half* Qhp = g_Qah + (bh * S_ + q0) * HD_;
    const __half* Khp = g_Kah + bh * S_ * HD_;
    const __half* Vtp = g_Vth + bh * HD_ * S_;
    const int* mkp = mask + b * S_;

    const uint32_t sb = smem_u32(sm);
    const int m0r = wid * 32;

    const uint32_t q_lrow = (uint32_t)((li + ((lane & 8) ? 8 : 0)) * FROWB)
                            + ((lane & 16) ? 16u : 0u);
    const uint32_t kv4_loff = (uint32_t)((li + ((lane & 16) ? 8 : 0)) * FROWB)
                              + ((lane & 8) ? 16u : 0u);

    // Q load                              -> group 0
    #pragma unroll
    for (int i = 0; i < 8; i++) {
        int idx = tid + i * 256;
        int r = idx >> 3, c = idx & 7;
        cp16(sb + SQH + r * FROWB + c * 16, Qhp + (size_t)r * HD_ + c * 8);
    }
    cp_commit();

    // ones region: row 0 = 1.0 halves, rows 1-7 = 0
    for (int idx = tid; idx < 8 * 36; idx += 256) {
        int r = idx / 36, w = idx % 36;
        *(uint32_t*)(sm + SONES + r * FROWB + w * 4) = (r == 0) ? 0x3C003C00u : 0u;
    }

    auto load_kv = [&](int tile) {
        const int kv0 = tile * 64;
        const uint32_t kbb = sb + SK0 + (tile & 1) * 9216;
        const uint32_t vbb = sb + SV0 + (tile % 3) * 9216;
        #pragma unroll
        for (int i = 0; i < 2; i++) {
            int idx = tid + i * 256;
            int r = idx >> 3, c = idx & 7;
            uint32_t so = r * FROWB + c * 16;
            cp16(kbb + so, Khp + (size_t)(kv0 + r) * HD_ + c * 8);
            cp16(vbb + so, Vtp + (size_t)r * S_ + kv0 + c * 8);
        }
        if (tid < 64) {
            __half bias = (mkp[kv0 + tid] == 0) ? __ushort_as_half(0xFC00u)
                                                : __ushort_as_half(0u);
            *(__half*)(sm + SMK + (tile % 3) * 128 + tid * 2) = bias;
        }
        cp_commit();
    };

    load_kv(0);                           // group 1
    load_kv(1);                           // group 2
    asm volatile("cp.async.wait_group 1;" ::: "memory");   // Q + load0 done
    __syncthreads();

    // Hoist Q fragments + ones B-fragment
    uint32_t qf[2][4][4];
    #pragma unroll
    for (int mi = 0; mi < 2; mi++)
        #pragma unroll
        for (int ks = 0; ks < 4; ks++)
            ldsm_x4(qf[mi][ks],
                    sb + SQH + (uint32_t)((m0r + mi * 16) * FROWB) + q_lrow + ks * 32);
    uint32_t b_ones[2];
    ldsm_x2(b_ones, sb + SONES + (uint32_t)(li * FROWB) + ((lane & 8) ? 16u : 0u));

    float sc[2][8][4], ctx[2][8][4], lacc[2][4];
    #pragma unroll
    for (int mi = 0; mi < 2; mi++) {
        #pragma unroll
        for (int nt = 0; nt < 8; nt++)
            #pragma unroll
            for (int e = 0; e < 4; e++) { sc[mi][nt][e] = 0.f; ctx[mi][nt][e] = 0.f; }
        #pragma unroll
        for (int e = 0; e < 4; e++) lacc[mi][e] = 0.f;
    }

    // QK(0) standalone (j = kk outer, ks inner)
    {
        const uint32_t kb0 = sb + SK0;
        #pragma unroll
        for (int kk = 0; kk < 4; kk++)
            #pragma unroll
            for (int ks = 0; ks < 4; ks++) {
                uint32_t tmp[4];
                ldsm_x4(tmp, kb0 + kv4_loff + kk * 2304 + ks * 32);
                #pragma unroll
                for (int mi = 0; mi < 2; mi++) {
                    mma16816(sc[mi][2 * kk],     qf[mi][ks], tmp);
                    mma16816(sc[mi][2 * kk + 1], qf[mi][ks], tmp + 2);
                }
            }
    }

    for (int tile = 0; tile < 32; tile++) {
        asm volatile("cp.async.wait_group 0;" ::: "memory");  // load(tile+1) done
        __syncthreads();
        if (tile + 2 < 32) load_kv(tile + 2);

        const uint32_t kbN = sb + SK0 + ((tile + 1) & 1) * 9216;  // K(t+1)
        const uint32_t vbC = sb + SV0 + (tile % 3) * 9216;        // V(t)
        const char* mkb = sm + SMK + (tile % 3) * 128;
        const bool do_qk = (tile < 31);

        #pragma unroll
        for (int kk = 0; kk < 4; kk++) {
            uint32_t bias_a = *(const uint32_t*)(mkb + ((2 * kk) * 8 + 2 * tq) * 2);
            uint32_t bias_b = *(const uint32_t*)(mkb + ((2 * kk + 1) * 8 + 2 * tq) * 2);
            uint32_t aph[2][4];
            #pragma unroll
            for (int mi = 0; mi < 2; mi++) {
                aph[mi][0] = exp2_pair(sc[mi][2 * kk][0],     sc[mi][2 * kk][1],     bias_a);
                aph[mi][1] = exp2_pair(sc[mi][2 * kk][2],     sc[mi][2 * kk][3],     bias_a);
                aph[mi][2] = exp2_pair(sc[mi][2 * kk + 1][0], sc[mi][2 * kk + 1][1], bias_b);
                aph[mi][3] = exp2_pair(sc[mi][2 * kk + 1][2], sc[mi][2 * kk + 1][3], bias_b);
            }
            // QK(t+1) for n-tiles 2kk,2kk+1 — refills the sc slots just freed
            if (do_qk) {
                #pragma unroll
                for (int mi = 0; mi < 2; mi++)
                    #pragma unroll
                    for (int e = 0; e < 4; e++) {
                        sc[mi][2 * kk][e] = 0.f;
                        sc[mi][2 * kk + 1][e] = 0.f;
                    }
                #pragma unroll
                for (int ks = 0; ks < 4; ks++) {
                    uint32_t tmp[4];
                    ldsm_x4(tmp, kbN + kv4_loff + kk * 2304 + ks * 32);
                    #pragma unroll
                    for (int mi = 0; mi < 2; mi++) {
                        mma16816(sc[mi][2 * kk],     qf[mi][ks], tmp);
                        mma16816(sc[mi][2 * kk + 1], qf[mi][ks], tmp + 2);
                    }
                }
            }
            // PV(t), k-chunk kk
            #pragma unroll
            for (int j = 0; j < 4; j++) {
                uint32_t tmp[4];
                ldsm_x4(tmp, vbC + kv4_loff + j * 2304 + kk * 32);
                #pragma unroll
                for (int mi = 0; mi < 2; mi++) {
                    mma16816(ctx[mi][2 * j],     aph[mi], tmp);
                    mma16816(ctx[mi][2 * j + 1], aph[mi], tmp + 2);
                }
            }
            #pragma unroll
            for (int mi = 0; mi < 2; mi++)
                mma16816(lacc[mi], aph[mi], b_ones);
        }
    }

    // Epilogue: l at n=64 -> lane tq==0 of each quad; broadcast, normalize.
    const int qbase = (lane >> 2) << 2;
    #pragma unroll
    for (int mi = 0; mi < 2; mi++) {
        const float l0 = __shfl_sync(0xffffffffu, lacc[mi][0], qbase);
        const float l1 = __shfl_sync(0xffffffffu, lacc[mi][2], qbase);
        const float inv0 = 1.f / l0;
        const float inv1 = 1.f / l1;
        const int r0 = b * S_ + q0 + m0r + mi * 16 + gid;
        #pragma unroll
        for (int nt = 0; nt < 8; nt++) {
            const int d0 = h * HD_ + nt * 8 + 2 * tq;
            *(uint32_t*)(g_Ch + (size_t)r0 * H_ + d0) =
                pack_h2(ctx[mi][nt][0] * inv0, ctx[mi][nt][1] * inv0);
            *(uint32_t*)(g_Ch + (size_t)(r0 + 8) * H_ + d0) =
                pack_h2(ctx[mi][nt][2] * inv1, ctx[mi][nt][3] * inv1);
        }
    }
}

// ---------------------------------------------------------------------------
// X convert: fp32 -> fp16
// ---------------------------------------------------------------------------
__global__ void xcvt(const float* __restrict__ A, int n4) {
    int i = blockIdx.x * blockDim.x + threadIdx.x;
    if (i >= n4) return;
    float4 v = ((const float4*)A)[i];
    ((uint32_t*)g_Xh)[2 * i + 0] = pack_h2(v.x, v.y);
    ((uint32_t*)g_Xh)[2 * i + 1] = pack_h2(v.z, v.w);
}

// ---------------------------------------------------------------------------
// Weight convert+transpose: W[K,N] fp32 -> WhT[z][N,K] fp16
// ---------------------------------------------------------------------------
__global__ void wcvt_t(const float* __restrict__ W0, const float* __restrict__ W1,
                       const float* __restrict__ W2, const float* __restrict__ W3) {
    __shared__ float tbuf[32][33];
    const int z = blockIdx.z;
    const float* W = (z == 0) ? W0 : (z == 1) ? W1 : (z == 2) ? W2 : W3;
    __half* O = g_WhT[z];
    int n0 = blockIdx.x * 32, k0 = blockIdx.y * 32;
    int x = threadIdx.x, y0 = threadIdx.y;
    #pragma unroll
    for (int i = y0; i < 32; i += 8)
        tbuf[i][x] = W[(size_t)(k0 + i) * H_ + n0 + x];
    __syncthreads();
    #pragma unroll
    for (int i = y0; i < 32; i += 8)
        O[(size_t)(n0 + i) * H_ + k0 + x] = __float2half_rn(tbuf[x][i]);
}

// ---------------------------------------------------------------------------
// Launch (flash_mma stays launch #4 -> ncu capture window)
// ---------------------------------------------------------------------------
extern "C" void kernel_launch(void* const* d_in, const int* in_sizes, int n_in,
                              void* d_out, int out_size) {
    const float* X    = (const float*)d_in[0];
    const int*   mask = (const int*)d_in[1];
    const float* WQ   = (const float*)d_in[2];
    const float* WK   = (const float*)d_in[3];
    const float* WV   = (const float*)d_in[4];
    const float* WO   = (const float*)d_in[5];
    float* out = (float*)d_out;

    cudaFuncSetAttribute(gemm_qkv, cudaFuncAttributeMaxDynamicSharedMemorySize, GSMEM);
    cudaFuncSetAttribute(gemm_o,   cudaFuncAttributeMaxDynamicSharedMemorySize, GSMEM);
    cudaFuncSetAttribute(flash_mma, cudaFuncAttributeMaxDynamicSharedMemorySize, FSMEM);

    // 1. Prep
    xcvt<<<(M_ * H_ / 4 + 255) / 256, 256>>>(X, M_ * H_ / 4);
    // 2.
    wcvt_t<<<dim3(32, 32, 4), dim3(32, 8)>>>(WQ, WK, WV, WO);
    // 3. QKV projections (Q pre-scaled into exp2 domain)
    gemm_qkv<<<dim3(H_ / TN, M_ / TM, 3), 256, GSMEM>>>();
    // 4. Attention (cross-tile pipelined QK/softmax/PV)
    flash_mma<<<dim3(S_ / 256, NH_, B_), 256, FSMEM>>>(mask);
    // 5. Output projection
    gemm_o<<<dim3(H_ / TN, M_ / TM), 256, GSMEM>>>(out);
}